// round 2
// baseline (speedup 1.0000x reference)
#include <cuda_runtime.h>
#include <math.h>

#define BATCH 16
#define CCH   256
#define HW    4096
#define HEADS 8
#define DH    64
#define HID   512
#define OQKV  1536
#define BHN   (BATCH*HEADS)   /* 128 */
#define QSCALE 0.125f
#define LNEPS  1e-5f
#define INV_N  (1.0f/4096.0f)

// -------------------- scratch (device globals; no allocations) --------------------
// NOTE: the GEMM4 activation A3[b][he][p2] is ALIASED onto the q-channel region
// of g_qkv (channels [0,512) per batch) — q is fully consumed by qsoft before
// gemm3 writes there. Saves 134 MB.
__device__ float g_stat1[BATCH*HW*2];                 // (mu, rstd) input LN
__device__ float g_wgT[CCH*OQKV];                     // (w_qkv * g_in)^T  [c][o]
__device__ float g_ws[OQKV];                          // row sums of w_qkv*g_in
__device__ float g_woT[HID*CCH];                      // w_out^T [he][o]
__device__ float g_qkv[(size_t)BATCH*OQKV*HW];        // raw qkv / A3 alias   402MB
__device__ float g_qs[(size_t)BHN*HW*DH];             // softmaxed q, [bh][p2][d] 134MB
__device__ float g_kmax[BHN*DH];
__device__ float g_ksum[BHN*DH];
__device__ float g_invn[BHN*HW];                      // 1/max(||v||,eps)
__device__ float g_ctxp[8*BHN*DH*DH];                 // split-K partials
__device__ float g_ctx[BHN*DH*DH];                    // context [bh][d][e]
__device__ float g_stat2[BATCH*HW*2];                 // output LN stats

// -------------------- weight prep --------------------
__global__ void __launch_bounds__(256) prep_w1(const float* __restrict__ wqkv,
                                               const float* __restrict__ gin) {
    int o = blockIdx.x, c = threadIdx.x;
    float w = wqkv[o*CCH + c] * gin[c];
    g_wgT[c*OQKV + o] = w;
    __shared__ float red[256];
    red[c] = w; __syncthreads();
    for (int s = 128; s > 0; s >>= 1) { if (c < s) red[c] += red[c+s]; __syncthreads(); }
    if (c == 0) g_ws[o] = red[0];
}

__global__ void __launch_bounds__(256) prep_w2(const float* __restrict__ wout) {
    int he = blockIdx.x, o = threadIdx.x;
    g_woT[he*CCH + o] = wout[o*HID + he];
}

// -------------------- LayerNorm stats (per pixel over channels) --------------------
template<bool S2>
__global__ void __launch_bounds__(256) ln_stats(const float* __restrict__ x) {
    int idx = blockIdx.x*256 + threadIdx.x;          // b*HW + p
    int p = idx & (HW-1);
    int b = idx >> 12;
    const float* base = x + (size_t)b*CCH*HW + p;
    float s = 0.f, ss = 0.f;
    #pragma unroll 8
    for (int c = 0; c < CCH; c++) { float v = base[(size_t)c*HW]; s += v; ss = fmaf(v, v, ss); }
    float mu  = s * (1.f/CCH);
    float var = fmaf(-mu, mu, ss * (1.f/CCH));
    float rstd = rsqrtf(var + LNEPS);
    float2* st = (float2*)(S2 ? g_stat2 : g_stat1);
    st[idx] = make_float2(mu, rstd);
}

// -------------------- tiled GEMM: C[b][m][n] = sum_k A[k][m] * B[b][k][n] --------------------
// 128x64 tile, 256 threads, 8x4 register blocking.
// G1=true : A=g_wgT (pitch OQKV), B=feature (pitch CCH*HW),  C=g_qkv, LN epilogue
// G1=false: A=g_woT (pitch CCH),  B=A3-alias in g_qkv (pitch OQKV*HW, rows 0..511), C=d_out
template<int KTOT, bool G1>
__global__ void __launch_bounds__(256) gemm_k(const float* __restrict__ Bext,
                                              float* __restrict__ Cext) {
    constexpr int AP = G1 ? OQKV : CCH;                          // A pitch == C channels
    constexpr size_t BPITCH = G1 ? (size_t)CCH*HW : (size_t)OQKV*HW;
    __shared__ float As[32][128];
    __shared__ float Bs[32][64];
    const float* A  = G1 ? (const float*)g_wgT : (const float*)g_woT;
    const float* Bb = G1 ? Bext : (const float*)g_qkv;           // A3 alias
    float* Cb       = G1 ? (float*)g_qkv : Cext;

    int b  = blockIdx.z;
    int m0 = blockIdx.y*128, n0 = blockIdx.x*64;
    const float* Bbase = Bb + (size_t)b*BPITCH + n0;
    float*       Cbase = Cb + (size_t)b*AP*HW + (size_t)m0*HW + n0;
    int tid = threadIdx.x, tx = tid & 15, ty = tid >> 4;
    float acc[8][4] = {};

    for (int kt = 0; kt < KTOT/32; kt++) {
        #pragma unroll
        for (int i = 0; i < 4; i++) {                            // A: 32x128 = 1024 float4
            int idx = tid + (i<<8);
            int r = idx >> 5, cg = (idx & 31) << 2;
            *(float4*)&As[r][cg] = *(const float4*)&A[(size_t)(kt*32+r)*AP + m0 + cg];
        }
        #pragma unroll
        for (int i = 0; i < 2; i++) {                            // B: 32x64 = 512 float4
            int idx = tid + (i<<8);
            int r = idx >> 4, cg = (idx & 15) << 2;
            *(float4*)&Bs[r][cg] = *(const float4*)&Bbase[(size_t)(kt*32+r)*HW + cg];
        }
        __syncthreads();
        #pragma unroll
        for (int k = 0; k < 32; k++) {
            float4 a0 = *(float4*)&As[k][(ty<<3)];
            float4 a1 = *(float4*)&As[k][(ty<<3)+4];
            float4 v  = *(float4*)&Bs[k][tx<<2];
            acc[0][0]+=a0.x*v.x; acc[0][1]+=a0.x*v.y; acc[0][2]+=a0.x*v.z; acc[0][3]+=a0.x*v.w;
            acc[1][0]+=a0.y*v.x; acc[1][1]+=a0.y*v.y; acc[1][2]+=a0.y*v.z; acc[1][3]+=a0.y*v.w;
            acc[2][0]+=a0.z*v.x; acc[2][1]+=a0.z*v.y; acc[2][2]+=a0.z*v.z; acc[2][3]+=a0.z*v.w;
            acc[3][0]+=a0.w*v.x; acc[3][1]+=a0.w*v.y; acc[3][2]+=a0.w*v.z; acc[3][3]+=a0.w*v.w;
            acc[4][0]+=a1.x*v.x; acc[4][1]+=a1.x*v.y; acc[4][2]+=a1.x*v.z; acc[4][3]+=a1.x*v.w;
            acc[5][0]+=a1.y*v.x; acc[5][1]+=a1.y*v.y; acc[5][2]+=a1.y*v.z; acc[5][3]+=a1.y*v.w;
            acc[6][0]+=a1.z*v.x; acc[6][1]+=a1.z*v.y; acc[6][2]+=a1.z*v.z; acc[6][3]+=a1.z*v.w;
            acc[7][0]+=a1.w*v.x; acc[7][1]+=a1.w*v.y; acc[7][2]+=a1.w*v.z; acc[7][3]+=a1.w*v.w;
        }
        __syncthreads();
    }

    if (G1) {
        float wsv[8]; float2 st[4];
        #pragma unroll
        for (int i = 0; i < 8; i++) wsv[i] = g_ws[m0 + (ty<<3) + i];
        #pragma unroll
        for (int j = 0; j < 4; j++) st[j] = ((const float2*)g_stat1)[((size_t)b<<12) + n0 + (tx<<2) + j];
        #pragma unroll
        for (int i = 0; i < 8; i++) {
            float4 o;
            o.x = st[0].y * (acc[i][0] - st[0].x*wsv[i]);
            o.y = st[1].y * (acc[i][1] - st[1].x*wsv[i]);
            o.z = st[2].y * (acc[i][2] - st[2].x*wsv[i]);
            o.w = st[3].y * (acc[i][3] - st[3].x*wsv[i]);
            *(float4*)&Cbase[(size_t)((ty<<3)+i)*HW + (tx<<2)] = o;
        }
    } else {
        #pragma unroll
        for (int i = 0; i < 8; i++) {
            float4 o = make_float4(acc[i][0], acc[i][1], acc[i][2], acc[i][3]);
            *(float4*)&Cbase[(size_t)((ty<<3)+i)*HW + (tx<<2)] = o;
        }
    }
}

// -------------------- q softmax over d + spatial transpose: g_qs[bh][p2][d] --------------------
__global__ void __launch_bounds__(256) qsoft() {
    __shared__ float S[64][65];
    int hi = blockIdx.x, bh = blockIdx.y;
    int b = bh >> 3, head = bh & 7;
    const float* qb = g_qkv + ((size_t)b*OQKV + head*DH)*HW + hi*64;
    int tid = threadIdx.x;
    #pragma unroll
    for (int i = 0; i < 16; i++) {
        int idx = tid + (i<<8); int d = idx >> 6, wi = idx & 63;
        S[d][wi] = qb[(size_t)d*HW + wi];
    }
    __syncthreads();
    if (tid < 64) {
        int wi = tid;
        float mx = -1e30f;
        #pragma unroll
        for (int d = 0; d < 64; d++) mx = fmaxf(mx, S[d][wi]);
        float sum = 0.f;
        #pragma unroll
        for (int d = 0; d < 64; d++) { float e = __expf(S[d][wi]-mx); sum += e; S[d][wi] = e; }
        float r = QSCALE / sum;
        #pragma unroll
        for (int d = 0; d < 64; d++) S[d][wi] *= r;
    }
    __syncthreads();
    // write rows p2 = wi*64 + hi, contiguous in d
    #pragma unroll
    for (int i = 0; i < 16; i++) {
        int idx = tid + (i<<8); int wi = idx >> 6, d = idx & 63;
        g_qs[((size_t)bh*HW + (size_t)wi*64 + hi)*DH + d] = S[d][wi];
    }
}

// -------------------- k softmax stats (over n per (bh,d)) --------------------
__global__ void __launch_bounds__(256) kstats() {
    int row = blockIdx.x;                // bh*64 + d
    int bh = row >> 6, d = row & 63;
    int b = bh >> 3, head = bh & 7;
    const float* base = g_qkv + ((size_t)b*OQKV + HID + head*DH + d)*HW;
    int tid = threadIdx.x;
    __shared__ float red[256];
    float mx = -1e30f;
    for (int n = tid; n < HW; n += 256) mx = fmaxf(mx, base[n]);
    red[tid] = mx; __syncthreads();
    for (int s = 128; s > 0; s >>= 1) { if (tid < s) red[tid] = fmaxf(red[tid], red[tid+s]); __syncthreads(); }
    mx = red[0]; __syncthreads();
    float sum = 0.f;
    for (int n = tid; n < HW; n += 256) sum += __expf(base[n] - mx);
    red[tid] = sum; __syncthreads();
    for (int s = 128; s > 0; s >>= 1) { if (tid < s) red[tid] += red[tid+s]; __syncthreads(); }
    if (tid == 0) { g_kmax[row] = mx; g_ksum[row] = red[0]; }
}

// -------------------- v row-norm --------------------
__global__ void __launch_bounds__(256) vnorm() {
    int bh = blockIdx.y;
    int n = blockIdx.x*256 + threadIdx.x;
    int b = bh >> 3, head = bh & 7;
    const float* base = g_qkv + ((size_t)b*OQKV + 2*HID + head*DH)*HW + n;
    float ss = 0.f;
    #pragma unroll
    for (int e = 0; e < 64; e++) { float v = base[(size_t)e*HW]; ss = fmaf(v, v, ss); }
    g_invn[(size_t)bh*HW + n] = 1.f / fmaxf(sqrtf(ss), 1e-12f);
}

// -------------------- context partials: C_p[d][e] = sum_{n chunk} ksm[d][n]*vhat[e][n] --------------------
__global__ void __launch_bounds__(256) gemm2() {
    int sp = blockIdx.x, bh = blockIdx.y;
    int b = bh >> 3, head = bh & 7;
    const float* kbase = g_qkv + ((size_t)b*OQKV + HID   + head*DH)*HW;
    const float* vbase = g_qkv + ((size_t)b*OQKV + 2*HID + head*DH)*HW;
    __shared__ float Ks[64][36];
    __shared__ float Vs[64][36];
    __shared__ float smx[64], srs[64];
    __shared__ float sinv[512];
    int tid = threadIdx.x;
    if (tid < 64) { smx[tid] = g_kmax[bh*64 + tid]; srs[tid] = 1.f / g_ksum[bh*64 + tid]; }
    int n0 = sp*512;
    for (int i = tid; i < 512; i += 256) sinv[i] = g_invn[(size_t)bh*HW + n0 + i] * INV_N;
    __syncthreads();
    int tx = tid & 15, ty = tid >> 4;
    float acc[4][4] = {};
    for (int nt = 0; nt < 16; nt++) {
        int nb = n0 + nt*32;
        #pragma unroll
        for (int i = 0; i < 2; i++) {
            int idx = tid + (i<<8);
            int r = idx >> 3, cg = (idx & 7) << 2;
            float4 kv = *(const float4*)&kbase[(size_t)r*HW + nb + cg];
            float m = smx[r], rs = srs[r];
            float4 ke = make_float4(__expf(kv.x-m)*rs, __expf(kv.y-m)*rs,
                                    __expf(kv.z-m)*rs, __expf(kv.w-m)*rs);
            *(float4*)&Ks[r][cg] = ke;
            float4 vv = *(const float4*)&vbase[(size_t)r*HW + nb + cg];
            int ln = nt*32 + cg;
            float4 ve = make_float4(vv.x*sinv[ln+0], vv.y*sinv[ln+1],
                                    vv.z*sinv[ln+2], vv.w*sinv[ln+3]);
            *(float4*)&Vs[r][cg] = ve;
        }
        __syncthreads();
        #pragma unroll
        for (int nn = 0; nn < 32; nn += 4) {
            float4 av[4], bv[4];
            #pragma unroll
            for (int i = 0; i < 4; i++) av[i] = *(float4*)&Ks[(ty<<2)+i][nn];
            #pragma unroll
            for (int j = 0; j < 4; j++) bv[j] = *(float4*)&Vs[(tx<<2)+j][nn];
            #pragma unroll
            for (int i = 0; i < 4; i++)
                #pragma unroll
                for (int j = 0; j < 4; j++)
                    acc[i][j] += av[i].x*bv[j].x + av[i].y*bv[j].y
                               + av[i].z*bv[j].z + av[i].w*bv[j].w;
        }
        __syncthreads();
    }
    float* cp = g_ctxp + ((size_t)(sp*BHN + bh))*4096;
    #pragma unroll
    for (int i = 0; i < 4; i++) {
        float4 o = make_float4(acc[i][0], acc[i][1], acc[i][2], acc[i][3]);
        *(float4*)&cp[((ty<<2)+i)*64 + (tx<<2)] = o;
    }
}

__global__ void __launch_bounds__(256) ctxred() {
    int bh = blockIdx.x, tid = threadIdx.x;
    for (int i = tid; i < 4096; i += 256) {
        float s = 0.f;
        #pragma unroll
        for (int sp = 0; sp < 8; sp++) s += g_ctxp[((size_t)(sp*BHN + bh))*4096 + i];
        g_ctx[(size_t)bh*4096 + i] = s;
    }
}

// -------------------- out = qs @ ctx, written as A3[b][he][p2] into g_qkv q-region --------------------
__global__ void __launch_bounds__(256) gemm3() {
    __shared__ float Cs[64][64];     // ctx [d][e]
    __shared__ float Qs[64][65];     // [p2 local][d]; reused as transpose buffer [e][p2]
    int p2t = blockIdx.x, bh = blockIdx.y;
    int b = bh >> 3, head = bh & 7;
    int tid = threadIdx.x;
    const float* ctx = g_ctx + (size_t)bh*4096;
    for (int i = tid; i < 4096; i += 256) Cs[i>>6][i&63] = ctx[i];
    const float* qb = g_qs + ((size_t)bh*HW + p2t*64)*DH;
    #pragma unroll
    for (int i = 0; i < 16; i++) { int idx = tid + (i<<8); Qs[idx>>6][idx&63] = qb[idx]; }
    __syncthreads();
    int tx = tid & 15, ty = tid >> 4;
    float acc[4][4] = {};
    #pragma unroll
    for (int d = 0; d < 64; d++) {
        float a0 = Qs[(ty<<2)+0][d], a1 = Qs[(ty<<2)+1][d];
        float a2 = Qs[(ty<<2)+2][d], a3 = Qs[(ty<<2)+3][d];
        float4 bv = *(float4*)&Cs[d][tx<<2];
        acc[0][0]+=a0*bv.x; acc[0][1]+=a0*bv.y; acc[0][2]+=a0*bv.z; acc[0][3]+=a0*bv.w;
        acc[1][0]+=a1*bv.x; acc[1][1]+=a1*bv.y; acc[1][2]+=a1*bv.z; acc[1][3]+=a1*bv.w;
        acc[2][0]+=a2*bv.x; acc[2][1]+=a2*bv.y; acc[2][2]+=a2*bv.z; acc[2][3]+=a2*bv.w;
        acc[3][0]+=a3*bv.x; acc[3][1]+=a3*bv.y; acc[3][2]+=a3*bv.z; acc[3][3]+=a3*bv.w;
    }
    __syncthreads();
    #pragma unroll
    for (int i = 0; i < 4; i++)
        #pragma unroll
        for (int j = 0; j < 4; j++)
            Qs[(tx<<2)+j][(ty<<2)+i] = acc[i][j];   // Ts[e][p2l]
    __syncthreads();
    // A3 alias: channels [head*64 + e] of the q region in g_qkv
    float* a3b = g_qkv + ((size_t)b*OQKV + head*DH)*HW + p2t*64;
    #pragma unroll
    for (int i = 0; i < 16; i++) {
        int idx = tid + (i<<8); int e = idx >> 6, pc = idx & 63;
        a3b[(size_t)e*HW + pc] = Qs[e][pc];
    }
}

// -------------------- final LN apply (in place on d_out) --------------------
__global__ void __launch_bounds__(256) ln_apply(float* __restrict__ y, const float* __restrict__ g) {
    size_t idx = (size_t)blockIdx.x*256 + threadIdx.x;
    int p = (int)(idx & (HW-1));
    int c = (int)((idx >> 12) & (CCH-1));
    int b = (int)(idx >> 20);
    float2 st = ((const float2*)g_stat2)[((size_t)b<<12) + p];
    y[idx] = (y[idx] - st.x) * st.y * g[c];
}

// -------------------- launch --------------------
extern "C" void kernel_launch(void* const* d_in, const int* in_sizes, int n_in,
                              void* d_out, int out_size) {
    const float* feat = (const float*)d_in[0];
    const float* gin  = (const float*)d_in[1];
    const float* wqkv = (const float*)d_in[2];
    const float* wout = (const float*)d_in[3];
    const float* gout = (const float*)d_in[4];
    float* out = (float*)d_out;

    prep_w1<<<OQKV, 256>>>(wqkv, gin);
    prep_w2<<<HID, 256>>>(wout);
    ln_stats<false><<<(BATCH*HW)/256, 256>>>(feat);
    gemm_k<CCH, true><<<dim3(HW/64, OQKV/128, BATCH), 256>>>(feat, nullptr);
    qsoft<<<dim3(64, BHN), 256>>>();
    kstats<<<BHN*DH, 256>>>();
    vnorm<<<dim3(HW/256, BHN), 256>>>();
    gemm2<<<dim3(8, BHN), 256>>>();
    ctxred<<<BHN, 256>>>();
    gemm3<<<dim3(HW/64, BHN), 256>>>();
    gemm_k<HID, false><<<dim3(HW/64, CCH/128, BATCH), 256>>>(nullptr, out);
    ln_stats<true><<<(BATCH*HW)/256, 256>>>(out);
    ln_apply<<<(BATCH*CCH*HW)/256, 256>>>(out, gout);
}

// round 4
// speedup vs baseline: 1.2787x; 1.2787x over previous
#include <cuda_runtime.h>
#include <cuda_bf16.h>
#include <math.h>
#include <stdint.h>

#define BATCH 16
#define CCH   256
#define HW    4096
#define HEADS 8
#define DH    64
#define HID   512
#define OQKV  1536
#define BHN   (BATCH*HEADS)   /* 128 */
#define QSCALE 0.125f
#define LNEPS  1e-5f
#define INV_N  (1.0f/4096.0f)

// ==================== scratch (device globals; no allocations) ====================
__device__ __align__(256) float g_stat1[BATCH*HW*2];            // (mu, rstd) input LN
__device__ __align__(256) float g_ws[OQKV];                     // row sums of (w_qkv*g) eff
__device__ __align__(256) __nv_bfloat16 g_w1hi[OQKV*CCH];       // (w_qkv*g) hi  [o][c] K-major
__device__ __align__(256) __nv_bfloat16 g_w1lo[OQKV*CCH];
__device__ __align__(256) __nv_bfloat16 g_w2hi[CCH*HID];        // w_out hi [o][he] K-major
__device__ __align__(256) __nv_bfloat16 g_w2lo[CCH*HID];
__device__ __align__(256) __nv_bfloat16 g_fThi[(size_t)BATCH*HW*CCH];  // feature^T hi [b][p][c]
__device__ __align__(256) __nv_bfloat16 g_fTlo[(size_t)BATCH*HW*CCH];
__device__ __align__(256) float g_qkv[(size_t)BATCH*OQKV*HW];   // raw qkv fp32   402MB
__device__ __align__(256) float g_qs[(size_t)BHN*HW*DH];        // softmaxed q [bh][p2][d]
__device__ __align__(256) float g_kmax[BHN*DH];
__device__ __align__(256) float g_ksum[BHN*DH];
__device__ __align__(256) float g_invn[BHN*HW];
__device__ __align__(256) float g_ctxp[8*BHN*DH*DH];
__device__ __align__(256) float g_ctx[BHN*DH*DH];
__device__ __align__(256) __nv_bfloat16 g_a3hi[(size_t)BATCH*HW*HID];  // [b][p][he] K-major
__device__ __align__(256) __nv_bfloat16 g_a3lo[(size_t)BATCH*HW*HID];
__device__ __align__(256) float g_stat2[BATCH*HW*2];

// ==================== warp-MMA helpers (sm_80+ PTX, valid on sm_100) ====================
__device__ __forceinline__ uint32_t smem_u32(const void* p) {
    uint32_t a;
    asm("{ .reg .u64 t; cvta.to.shared.u64 t, %1; cvt.u32.u64 %0, t; }" : "=r"(a) : "l"(p));
    return a;
}
__device__ __forceinline__ void ldmx4(uint32_t* r, uint32_t a) {
    asm volatile("ldmatrix.sync.aligned.m8n8.x4.shared.b16 {%0,%1,%2,%3}, [%4];"
        : "=r"(r[0]), "=r"(r[1]), "=r"(r[2]), "=r"(r[3]) : "r"(a));
}
__device__ __forceinline__ void mma_bf16(float* d, const uint32_t* a, uint32_t b0, uint32_t b1) {
    asm volatile("mma.sync.aligned.m16n8k16.row.col.f32.bf16.bf16.f32 "
        "{%0,%1,%2,%3}, {%4,%5,%6,%7}, {%8,%9}, {%0,%1,%2,%3};"
        : "+f"(d[0]), "+f"(d[1]), "+f"(d[2]), "+f"(d[3])
        : "r"(a[0]), "r"(a[1]), "r"(a[2]), "r"(a[3]), "r"(b0), "r"(b1));
}

// ==================== weight prep (bf16 hi/lo splits) ====================
__global__ void __launch_bounds__(256) prep_w1b(const float* __restrict__ wqkv,
                                                const float* __restrict__ gin) {
    int o = blockIdx.x, c = threadIdx.x;
    float w = wqkv[o*CCH + c] * gin[c];
    __nv_bfloat16 h = __float2bfloat16(w);
    __nv_bfloat16 l = __float2bfloat16(w - __bfloat162float(h));
    g_w1hi[o*CCH + c] = h;
    g_w1lo[o*CCH + c] = l;
    float we = __bfloat162float(h) + __bfloat162float(l);
    __shared__ float red[256];
    red[c] = we; __syncthreads();
    for (int s = 128; s > 0; s >>= 1) { if (c < s) red[c] += red[c+s]; __syncthreads(); }
    if (c == 0) g_ws[o] = red[0];
}

__global__ void __launch_bounds__(256) prep_w2b(const float* __restrict__ wout) {
    int o = blockIdx.x;
    for (int t = threadIdx.x; t < HID; t += 256) {
        float w = wout[o*HID + t];
        __nv_bfloat16 h = __float2bfloat16(w);
        __nv_bfloat16 l = __float2bfloat16(w - __bfloat162float(h));
        g_w2hi[o*HID + t] = h;
        g_w2lo[o*HID + t] = l;
    }
}

// ==================== feature transpose + bf16 split + LN stats (fused) ====================
__global__ void __launch_bounds__(256) conv_feat(const float* __restrict__ feat) {
    __shared__ float S[128][65];
    __shared__ float s_s[256], s_ss[256];
    int p0 = blockIdx.x*64, b = blockIdx.y;
    int tid = threadIdx.x;
    float sum = 0.f, ssum = 0.f;
    for (int h = 0; h < 2; h++) {
        #pragma unroll
        for (int i = 0; i < 32; i++) {
            int idx = tid + (i<<8);
            int cl = idx >> 6, pl = idx & 63;
            float v = feat[((size_t)(b*CCH + h*128 + cl))*HW + p0 + pl];
            S[cl][pl] = v;
            sum += v; ssum = fmaf(v, v, ssum);
        }
        __syncthreads();
        #pragma unroll
        for (int i = 0; i < 32; i++) {
            int idx = tid + (i<<8);
            int pl = idx >> 7, cl = idx & 127;
            float v = S[cl][pl];
            __nv_bfloat16 hi = __float2bfloat16(v);
            __nv_bfloat16 lo = __float2bfloat16(v - __bfloat162float(hi));
            size_t o = ((size_t)b*HW + p0 + pl)*CCH + h*128 + cl;
            g_fThi[o] = hi;
            g_fTlo[o] = lo;
        }
        __syncthreads();
    }
    s_s[tid] = sum; s_ss[tid] = ssum;
    __syncthreads();
    if (tid < 64) {
        float s  = s_s[tid] + s_s[tid+64] + s_s[tid+128] + s_s[tid+192];
        float ss = s_ss[tid] + s_ss[tid+64] + s_ss[tid+128] + s_ss[tid+192];
        float mu = s * (1.f/CCH);
        float var = fmaf(-mu, mu, ss * (1.f/CCH));
        ((float2*)g_stat1)[(size_t)b*HW + p0 + tid] = make_float2(mu, rsqrtf(var + LNEPS));
    }
}

// ==================== warp-MMA GEMM (bf16x3): C[b][m][n] = A[m][k] * B[b][n][k]^T ====================
// 128x128 tile, 8 warps (2x4), warp = 64x32 via 4x4 m16n8k16 tiles.
// G1=true : A=w1 (pitch 256), B=fT (pitch 256), C=g_qkv + LN epilogue.  K=256
// G1=false: A=w2 (pitch 512), B=a3 (pitch 512), C=d_out raw.            K=512
#define SPAD 40   /* smem row pitch in bf16: 80B -> 8 ldmatrix rows hit distinct banks */

template<int KTOT, bool G1>
__global__ void __launch_bounds__(256, 1) gemm_m(float* __restrict__ Cext) {
    __shared__ __nv_bfloat16 sAh[128*SPAD], sAl[128*SPAD];
    __shared__ __nv_bfloat16 sBh[128*SPAD], sBl[128*SPAD];
    __shared__ float2 sstat[128];
    __shared__ float  sws[128];
    int tid = threadIdx.x, wid = tid >> 5, lane = tid & 31;
    int b = blockIdx.z, m0 = blockIdx.y*128, n0 = blockIdx.x*128;
    int wm = wid >> 2, wn = wid & 3;

    const __nv_bfloat16* Ah = (G1 ? g_w1hi : g_w2hi) + (size_t)m0*KTOT;
    const __nv_bfloat16* Al = (G1 ? g_w1lo : g_w2lo) + (size_t)m0*KTOT;
    const __nv_bfloat16* Bh = (G1 ? g_fThi : g_a3hi) + ((size_t)b*HW + n0)*KTOT;
    const __nv_bfloat16* Bl = (G1 ? g_fTlo : g_a3lo) + ((size_t)b*HW + n0)*KTOT;
    float* Cb = (G1 ? g_qkv : Cext) + ((size_t)(b*(G1 ? OQKV : CCH) + m0))*HW + n0;

    if (G1) {
        if (tid < 128) sstat[tid] = ((const float2*)g_stat1)[(size_t)b*HW + n0 + tid];
        else           sws[tid-128] = g_ws[m0 + tid - 128];
    }

    float acc[4][4][4] = {};

    // ldmatrix lane addressing (same formula for A and B .x4 loads)
    int lrow = (lane & 7) + (((lane >> 3) & 1) << 3);   // row within 16-row group
    int lcol = (lane >> 4) << 3;                        // 0 or 8

    for (int kc = 0; kc < KTOT/32; kc++) {
        #pragma unroll
        for (int i = 0; i < 2; i++) {
            int e = tid + (i << 8);
            int r = e >> 2, q = e & 3;
            size_t g = (size_t)r*KTOT + kc*32 + q*8;
            int so = r*SPAD + q*8;
            *(uint4*)&sAh[so] = *(const uint4*)&Ah[g];
            *(uint4*)&sAl[so] = *(const uint4*)&Al[g];
            *(uint4*)&sBh[so] = *(const uint4*)&Bh[g];
            *(uint4*)&sBl[so] = *(const uint4*)&Bl[g];
        }
        __syncthreads();
        #pragma unroll
        for (int ks = 0; ks < 2; ks++) {
            int kof = ks*16 + lcol;
            uint32_t afh[4][4], afl[4][4];
            #pragma unroll
            for (int mt = 0; mt < 4; mt++) {
                int row = wm*64 + mt*16 + lrow;
                ldmx4(afh[mt], smem_u32(&sAh[row*SPAD + kof]));
                ldmx4(afl[mt], smem_u32(&sAl[row*SPAD + kof]));
            }
            uint32_t bfh[2][4], bfl[2][4];
            #pragma unroll
            for (int bt = 0; bt < 2; bt++) {
                int row = wn*32 + bt*16 + lrow;
                ldmx4(bfh[bt], smem_u32(&sBh[row*SPAD + kof]));
                ldmx4(bfl[bt], smem_u32(&sBl[row*SPAD + kof]));
            }
            #pragma unroll
            for (int mt = 0; mt < 4; mt++) {
                #pragma unroll
                for (int nt = 0; nt < 4; nt++) {
                    int bt = nt >> 1, od = nt & 1;
                    mma_bf16(acc[mt][nt], afh[mt], bfh[bt][od],   bfh[bt][od+2]);
                    mma_bf16(acc[mt][nt], afh[mt], bfl[bt][od],   bfl[bt][od+2]);
                    mma_bf16(acc[mt][nt], afl[mt], bfh[bt][od],   bfh[bt][od+2]);
                }
            }
        }
        __syncthreads();
    }

    // epilogue: D frag -> (optionally LN-folded) fp32 stores
    #pragma unroll
    for (int mt = 0; mt < 4; mt++) {
        int rml = wm*64 + mt*16 + (lane >> 2);
        #pragma unroll
        for (int nt = 0; nt < 4; nt++) {
            int cl = wn*32 + nt*8 + 2*(lane & 3);
            float* d = acc[mt][nt];
            float2 v0 = make_float2(d[0], d[1]);
            float2 v1 = make_float2(d[2], d[3]);
            if (G1) {
                float2 s0 = sstat[cl], s1 = sstat[cl+1];
                float w0 = sws[rml], w1 = sws[rml+8];
                v0.x = s0.y*(v0.x - s0.x*w0); v0.y = s1.y*(v0.y - s1.x*w0);
                v1.x = s0.y*(v1.x - s0.x*w1); v1.y = s1.y*(v1.y - s1.x*w1);
            }
            *(float2*)&Cb[(size_t)rml*HW + cl]     = v0;
            *(float2*)&Cb[(size_t)(rml+8)*HW + cl] = v1;
        }
    }
}

// ==================== output LN stats ====================
template<bool S2>
__global__ void __launch_bounds__(256) ln_stats(const float* __restrict__ x) {
    int idx = blockIdx.x*256 + threadIdx.x;
    int p = idx & (HW-1);
    int b = idx >> 12;
    const float* base = x + (size_t)b*CCH*HW + p;
    float s = 0.f, ss = 0.f;
    #pragma unroll 8
    for (int c = 0; c < CCH; c++) { float v = base[(size_t)c*HW]; s += v; ss = fmaf(v, v, ss); }
    float mu  = s * (1.f/CCH);
    float var = fmaf(-mu, mu, ss * (1.f/CCH));
    float rstd = rsqrtf(var + LNEPS);
    float2* st = (float2*)(S2 ? g_stat2 : g_stat1);
    st[idx] = make_float2(mu, rstd);
}

// ==================== q softmax over d + spatial transpose: g_qs[bh][p2][d] ====================
__global__ void __launch_bounds__(256) qsoft() {
    __shared__ float S[64][65];
    int hi = blockIdx.x, bh = blockIdx.y;
    int b = bh >> 3, head = bh & 7;
    const float* qb = g_qkv + ((size_t)b*OQKV + head*DH)*HW + hi*64;
    int tid = threadIdx.x;
    #pragma unroll
    for (int i = 0; i < 16; i++) {
        int idx = tid + (i<<8); int d = idx >> 6, wi = idx & 63;
        S[d][wi] = qb[(size_t)d*HW + wi];
    }
    __syncthreads();
    if (tid < 64) {
        int wi = tid;
        float mx = -1e30f;
        #pragma unroll
        for (int d = 0; d < 64; d++) mx = fmaxf(mx, S[d][wi]);
        float sum = 0.f;
        #pragma unroll
        for (int d = 0; d < 64; d++) { float e = __expf(S[d][wi]-mx); sum += e; S[d][wi] = e; }
        float r = QSCALE / sum;
        #pragma unroll
        for (int d = 0; d < 64; d++) S[d][wi] *= r;
    }
    __syncthreads();
    #pragma unroll
    for (int i = 0; i < 16; i++) {
        int idx = tid + (i<<8); int wi = idx >> 6, d = idx & 63;
        g_qs[((size_t)bh*HW + (size_t)wi*64 + hi)*DH + d] = S[d][wi];
    }
}

// ==================== k softmax stats ====================
__global__ void __launch_bounds__(256) kstats() {
    int row = blockIdx.x;
    int bh = row >> 6, d = row & 63;
    int b = bh >> 3, head = bh & 7;
    const float* base = g_qkv + ((size_t)b*OQKV + HID + head*DH + d)*HW;
    int tid = threadIdx.x;
    __shared__ float red[256];
    float mx = -1e30f;
    for (int n = tid; n < HW; n += 256) mx = fmaxf(mx, base[n]);
    red[tid] = mx; __syncthreads();
    for (int s = 128; s > 0; s >>= 1) { if (tid < s) red[tid] = fmaxf(red[tid], red[tid+s]); __syncthreads(); }
    mx = red[0]; __syncthreads();
    float sum = 0.f;
    for (int n = tid; n < HW; n += 256) sum += __expf(base[n] - mx);
    red[tid] = sum; __syncthreads();
    for (int s = 128; s > 0; s >>= 1) { if (tid < s) red[tid] += red[tid+s]; __syncthreads(); }
    if (tid == 0) { g_kmax[row] = mx; g_ksum[row] = red[0]; }
}

// ==================== v row-norm ====================
__global__ void __launch_bounds__(256) vnorm() {
    int bh = blockIdx.y;
    int n = blockIdx.x*256 + threadIdx.x;
    int b = bh >> 3, head = bh & 7;
    const float* base = g_qkv + ((size_t)b*OQKV + 2*HID + head*DH)*HW + n;
    float ss = 0.f;
    #pragma unroll
    for (int e = 0; e < 64; e++) { float v = base[(size_t)e*HW]; ss = fmaf(v, v, ss); }
    g_invn[(size_t)bh*HW + n] = 1.f / fmaxf(sqrtf(ss), 1e-12f);
}

// ==================== context partials ====================
__global__ void __launch_bounds__(256) gemm2() {
    int sp = blockIdx.x, bh = blockIdx.y;
    int b = bh >> 3, head = bh & 7;
    const float* kbase = g_qkv + ((size_t)b*OQKV + HID   + head*DH)*HW;
    const float* vbase = g_qkv + ((size_t)b*OQKV + 2*HID + head*DH)*HW;
    __shared__ float Ks[64][36];
    __shared__ float Vs[64][36];
    __shared__ float smx[64], srs[64];
    __shared__ float sinv[512];
    int tid = threadIdx.x;
    if (tid < 64) { smx[tid] = g_kmax[bh*64 + tid]; srs[tid] = 1.f / g_ksum[bh*64 + tid]; }
    int n0 = sp*512;
    for (int i = tid; i < 512; i += 256) sinv[i] = g_invn[(size_t)bh*HW + n0 + i] * INV_N;
    __syncthreads();
    int tx = tid & 15, ty = tid >> 4;
    float acc[4][4] = {};
    for (int nt = 0; nt < 16; nt++) {
        int nb = n0 + nt*32;
        #pragma unroll
        for (int i = 0; i < 2; i++) {
            int idx = tid + (i<<8);
            int r = idx >> 3, cg = (idx & 7) << 2;
            float4 kv = *(const float4*)&kbase[(size_t)r*HW + nb + cg];
            float m = smx[r], rs = srs[r];
            float4 ke = make_float4(__expf(kv.x-m)*rs, __expf(kv.y-m)*rs,
                                    __expf(kv.z-m)*rs, __expf(kv.w-m)*rs);
            *(float4*)&Ks[r][cg] = ke;
            float4 vv = *(const float4*)&vbase[(size_t)r*HW + nb + cg];
            int ln = nt*32 + cg;
            float4 ve = make_float4(vv.x*sinv[ln+0], vv.y*sinv[ln+1],
                                    vv.z*sinv[ln+2], vv.w*sinv[ln+3]);
            *(float4*)&Vs[r][cg] = ve;
        }
        __syncthreads();
        #pragma unroll
        for (int nn = 0; nn < 32; nn += 4) {
            float4 av[4], bv[4];
            #pragma unroll
            for (int i = 0; i < 4; i++) av[i] = *(float4*)&Ks[(ty<<2)+i][nn];
            #pragma unroll
            for (int j = 0; j < 4; j++) bv[j] = *(float4*)&Vs[(tx<<2)+j][nn];
            #pragma unroll
            for (int i = 0; i < 4; i++)
                #pragma unroll
                for (int j = 0; j < 4; j++)
                    acc[i][j] += av[i].x*bv[j].x + av[i].y*bv[j].y
                               + av[i].z*bv[j].z + av[i].w*bv[j].w;
        }
        __syncthreads();
    }
    float* cp = g_ctxp + ((size_t)(sp*BHN + bh))*4096;
    #pragma unroll
    for (int i = 0; i < 4; i++) {
        float4 o = make_float4(acc[i][0], acc[i][1], acc[i][2], acc[i][3]);
        *(float4*)&cp[((ty<<2)+i)*64 + (tx<<2)] = o;
    }
}

__global__ void __launch_bounds__(256) ctxred() {
    int bh = blockIdx.x, tid = threadIdx.x;
    for (int i = tid; i < 4096; i += 256) {
        float s = 0.f;
        #pragma unroll
        for (int sp = 0; sp < 8; sp++) s += g_ctxp[((size_t)(sp*BHN + bh))*4096 + i];
        g_ctx[(size_t)bh*4096 + i] = s;
    }
}

// ==================== out = qs @ ctx -> a3 hi/lo [b][p][he] (K-major for GEMM4) ====================
__global__ void __launch_bounds__(256) gemm3() {
    __shared__ float Cs[64][64];
    __shared__ float Qs[64][65];
    int p2t = blockIdx.x, bh = blockIdx.y;
    int b = bh >> 3, head = bh & 7;
    int tid = threadIdx.x;
    const float* ctx = g_ctx + (size_t)bh*4096;
    for (int i = tid; i < 4096; i += 256) Cs[i>>6][i&63] = ctx[i];
    const float* qb = g_qs + ((size_t)bh*HW + p2t*64)*DH;
    #pragma unroll
    for (int i = 0; i < 16; i++) { int idx = tid + (i<<8); Qs[idx>>6][idx&63] = qb[idx]; }
    __syncthreads();
    int tx = tid & 15, ty = tid >> 4;
    float acc[4][4] = {};
    #pragma unroll
    for (int d = 0; d < 64; d++) {
        float a0 = Qs[(ty<<2)+0][d], a1 = Qs[(ty<<2)+1][d];
        float a2 = Qs[(ty<<2)+2][d], a3 = Qs[(ty<<2)+3][d];
        float4 bv = *(float4*)&Cs[d][tx<<2];
        acc[0][0]+=a0*bv.x; acc[0][1]+=a0*bv.y; acc[0][2]+=a0*bv.z; acc[0][3]+=a0*bv.w;
        acc[1][0]+=a1*bv.x; acc[1][1]+=a1*bv.y; acc[1][2]+=a1*bv.z; acc[1][3]+=a1*bv.w;
        acc[2][0]+=a2*bv.x; acc[2][1]+=a2*bv.y; acc[2][2]+=a2*bv.z; acc[2][3]+=a2*bv.w;
        acc[3][0]+=a3*bv.x; acc[3][1]+=a3*bv.y; acc[3][2]+=a3*bv.z; acc[3][3]+=a3*bv.w;
    }
    __syncthreads();
    #pragma unroll
    for (int i = 0; i < 4; i++)
        #pragma unroll
        for (int j = 0; j < 4; j++)
            Qs[(ty<<2)+i][(tx<<2)+j] = acc[i][j];   // [p2l][e]
    __syncthreads();
    size_t rowbase = (size_t)b*HW + p2t*64;
    #pragma unroll
    for (int i = 0; i < 16; i++) {
        int idx = tid + (i<<8); int pl = idx >> 6, e = idx & 63;
        float v = Qs[pl][e];
        __nv_bfloat16 h = __float2bfloat16(v);
        __nv_bfloat16 l = __float2bfloat16(v - __bfloat162float(h));
        size_t o = (rowbase + pl)*HID + head*DH + e;
        g_a3hi[o] = h;
        g_a3lo[o] = l;
    }
}

// ==================== final LN apply ====================
__global__ void __launch_bounds__(256) ln_apply(float* __restrict__ y, const float* __restrict__ g) {
    size_t idx = (size_t)blockIdx.x*256 + threadIdx.x;
    int p = (int)(idx & (HW-1));
    int c = (int)((idx >> 12) & (CCH-1));
    int b = (int)(idx >> 20);
    float2 st = ((const float2*)g_stat2)[((size_t)b<<12) + p];
    y[idx] = (y[idx] - st.x) * st.y * g[c];
}

// ==================== launch ====================
extern "C" void kernel_launch(void* const* d_in, const int* in_sizes, int n_in,
                              void* d_out, int out_size) {
    const float* feat = (const float*)d_in[0];
    const float* gin  = (const float*)d_in[1];
    const float* wqkv = (const float*)d_in[2];
    const float* wout = (const float*)d_in[3];
    const float* gout = (const float*)d_in[4];
    float* out = (float*)d_out;

    prep_w1b<<<OQKV, 256>>>(wqkv, gin);
    prep_w2b<<<CCH, 256>>>(wout);
    conv_feat<<<dim3(HW/64, BATCH), 256>>>(feat);
    gemm_m<CCH, true><<<dim3(HW/128, OQKV/128, BATCH), 256>>>(nullptr);
    qsoft<<<dim3(64, BHN), 256>>>();
    kstats<<<BHN*DH, 256>>>();
    vnorm<<<dim3(HW/256, BHN), 256>>>();
    gemm2<<<dim3(8, BHN), 256>>>();
    ctxred<<<BHN, 256>>>();
    gemm3<<<dim3(HW/64, BHN), 256>>>();
    gemm_m<HID, false><<<dim3(HW/128, CCH/128, BATCH), 256>>>(out);
    ln_stats<true><<<(BATCH*HW)/256, 256>>>(out);
    ln_apply<<<(BATCH*CCH*HW)/256, 256>>>(out, gout);
}

// round 5
// speedup vs baseline: 1.4051x; 1.0988x over previous
#include <cuda_runtime.h>
#include <cuda_bf16.h>
#include <math.h>
#include <stdint.h>

#define BATCH 16
#define CCH   256
#define HW    4096
#define HEADS 8
#define DH    64
#define HID   512
#define OQKV  1536
#define BHN   (BATCH*HEADS)   /* 128 */
#define QSCALE 0.125f
#define LNEPS  1e-5f
#define INV_N  (1.0f/4096.0f)
#define SPAD  40   /* smem row pitch in bf16: 80B -> 8 ldmatrix rows hit distinct banks */

// ==================== scratch (device globals; no allocations) ====================
__device__ __align__(256) float g_stat1[BATCH*HW*2];            // (mu, rstd) input LN
__device__ __align__(256) float g_ws[OQKV];                     // row sums of (w_qkv*g) eff
__device__ __align__(256) __nv_bfloat16 g_w1hi[OQKV*CCH];       // (w_qkv*g) hi  [o][c] K-major
__device__ __align__(256) __nv_bfloat16 g_w1lo[OQKV*CCH];
__device__ __align__(256) __nv_bfloat16 g_w2hi[CCH*HID];        // w_out hi [o][he] K-major
__device__ __align__(256) __nv_bfloat16 g_w2lo[CCH*HID];
__device__ __align__(256) __nv_bfloat16 g_fThi[(size_t)BATCH*HW*CCH];  // feature^T hi [b][p][c]
__device__ __align__(256) __nv_bfloat16 g_fTlo[(size_t)BATCH*HW*CCH];
__device__ __align__(256) float g_qkv[(size_t)BATCH*OQKV*HW];   // raw qkv fp32   402MB
__device__ __align__(256) float g_qs[(size_t)BHN*HW*DH];        // softmaxed q [bh][p2][d]
__device__ __align__(256) float g_kmax[BHN*DH];
__device__ __align__(256) float g_ksum[BHN*DH];
__device__ __align__(256) float g_invn[BHN*HW];
__device__ __align__(256) float g_ctxp[8*BHN*DH*DH];
__device__ __align__(256) float g_ctx[BHN*DH*DH];
__device__ __align__(256) __nv_bfloat16 g_a3hi[(size_t)BATCH*HW*HID];  // [b][p][he] K-major
__device__ __align__(256) __nv_bfloat16 g_a3lo[(size_t)BATCH*HW*HID];

// ==================== helpers (sm_80+ PTX, valid on sm_100) ====================
__device__ __forceinline__ uint32_t smem_u32(const void* p) {
    uint32_t a;
    asm("{ .reg .u64 t; cvta.to.shared.u64 t, %1; cvt.u32.u64 %0, t; }" : "=r"(a) : "l"(p));
    return a;
}
__device__ __forceinline__ void ldmx4(uint32_t* r, uint32_t a) {
    asm volatile("ldmatrix.sync.aligned.m8n8.x4.shared.b16 {%0,%1,%2,%3}, [%4];"
        : "=r"(r[0]), "=r"(r[1]), "=r"(r[2]), "=r"(r[3]) : "r"(a));
}
__device__ __forceinline__ void mma_bf16(float* d, const uint32_t* a, uint32_t b0, uint32_t b1) {
    asm volatile("mma.sync.aligned.m16n8k16.row.col.f32.bf16.bf16.f32 "
        "{%0,%1,%2,%3}, {%4,%5,%6,%7}, {%8,%9}, {%0,%1,%2,%3};"
        : "+f"(d[0]), "+f"(d[1]), "+f"(d[2]), "+f"(d[3])
        : "r"(a[0]), "r"(a[1]), "r"(a[2]), "r"(a[3]), "r"(b0), "r"(b1));
}
__device__ __forceinline__ void cp16(uint32_t s, const void* g) {
    asm volatile("cp.async.cg.shared.global [%0], [%1], 16;" :: "r"(s), "l"(g) : "memory");
}
#define CP_COMMIT() asm volatile("cp.async.commit_group;" ::: "memory")
#define CP_WAIT1()  asm volatile("cp.async.wait_group 1;" ::: "memory")

// ==================== weight prep (bf16 hi/lo splits) ====================
__global__ void __launch_bounds__(256) prep_w1b(const float* __restrict__ wqkv,
                                                const float* __restrict__ gin) {
    int o = blockIdx.x, c = threadIdx.x;
    float w = wqkv[o*CCH + c] * gin[c];
    __nv_bfloat16 h = __float2bfloat16(w);
    __nv_bfloat16 l = __float2bfloat16(w - __bfloat162float(h));
    g_w1hi[o*CCH + c] = h;
    g_w1lo[o*CCH + c] = l;
    float we = __bfloat162float(h) + __bfloat162float(l);
    __shared__ float red[256];
    red[c] = we; __syncthreads();
    for (int s = 128; s > 0; s >>= 1) { if (c < s) red[c] += red[c+s]; __syncthreads(); }
    if (c == 0) g_ws[o] = red[0];
}

__global__ void __launch_bounds__(256) prep_w2b(const float* __restrict__ wout) {
    int o = blockIdx.x;
    for (int t = threadIdx.x; t < HID; t += 256) {
        float w = wout[o*HID + t];
        __nv_bfloat16 h = __float2bfloat16(w);
        __nv_bfloat16 l = __float2bfloat16(w - __bfloat162float(h));
        g_w2hi[o*HID + t] = h;
        g_w2lo[o*HID + t] = l;
    }
}

// ==================== feature transpose + bf16 split + LN stats (fused) ====================
__global__ void __launch_bounds__(256) conv_feat(const float* __restrict__ feat) {
    __shared__ float S[128][65];
    __shared__ float s_s[256], s_ss[256];
    int p0 = blockIdx.x*64, b = blockIdx.y;
    int tid = threadIdx.x;
    float sum = 0.f, ssum = 0.f;
    for (int h = 0; h < 2; h++) {
        #pragma unroll
        for (int i = 0; i < 32; i++) {
            int idx = tid + (i<<8);
            int cl = idx >> 6, pl = idx & 63;
            float v = feat[((size_t)(b*CCH + h*128 + cl))*HW + p0 + pl];
            S[cl][pl] = v;
            sum += v; ssum = fmaf(v, v, ssum);
        }
        __syncthreads();
        #pragma unroll
        for (int i = 0; i < 32; i++) {
            int idx = tid + (i<<8);
            int pl = idx >> 7, cl = idx & 127;
            float v = S[cl][pl];
            __nv_bfloat16 hi = __float2bfloat16(v);
            __nv_bfloat16 lo = __float2bfloat16(v - __bfloat162float(hi));
            size_t o = ((size_t)b*HW + p0 + pl)*CCH + h*128 + cl;
            g_fThi[o] = hi;
            g_fTlo[o] = lo;
        }
        __syncthreads();
    }
    s_s[tid] = sum; s_ss[tid] = ssum;
    __syncthreads();
    if (tid < 64) {
        float s  = s_s[tid] + s_s[tid+64] + s_s[tid+128] + s_s[tid+192];
        float ss = s_ss[tid] + s_ss[tid+64] + s_ss[tid+128] + s_ss[tid+192];
        float mu = s * (1.f/CCH);
        float var = fmaf(-mu, mu, ss * (1.f/CCH));
        ((float2*)g_stat1)[(size_t)b*HW + p0 + tid] = make_float2(mu, rsqrtf(var + LNEPS));
    }
}

// ==================== pipelined warp-MMA GEMM (bf16x3, cp.async 2-stage) ====================
// G1=true : TM=128,TN=128,K=256. A=w1, B=fT.  C=g_qkv with input-LN fold epilogue.
// G1=false: TM=256,TN=64, K=512. A=w2, B=a3.  Epilogue computes FULL output LN and
//           writes final result (d_out) directly — per-pixel stats over all 256 channels.
template<int TM, int TN, int KTOT, bool G1>
__global__ void __launch_bounds__(256, 1) gemm_p(float* __restrict__ Cext,
                                                 const float* __restrict__ gout) {
    extern __shared__ char smem[];
    constexpr int WN    = TN/32;            // warps along n
    constexpr int A_ARR = TM*SPAD*2;        // bytes per A array per stage
    constexpr int B_ARR = TN*SPAD*2;
    constexpr int STAGE = 2*A_ARR + 2*B_ARR;
    constexpr int FIX   = 2*STAGE;
    constexpr int KC    = KTOT/32;

    int tid = threadIdx.x, wid = tid >> 5, lane = tid & 31;
    int b = blockIdx.z, m0 = blockIdx.y*TM, n0 = blockIdx.x*TN;
    int wm = wid / WN, wn = wid % WN;
    uint32_t sb = smem_u32(smem);

    const __nv_bfloat16* Ah = (G1 ? g_w1hi : g_w2hi) + (size_t)m0*KTOT;
    const __nv_bfloat16* Al = (G1 ? g_w1lo : g_w2lo) + (size_t)m0*KTOT;
    const __nv_bfloat16* Bh = (G1 ? g_fThi : g_a3hi) + ((size_t)b*HW + n0)*KTOT;
    const __nv_bfloat16* Bl = (G1 ? g_fTlo : g_a3lo) + ((size_t)b*HW + n0)*KTOT;
    float* Cb = (G1 ? g_qkv : Cext) + ((size_t)(b*(G1 ? OQKV : CCH) + m0))*HW + n0;

    float2* sstat = (float2*)(smem + FIX);          // G1
    float*  sws   = (float*)(smem + FIX + 1024);    // G1
    float*  sg    = (float*)(smem + FIX);           // G4
    float*  ps    = (float*)(smem + FIX + 1024);    // G4 partial sums [4][64]
    float*  pss   = (float*)(smem + FIX + 2048);    // G4 partial sumsq
    float2* mrs   = (float2*)(smem + FIX + 3072);   // G4 (mu, rstd)[64]

    if (G1) {
        if (tid < 128) sstat[tid] = ((const float2*)g_stat1)[(size_t)b*HW + n0 + tid];
        else           sws[tid-128] = g_ws[m0 + tid - 128];
    } else {
        sg[tid] = gout[tid];
    }

    auto load_stage = [&](int kc, int s) {
        #pragma unroll
        for (int i = 0; i < TM*8/256; i++) {        // A hi+lo chunks
            int e = tid + (i << 8);
            int arr = e >= TM*4;
            int rq = arr ? e - TM*4 : e;
            int r = rq >> 2, q = rq & 3;
            const __nv_bfloat16* gp = (arr ? Al : Ah) + (size_t)r*KTOT + kc*32 + q*8;
            cp16(sb + s*STAGE + arr*A_ARR + (r*SPAD + q*8)*2, gp);
        }
        #pragma unroll
        for (int i = 0; i < TN*8/256; i++) {        // B hi+lo chunks
            int e = tid + (i << 8);
            int arr = e >= TN*4;
            int rq = arr ? e - TN*4 : e;
            int r = rq >> 2, q = rq & 3;
            const __nv_bfloat16* gp = (arr ? Bl : Bh) + (size_t)r*KTOT + kc*32 + q*8;
            cp16(sb + s*STAGE + 2*A_ARR + arr*B_ARR + (r*SPAD + q*8)*2, gp);
        }
    };

    float acc[4][4][4] = {};
    int lrow = (lane & 7) + (((lane >> 3) & 1) << 3);
    int lcol = (lane >> 4) << 3;

    load_stage(0, 0);
    CP_COMMIT();

    for (int kc = 0; kc < KC; kc++) {
        if (kc + 1 < KC) load_stage(kc+1, (kc+1) & 1);
        CP_COMMIT();
        CP_WAIT1();
        __syncthreads();
        uint32_t sbase = sb + (kc & 1)*STAGE;
        #pragma unroll
        for (int ks = 0; ks < 2; ks++) {
            int kof = ks*16 + lcol;
            uint32_t afh[4][4], afl[4][4];
            #pragma unroll
            for (int mt = 0; mt < 4; mt++) {
                int row = wm*64 + mt*16 + lrow;
                ldmx4(afh[mt], sbase + (row*SPAD + kof)*2);
                ldmx4(afl[mt], sbase + A_ARR + (row*SPAD + kof)*2);
            }
            uint32_t bfh[2][4], bfl[2][4];
            #pragma unroll
            for (int bt = 0; bt < 2; bt++) {
                int row = wn*32 + bt*16 + lrow;
                ldmx4(bfh[bt], sbase + 2*A_ARR + (row*SPAD + kof)*2);
                ldmx4(bfl[bt], sbase + 2*A_ARR + B_ARR + (row*SPAD + kof)*2);
            }
            #pragma unroll
            for (int mt = 0; mt < 4; mt++) {
                #pragma unroll
                for (int nt = 0; nt < 4; nt++) {
                    int bt = nt >> 1, od = nt & 1;
                    mma_bf16(acc[mt][nt], afh[mt], bfh[bt][od], bfh[bt][od+2]);
                    mma_bf16(acc[mt][nt], afh[mt], bfl[bt][od], bfl[bt][od+2]);
                    mma_bf16(acc[mt][nt], afl[mt], bfh[bt][od], bfh[bt][od+2]);
                }
            }
        }
        __syncthreads();
    }

    if (G1) {
        // epilogue: input-LN fold, direct fp32 stores
        #pragma unroll
        for (int mt = 0; mt < 4; mt++) {
            int rml = wm*64 + mt*16 + (lane >> 2);
            #pragma unroll
            for (int nt = 0; nt < 4; nt++) {
                int cl = wn*32 + nt*8 + 2*(lane & 3);
                float* d = acc[mt][nt];
                float2 s0 = sstat[cl], s1 = sstat[cl+1];
                float w0 = sws[rml], w1 = sws[rml+8];
                float2 v0 = make_float2(s0.y*(d[0] - s0.x*w0), s1.y*(d[1] - s1.x*w0));
                float2 v1 = make_float2(s0.y*(d[2] - s0.x*w1), s1.y*(d[3] - s1.x*w1));
                *(float2*)&Cb[(size_t)rml*HW + cl]     = v0;
                *(float2*)&Cb[(size_t)(rml+8)*HW + cl] = v1;
            }
        }
    } else {
        // epilogue: full output LN over 256 channels for 64 pixels, then final store
        float* buf = (float*)smem;   // 256 x 64, pitch 68 (reuses operand stages)
        #pragma unroll
        for (int mt = 0; mt < 4; mt++) {
            int rml = wm*64 + mt*16 + (lane >> 2);
            #pragma unroll
            for (int nt = 0; nt < 4; nt++) {
                int cl = wn*32 + nt*8 + 2*(lane & 3);
                float* d = acc[mt][nt];
                buf[rml*68 + cl]     = d[0];
                buf[rml*68 + cl + 1] = d[1];
                buf[(rml+8)*68 + cl]     = d[2];
                buf[(rml+8)*68 + cl + 1] = d[3];
            }
        }
        __syncthreads();
        {
            int col = tid & 63, part = tid >> 6;
            float s = 0.f, ss = 0.f;
            #pragma unroll 8
            for (int r = part*64; r < part*64 + 64; r++) {
                float v = buf[r*68 + col];
                s += v; ss = fmaf(v, v, ss);
            }
            ps[part*64 + col] = s;
            pss[part*64 + col] = ss;
        }
        __syncthreads();
        if (tid < 64) {
            float s  = ps[tid] + ps[64+tid] + ps[128+tid] + ps[192+tid];
            float ss = pss[tid] + pss[64+tid] + pss[128+tid] + pss[192+tid];
            float mu = s * (1.f/CCH);
            float var = fmaf(-mu, mu, ss * (1.f/CCH));
            mrs[tid] = make_float2(mu, rsqrtf(var + LNEPS));
        }
        __syncthreads();
        #pragma unroll 8
        for (int i = 0; i < 64; i++) {
            int idx = tid + (i << 8);
            int row = idx >> 6, col = idx & 63;
            float2 st = mrs[col];
            Cb[(size_t)row*HW + col] = (buf[row*68 + col] - st.x) * st.y * sg[row];
        }
    }
}

// ==================== q softmax over d + spatial transpose: g_qs[bh][p2][d] ====================
__global__ void __launch_bounds__(256) qsoft() {
    __shared__ float S[64][65];
    int hi = blockIdx.x, bh = blockIdx.y;
    int b = bh >> 3, head = bh & 7;
    const float* qb = g_qkv + ((size_t)b*OQKV + head*DH)*HW + hi*64;
    int tid = threadIdx.x;
    #pragma unroll
    for (int i = 0; i < 16; i++) {
        int idx = tid + (i<<8); int d = idx >> 6, wi = idx & 63;
        S[d][wi] = qb[(size_t)d*HW + wi];
    }
    __syncthreads();
    if (tid < 64) {
        int wi = tid;
        float mx = -1e30f;
        #pragma unroll
        for (int d = 0; d < 64; d++) mx = fmaxf(mx, S[d][wi]);
        float sum = 0.f;
        #pragma unroll
        for (int d = 0; d < 64; d++) { float e = __expf(S[d][wi]-mx); sum += e; S[d][wi] = e; }
        float r = QSCALE / sum;
        #pragma unroll
        for (int d = 0; d < 64; d++) S[d][wi] *= r;
    }
    __syncthreads();
    #pragma unroll
    for (int i = 0; i < 16; i++) {
        int idx = tid + (i<<8); int wi = idx >> 6, d = idx & 63;
        g_qs[((size_t)bh*HW + (size_t)wi*64 + hi)*DH + d] = S[d][wi];
    }
}

// ==================== k softmax stats ====================
__global__ void __launch_bounds__(256) kstats() {
    int row = blockIdx.x;
    int bh = row >> 6, d = row & 63;
    int b = bh >> 3, head = bh & 7;
    const float* base = g_qkv + ((size_t)b*OQKV + HID + head*DH + d)*HW;
    int tid = threadIdx.x;
    __shared__ float red[256];
    float mx = -1e30f;
    for (int n = tid; n < HW; n += 256) mx = fmaxf(mx, base[n]);
    red[tid] = mx; __syncthreads();
    for (int s = 128; s > 0; s >>= 1) { if (tid < s) red[tid] = fmaxf(red[tid], red[tid+s]); __syncthreads(); }
    mx = red[0]; __syncthreads();
    float sum = 0.f;
    for (int n = tid; n < HW; n += 256) sum += __expf(base[n] - mx);
    red[tid] = sum; __syncthreads();
    for (int s = 128; s > 0; s >>= 1) { if (tid < s) red[tid] += red[tid+s]; __syncthreads(); }
    if (tid == 0) { g_kmax[row] = mx; g_ksum[row] = red[0]; }
}

// ==================== v row-norm ====================
__global__ void __launch_bounds__(256) vnorm() {
    int bh = blockIdx.y;
    int n = blockIdx.x*256 + threadIdx.x;
    int b = bh >> 3, head = bh & 7;
    const float* base = g_qkv + ((size_t)b*OQKV + 2*HID + head*DH)*HW + n;
    float ss = 0.f;
    #pragma unroll
    for (int e = 0; e < 64; e++) { float v = base[(size_t)e*HW]; ss = fmaf(v, v, ss); }
    g_invn[(size_t)bh*HW + n] = 1.f / fmaxf(sqrtf(ss), 1e-12f);
}

// ==================== context partials ====================
__global__ void __launch_bounds__(256) gemm2() {
    int sp = blockIdx.x, bh = blockIdx.y;
    int b = bh >> 3, head = bh & 7;
    const float* kbase = g_qkv + ((size_t)b*OQKV + HID   + head*DH)*HW;
    const float* vbase = g_qkv + ((size_t)b*OQKV + 2*HID + head*DH)*HW;
    __shared__ float Ks[64][36];
    __shared__ float Vs[64][36];
    __shared__ float smx[64], srs[64];
    __shared__ float sinv[512];
    int tid = threadIdx.x;
    if (tid < 64) { smx[tid] = g_kmax[bh*64 + tid]; srs[tid] = 1.f / g_ksum[bh*64 + tid]; }
    int n0 = sp*512;
    for (int i = tid; i < 512; i += 256) sinv[i] = g_invn[(size_t)bh*HW + n0 + i] * INV_N;
    __syncthreads();
    int tx = tid & 15, ty = tid >> 4;
    float acc[4][4] = {};
    for (int nt = 0; nt < 16; nt++) {
        int nb = n0 + nt*32;
        #pragma unroll
        for (int i = 0; i < 2; i++) {
            int idx = tid + (i<<8);
            int r = idx >> 3, cg = (idx & 7) << 2;
            float4 kv = *(const float4*)&kbase[(size_t)r*HW + nb + cg];
            float m = smx[r], rs = srs[r];
            float4 ke = make_float4(__expf(kv.x-m)*rs, __expf(kv.y-m)*rs,
                                    __expf(kv.z-m)*rs, __expf(kv.w-m)*rs);
            *(float4*)&Ks[r][cg] = ke;
            float4 vv = *(const float4*)&vbase[(size_t)r*HW + nb + cg];
            int ln = nt*32 + cg;
            float4 ve = make_float4(vv.x*sinv[ln+0], vv.y*sinv[ln+1],
                                    vv.z*sinv[ln+2], vv.w*sinv[ln+3]);
            *(float4*)&Vs[r][cg] = ve;
        }
        __syncthreads();
        #pragma unroll
        for (int nn = 0; nn < 32; nn += 4) {
            float4 av[4], bv[4];
            #pragma unroll
            for (int i = 0; i < 4; i++) av[i] = *(float4*)&Ks[(ty<<2)+i][nn];
            #pragma unroll
            for (int j = 0; j < 4; j++) bv[j] = *(float4*)&Vs[(tx<<2)+j][nn];
            #pragma unroll
            for (int i = 0; i < 4; i++)
                #pragma unroll
                for (int j = 0; j < 4; j++)
                    acc[i][j] += av[i].x*bv[j].x + av[i].y*bv[j].y
                               + av[i].z*bv[j].z + av[i].w*bv[j].w;
        }
        __syncthreads();
    }
    float* cp = g_ctxp + ((size_t)(sp*BHN + bh))*4096;
    #pragma unroll
    for (int i = 0; i < 4; i++) {
        float4 o = make_float4(acc[i][0], acc[i][1], acc[i][2], acc[i][3]);
        *(float4*)&cp[((ty<<2)+i)*64 + (tx<<2)] = o;
    }
}

__global__ void __launch_bounds__(256) ctxred() {
    int bh = blockIdx.x, tid = threadIdx.x;
    for (int i = tid; i < 4096; i += 256) {
        float s = 0.f;
        #pragma unroll
        for (int sp = 0; sp < 8; sp++) s += g_ctxp[((size_t)(sp*BHN + bh))*4096 + i];
        g_ctx[(size_t)bh*4096 + i] = s;
    }
}

// ==================== out = qs @ ctx -> a3 hi/lo [b][p][he] (K-major for GEMM4) ====================
__global__ void __launch_bounds__(256) gemm3() {
    __shared__ float Cs[64][64];
    __shared__ float Qs[64][65];
    int p2t = blockIdx.x, bh = blockIdx.y;
    int b = bh >> 3, head = bh & 7;
    int tid = threadIdx.x;
    const float* ctx = g_ctx + (size_t)bh*4096;
    for (int i = tid; i < 4096; i += 256) Cs[i>>6][i&63] = ctx[i];
    const float* qb = g_qs + ((size_t)bh*HW + p2t*64)*DH;
    #pragma unroll
    for (int i = 0; i < 16; i++) { int idx = tid + (i<<8); Qs[idx>>6][idx&63] = qb[idx]; }
    __syncthreads();
    int tx = tid & 15, ty = tid >> 4;
    float acc[4][4] = {};
    #pragma unroll
    for (int d = 0; d < 64; d++) {
        float a0 = Qs[(ty<<2)+0][d], a1 = Qs[(ty<<2)+1][d];
        float a2 = Qs[(ty<<2)+2][d], a3 = Qs[(ty<<2)+3][d];
        float4 bv = *(float4*)&Cs[d][tx<<2];
        acc[0][0]+=a0*bv.x; acc[0][1]+=a0*bv.y; acc[0][2]+=a0*bv.z; acc[0][3]+=a0*bv.w;
        acc[1][0]+=a1*bv.x; acc[1][1]+=a1*bv.y; acc[1][2]+=a1*bv.z; acc[1][3]+=a1*bv.w;
        acc[2][0]+=a2*bv.x; acc[2][1]+=a2*bv.y; acc[2][2]+=a2*bv.z; acc[2][3]+=a2*bv.w;
        acc[3][0]+=a3*bv.x; acc[3][1]+=a3*bv.y; acc[3][2]+=a3*bv.z; acc[3][3]+=a3*bv.w;
    }
    __syncthreads();
    #pragma unroll
    for (int i = 0; i < 4; i++)
        #pragma unroll
        for (int j = 0; j < 4; j++)
            Qs[(ty<<2)+i][(tx<<2)+j] = acc[i][j];   // [p2l][e]
    __syncthreads();
    size_t rowbase = (size_t)b*HW + p2t*64;
    #pragma unroll
    for (int i = 0; i < 16; i++) {
        int idx = tid + (i<<8); int pl = idx >> 6, e = idx & 63;
        float v = Qs[pl][e];
        __nv_bfloat16 h = __float2bfloat16(v);
        __nv_bfloat16 l = __float2bfloat16(v - __bfloat162float(h));
        size_t o = (rowbase + pl)*HID + head*DH + e;
        g_a3hi[o] = h;
        g_a3lo[o] = l;
    }
}

// ==================== launch ====================
#define SMEM_G1 83456    /* 2*40960 + 1536 */
#define SMEM_G4 105984   /* 2*51200 + 3584 */

extern "C" void kernel_launch(void* const* d_in, const int* in_sizes, int n_in,
                              void* d_out, int out_size) {
    const float* feat = (const float*)d_in[0];
    const float* gin  = (const float*)d_in[1];
    const float* wqkv = (const float*)d_in[2];
    const float* wout = (const float*)d_in[3];
    const float* gout = (const float*)d_in[4];
    float* out = (float*)d_out;

    cudaFuncSetAttribute(gemm_p<128,128,256,true>,
                         cudaFuncAttributeMaxDynamicSharedMemorySize, SMEM_G1);
    cudaFuncSetAttribute(gemm_p<256,64,512,false>,
                         cudaFuncAttributeMaxDynamicSharedMemorySize, SMEM_G4);

    prep_w1b<<<OQKV, 256>>>(wqkv, gin);
    prep_w2b<<<CCH, 256>>>(wout);
    conv_feat<<<dim3(HW/64, BATCH), 256>>>(feat);
    gemm_p<128,128,256,true><<<dim3(HW/128, OQKV/128, BATCH), 256, SMEM_G1>>>(nullptr, nullptr);
    qsoft<<<dim3(64, BHN), 256>>>();
    kstats<<<BHN*DH, 256>>>();
    vnorm<<<dim3(HW/256, BHN), 256>>>();
    gemm2<<<dim3(8, BHN), 256>>>();
    ctxred<<<BHN, 256>>>();
    gemm3<<<dim3(HW/64, BHN), 256>>>();
    gemm_p<256,64,512,false><<<dim3(HW/64, 1, BATCH), 256, SMEM_G4>>>(out, gout);
}

// round 6
// speedup vs baseline: 1.6448x; 1.1706x over previous
#include <cuda_runtime.h>
#include <cuda_bf16.h>
#include <math.h>
#include <stdint.h>

#define BATCH 16
#define CCH   256
#define HW    4096
#define HEADS 8
#define DH    64
#define HID   512
#define OQKV  1536
#define BHN   (BATCH*HEADS)   /* 128 */
#define QSCALE 0.125f
#define LNEPS  1e-5f
#define INV_N  (1.0f/4096.0f)
#define SPAD  40   /* smem row pitch in bf16: 80B -> 8 ldmatrix rows hit distinct banks */

// ==================== scratch (device globals; no allocations) ====================
__device__ __align__(256) float g_stat1[BATCH*HW*2];            // (mu, rstd) input LN
__device__ __align__(256) float g_ws[OQKV];                     // row sums of (w_qkv*g) eff
__device__ __align__(256) __nv_bfloat16 g_w1hi[OQKV*CCH];       // (w_qkv*g) hi  [o][c] K-major
__device__ __align__(256) __nv_bfloat16 g_w1lo[OQKV*CCH];
__device__ __align__(256) __nv_bfloat16 g_w2hi[CCH*HID];        // w_out hi [o][he] K-major
__device__ __align__(256) __nv_bfloat16 g_w2lo[CCH*HID];
__device__ __align__(256) __nv_bfloat16 g_fThi[(size_t)BATCH*HW*CCH];  // feature^T hi [b][p][c]
__device__ __align__(256) __nv_bfloat16 g_fTlo[(size_t)BATCH*HW*CCH];
__device__ __align__(256) float g_qkv[(size_t)BATCH*OQKV*HW];   // raw qkv fp32 (k,v regions used)
__device__ __align__(256) float g_qs[(size_t)BHN*HW*DH];        // softmaxed q [bh][p2][d]
__device__ __align__(256) float g_kpm[32*BHN*DH];               // per-tile partial max
__device__ __align__(256) float g_kps[32*BHN*DH];               // per-tile partial sumexp
__device__ __align__(256) float g_kmax[BHN*DH];
__device__ __align__(256) float g_ksum[BHN*DH];
__device__ __align__(256) float g_invn[BHN*HW];
__device__ __align__(256) float g_ctxp[8*BHN*DH*DH];
__device__ __align__(256) float g_ctx[BHN*DH*DH];
__device__ __align__(256) __nv_bfloat16 g_a3hi[(size_t)BATCH*HW*HID];  // [b][p][he] K-major
__device__ __align__(256) __nv_bfloat16 g_a3lo[(size_t)BATCH*HW*HID];

// ==================== helpers (sm_80+ PTX, valid on sm_100) ====================
__device__ __forceinline__ uint32_t smem_u32(const void* p) {
    uint32_t a;
    asm("{ .reg .u64 t; cvta.to.shared.u64 t, %1; cvt.u32.u64 %0, t; }" : "=r"(a) : "l"(p));
    return a;
}
__device__ __forceinline__ void ldmx4(uint32_t* r, uint32_t a) {
    asm volatile("ldmatrix.sync.aligned.m8n8.x4.shared.b16 {%0,%1,%2,%3}, [%4];"
        : "=r"(r[0]), "=r"(r[1]), "=r"(r[2]), "=r"(r[3]) : "r"(a));
}
__device__ __forceinline__ void mma_bf16(float* d, const uint32_t* a, uint32_t b0, uint32_t b1) {
    asm volatile("mma.sync.aligned.m16n8k16.row.col.f32.bf16.bf16.f32 "
        "{%0,%1,%2,%3}, {%4,%5,%6,%7}, {%8,%9}, {%0,%1,%2,%3};"
        : "+f"(d[0]), "+f"(d[1]), "+f"(d[2]), "+f"(d[3])
        : "r"(a[0]), "r"(a[1]), "r"(a[2]), "r"(a[3]), "r"(b0), "r"(b1));
}
__device__ __forceinline__ void cp16(uint32_t s, const void* g) {
    asm volatile("cp.async.cg.shared.global [%0], [%1], 16;" :: "r"(s), "l"(g) : "memory");
}
#define CP_COMMIT() asm volatile("cp.async.commit_group;" ::: "memory")
#define CP_WAIT1()  asm volatile("cp.async.wait_group 1;" ::: "memory")

// ==================== weight prep (bf16 hi/lo splits) ====================
__global__ void __launch_bounds__(256) prep_w1b(const float* __restrict__ wqkv,
                                                const float* __restrict__ gin) {
    int o = blockIdx.x, c = threadIdx.x;
    float w = wqkv[o*CCH + c] * gin[c];
    __nv_bfloat16 h = __float2bfloat16(w);
    __nv_bfloat16 l = __float2bfloat16(w - __bfloat162float(h));
    g_w1hi[o*CCH + c] = h;
    g_w1lo[o*CCH + c] = l;
    float we = __bfloat162float(h) + __bfloat162float(l);
    __shared__ float red[256];
    red[c] = we; __syncthreads();
    for (int s = 128; s > 0; s >>= 1) { if (c < s) red[c] += red[c+s]; __syncthreads(); }
    if (c == 0) g_ws[o] = red[0];
}

__global__ void __launch_bounds__(256) prep_w2b(const float* __restrict__ wout) {
    int o = blockIdx.x;
    for (int t = threadIdx.x; t < HID; t += 256) {
        float w = wout[o*HID + t];
        __nv_bfloat16 h = __float2bfloat16(w);
        __nv_bfloat16 l = __float2bfloat16(w - __bfloat162float(h));
        g_w2hi[o*HID + t] = h;
        g_w2lo[o*HID + t] = l;
    }
}

// ==================== feature transpose + bf16 split + LN stats (fused) ====================
__global__ void __launch_bounds__(256) conv_feat(const float* __restrict__ feat) {
    __shared__ float S[128][65];
    __shared__ float s_s[256], s_ss[256];
    int p0 = blockIdx.x*64, b = blockIdx.y;
    int tid = threadIdx.x;
    float sum = 0.f, ssum = 0.f;
    for (int h = 0; h < 2; h++) {
        #pragma unroll
        for (int i = 0; i < 32; i++) {
            int idx = tid + (i<<8);
            int cl = idx >> 6, pl = idx & 63;
            float v = feat[((size_t)(b*CCH + h*128 + cl))*HW + p0 + pl];
            S[cl][pl] = v;
            sum += v; ssum = fmaf(v, v, ssum);
        }
        __syncthreads();
        #pragma unroll
        for (int i = 0; i < 32; i++) {
            int idx = tid + (i<<8);
            int pl = idx >> 7, cl = idx & 127;
            float v = S[cl][pl];
            __nv_bfloat16 hi = __float2bfloat16(v);
            __nv_bfloat16 lo = __float2bfloat16(v - __bfloat162float(hi));
            size_t o = ((size_t)b*HW + p0 + pl)*CCH + h*128 + cl;
            g_fThi[o] = hi;
            g_fTlo[o] = lo;
        }
        __syncthreads();
    }
    s_s[tid] = sum; s_ss[tid] = ssum;
    __syncthreads();
    if (tid < 64) {
        float s  = s_s[tid] + s_s[tid+64] + s_s[tid+128] + s_s[tid+192];
        float ss = s_ss[tid] + s_ss[tid+64] + s_ss[tid+128] + s_ss[tid+192];
        float mu = s * (1.f/CCH);
        float var = fmaf(-mu, mu, ss * (1.f/CCH));
        ((float2*)g_stat1)[(size_t)b*HW + p0 + tid] = make_float2(mu, rsqrtf(var + LNEPS));
    }
}

// ==================== pipelined warp-MMA GEMM (bf16x3, cp.async, 2 CTA/SM) ====================
// G1=true : TM=128,TN=128,K=256. C rows = qkv channels. Epilogue by region:
//   q (by 0-3): softmax over d + spatial-transpose store to g_qs (g_qkv untouched)
//   k (by 4-7): store + per-tile online-softmax partials (g_kpm/g_kps)
//   v (by 8-11): store + per-pixel inv-norm (g_invn)
// G1=false: TM=256,TN=64,K=512. Epilogue = full output LayerNorm, writes d_out.
template<int TM, int TN, int KTOT, bool G1>
__global__ void __launch_bounds__(256, 2) gemm_p(float* __restrict__ Cext,
                                                 const float* __restrict__ gout) {
    extern __shared__ char smem[];
    constexpr int WN    = TN/32;
    constexpr int A_ARR = TM*SPAD*2;
    constexpr int B_ARR = TN*SPAD*2;
    constexpr int STAGE = 2*A_ARR + 2*B_ARR;
    constexpr int FIX   = 2*STAGE;
    constexpr int KC    = KTOT/32;

    int tid = threadIdx.x, wid = tid >> 5, lane = tid & 31;
    int b = blockIdx.z, m0 = blockIdx.y*TM, n0 = blockIdx.x*TN;
    int wm = wid / WN, wn = wid % WN;
    uint32_t sb = smem_u32(smem);

    const __nv_bfloat16* Ah = (G1 ? g_w1hi : g_w2hi) + (size_t)m0*KTOT;
    const __nv_bfloat16* Al = (G1 ? g_w1lo : g_w2lo) + (size_t)m0*KTOT;
    const __nv_bfloat16* Bh = (G1 ? g_fThi : g_a3hi) + ((size_t)b*HW + n0)*KTOT;
    const __nv_bfloat16* Bl = (G1 ? g_fTlo : g_a3lo) + ((size_t)b*HW + n0)*KTOT;
    float* Cb = (G1 ? g_qkv : Cext) + ((size_t)(b*(G1 ? OQKV : CCH) + m0))*HW + n0;

    float2* sstat = (float2*)(smem + FIX);          // G1
    float*  sws   = (float*)(smem + FIX + 1024);    // G1
    float*  sg    = (float*)(smem + FIX);           // G4
    float*  ps    = (float*)(smem + FIX + 1024);    // G4
    float*  pss   = (float*)(smem + FIX + 2048);    // G4
    float2* mrs   = (float2*)(smem + FIX + 3072);   // G4

    if (G1) {
        if (tid < 128) sstat[tid] = ((const float2*)g_stat1)[(size_t)b*HW + n0 + tid];
        else           sws[tid-128] = g_ws[m0 + tid - 128];
    } else {
        sg[tid] = gout[tid];
    }

    auto load_stage = [&](int kc, int s) {
        #pragma unroll
        for (int i = 0; i < TM*8/256; i++) {
            int e = tid + (i << 8);
            int arr = e >= TM*4;
            int rq = arr ? e - TM*4 : e;
            int r = rq >> 2, q = rq & 3;
            const __nv_bfloat16* gp = (arr ? Al : Ah) + (size_t)r*KTOT + kc*32 + q*8;
            cp16(sb + s*STAGE + arr*A_ARR + (r*SPAD + q*8)*2, gp);
        }
        #pragma unroll
        for (int i = 0; i < TN*8/256; i++) {
            int e = tid + (i << 8);
            int arr = e >= TN*4;
            int rq = arr ? e - TN*4 : e;
            int r = rq >> 2, q = rq & 3;
            const __nv_bfloat16* gp = (arr ? Bl : Bh) + (size_t)r*KTOT + kc*32 + q*8;
            cp16(sb + s*STAGE + 2*A_ARR + arr*B_ARR + (r*SPAD + q*8)*2, gp);
        }
    };

    float acc[4][4][4] = {};
    int lrow = (lane & 7) + (((lane >> 3) & 1) << 3);
    int lcol = (lane >> 4) << 3;

    load_stage(0, 0);
    CP_COMMIT();

    for (int kc = 0; kc < KC; kc++) {
        if (kc + 1 < KC) load_stage(kc+1, (kc+1) & 1);
        CP_COMMIT();
        CP_WAIT1();
        __syncthreads();
        uint32_t sbase = sb + (kc & 1)*STAGE;
        #pragma unroll
        for (int ks = 0; ks < 2; ks++) {
            int kof = ks*16 + lcol;
            uint32_t bfh[2][4], bfl[2][4];
            #pragma unroll
            for (int bt = 0; bt < 2; bt++) {
                int row = wn*32 + bt*16 + lrow;
                ldmx4(bfh[bt], sbase + 2*A_ARR + (row*SPAD + kof)*2);
                ldmx4(bfl[bt], sbase + 2*A_ARR + B_ARR + (row*SPAD + kof)*2);
            }
            #pragma unroll
            for (int mt = 0; mt < 4; mt++) {
                uint32_t afh[4], afl[4];
                int row = wm*64 + mt*16 + lrow;
                ldmx4(afh, sbase + (row*SPAD + kof)*2);
                ldmx4(afl, sbase + A_ARR + (row*SPAD + kof)*2);
                #pragma unroll
                for (int nt = 0; nt < 4; nt++) {
                    int bt = nt >> 1, od = nt & 1;
                    mma_bf16(acc[mt][nt], afh, bfh[bt][od], bfh[bt][od+2]);
                    mma_bf16(acc[mt][nt], afh, bfl[bt][od], bfl[bt][od+2]);
                    mma_bf16(acc[mt][nt], afl, bfh[bt][od], bfh[bt][od+2]);
                }
            }
        }
        __syncthreads();
    }

    if (G1) {
        // stash LN-folded tile to smem buf (pitch 130)
        float* buf = (float*)smem;
        #pragma unroll
        for (int mt = 0; mt < 4; mt++) {
            int rml = wm*64 + mt*16 + (lane >> 2);
            #pragma unroll
            for (int nt = 0; nt < 4; nt++) {
                int cl = wn*32 + nt*8 + 2*(lane & 3);
                float* d = acc[mt][nt];
                float2 s0 = sstat[cl], s1 = sstat[cl+1];
                float w0 = sws[rml], w1 = sws[rml+8];
                buf[rml*130 + cl]       = s0.y*(d[0] - s0.x*w0);
                buf[rml*130 + cl + 1]   = s1.y*(d[1] - s1.x*w0);
                buf[(rml+8)*130 + cl]     = s0.y*(d[2] - s0.x*w1);
                buf[(rml+8)*130 + cl + 1] = s1.y*(d[3] - s1.x*w1);
            }
        }
        __syncthreads();
        int region = blockIdx.y >> 2;
        if (region == 0) {
            // q: softmax over d (64 rows per head group) + transpose store to g_qs
            int col = tid & 127, g = tid >> 7;
            int p = n0 + col, h2 = p >> 6, wi = p & 63;
            int bh = b*8 + blockIdx.y*2 + g;
            float mx = -1e30f;
            #pragma unroll 8
            for (int d = 0; d < 64; d++) mx = fmaxf(mx, buf[(g*64+d)*130 + col]);
            float sum = 0.f;
            #pragma unroll 8
            for (int d = 0; d < 64; d++) {
                float e = __expf(buf[(g*64+d)*130 + col] - mx);
                buf[(g*64+d)*130 + col] = e;
                sum += e;
            }
            float r = QSCALE / sum;
            float4* dst = (float4*)&g_qs[((size_t)bh*HW + wi*64 + h2)*DH];
            #pragma unroll
            for (int d4 = 0; d4 < 16; d4++) {
                dst[d4] = make_float4(buf[(g*64+d4*4+0)*130+col]*r, buf[(g*64+d4*4+1)*130+col]*r,
                                      buf[(g*64+d4*4+2)*130+col]*r, buf[(g*64+d4*4+3)*130+col]*r);
            }
        } else {
            // k / v: store tile to g_qkv
            #pragma unroll 8
            for (int i = 0; i < 64; i++) {
                int idx = tid + (i << 8);
                int row = idx >> 7, col = idx & 127;
                Cb[(size_t)row*HW + col] = buf[row*130 + col];
            }
            if (region == 1) {
                // k: per-row online-softmax partial over this tile's 128 pixels
                int row = tid >> 1, half = tid & 1;
                float m = -1e30f;
                #pragma unroll 8
                for (int c = half*64; c < half*64 + 64; c++) m = fmaxf(m, buf[row*130 + c]);
                float s = 0.f;
                #pragma unroll 8
                for (int c = half*64; c < half*64 + 64; c++) s += __expf(buf[row*130 + c] - m);
                float om = __shfl_xor_sync(0xffffffffu, m, 1);
                float os = __shfl_xor_sync(0xffffffffu, s, 1);
                float M = fmaxf(m, om);
                float S = s*__expf(m - M) + os*__expf(om - M);
                if (half == 0) {
                    int ch = (blockIdx.y - 4)*128 + row;
                    int r = (b*8 + (ch >> 6))*64 + (ch & 63);
                    g_kpm[blockIdx.x*(BHN*DH) + r] = M;
                    g_kps[blockIdx.x*(BHN*DH) + r] = S;
                }
            } else {
                // v: per-pixel inverse norm over 64 rows (one head per group)
                int col = tid & 127, g = tid >> 7;
                float ss = 0.f;
                #pragma unroll 8
                for (int d = 0; d < 64; d++) {
                    float v = buf[(g*64+d)*130 + col];
                    ss = fmaf(v, v, ss);
                }
                int bh = b*8 + (blockIdx.y - 8)*2 + g;
                g_invn[(size_t)bh*HW + n0 + col] = 1.f / fmaxf(sqrtf(ss), 1e-12f);
            }
        }
    } else {
        // G4 epilogue: full output LN over 256 channels for 64 pixels, final store
        float* buf = (float*)smem;   // 256 x 64, pitch 68
        #pragma unroll
        for (int mt = 0; mt < 4; mt++) {
            int rml = wm*64 + mt*16 + (lane >> 2);
            #pragma unroll
            for (int nt = 0; nt < 4; nt++) {
                int cl = wn*32 + nt*8 + 2*(lane & 3);
                float* d = acc[mt][nt];
                buf[rml*68 + cl]     = d[0];
                buf[rml*68 + cl + 1] = d[1];
                buf[(rml+8)*68 + cl]     = d[2];
                buf[(rml+8)*68 + cl + 1] = d[3];
            }
        }
        __syncthreads();
        {
            int col = tid & 63, part = tid >> 6;
            float s = 0.f, ss = 0.f;
            #pragma unroll 8
            for (int r = part*64; r < part*64 + 64; r++) {
                float v = buf[r*68 + col];
                s += v; ss = fmaf(v, v, ss);
            }
            ps[part*64 + col] = s;
            pss[part*64 + col] = ss;
        }
        __syncthreads();
        if (tid < 64) {
            float s  = ps[tid] + ps[64+tid] + ps[128+tid] + ps[192+tid];
            float ss = pss[tid] + pss[64+tid] + pss[128+tid] + pss[192+tid];
            float mu = s * (1.f/CCH);
            float var = fmaf(-mu, mu, ss * (1.f/CCH));
            mrs[tid] = make_float2(mu, rsqrtf(var + LNEPS));
        }
        __syncthreads();
        #pragma unroll 8
        for (int i = 0; i < 64; i++) {
            int idx = tid + (i << 8);
            int row = idx >> 6, col = idx & 63;
            float2 st = mrs[col];
            Cb[(size_t)row*HW + col] = (buf[row*68 + col] - st.x) * st.y * sg[row];
        }
    }
}

// ==================== merge k-softmax partials over 32 tiles ====================
__global__ void __launch_bounds__(256) kmerge() {
    int r = blockIdx.x*8 + (threadIdx.x >> 5);
    int lane = threadIdx.x & 31;
    float m = g_kpm[lane*(BHN*DH) + r];
    float s = g_kps[lane*(BHN*DH) + r];
    float M = m;
    #pragma unroll
    for (int o = 16; o > 0; o >>= 1) M = fmaxf(M, __shfl_xor_sync(0xffffffffu, M, o));
    float sc = s * __expf(m - M);
    #pragma unroll
    for (int o = 16; o > 0; o >>= 1) sc += __shfl_xor_sync(0xffffffffu, sc, o);
    if (lane == 0) { g_kmax[r] = M; g_ksum[r] = sc; }
}

// ==================== context partials ====================
__global__ void __launch_bounds__(256) gemm2() {
    int sp = blockIdx.x, bh = blockIdx.y;
    int b = bh >> 3, head = bh & 7;
    const float* kbase = g_qkv + ((size_t)b*OQKV + HID   + head*DH)*HW;
    const float* vbase = g_qkv + ((size_t)b*OQKV + 2*HID + head*DH)*HW;
    __shared__ float Ks[64][36];
    __shared__ float Vs[64][36];
    __shared__ float smx[64], srs[64];
    __shared__ float sinv[512];
    int tid = threadIdx.x;
    if (tid < 64) { smx[tid] = g_kmax[bh*64 + tid]; srs[tid] = 1.f / g_ksum[bh*64 + tid]; }
    int n0 = sp*512;
    for (int i = tid; i < 512; i += 256) sinv[i] = g_invn[(size_t)bh*HW + n0 + i] * INV_N;
    __syncthreads();
    int tx = tid & 15, ty = tid >> 4;
    float acc[4][4] = {};
    for (int nt = 0; nt < 16; nt++) {
        int nb = n0 + nt*32;
        #pragma unroll
        for (int i = 0; i < 2; i++) {
            int idx = tid + (i<<8);
            int r = idx >> 3, cg = (idx & 7) << 2;
            float4 kv = *(const float4*)&kbase[(size_t)r*HW + nb + cg];
            float m = smx[r], rs = srs[r];
            float4 ke = make_float4(__expf(kv.x-m)*rs, __expf(kv.y-m)*rs,
                                    __expf(kv.z-m)*rs, __expf(kv.w-m)*rs);
            *(float4*)&Ks[r][cg] = ke;
            float4 vv = *(const float4*)&vbase[(size_t)r*HW + nb + cg];
            int ln = nt*32 + cg;
            float4 ve = make_float4(vv.x*sinv[ln+0], vv.y*sinv[ln+1],
                                    vv.z*sinv[ln+2], vv.w*sinv[ln+3]);
            *(float4*)&Vs[r][cg] = ve;
        }
        __syncthreads();
        #pragma unroll
        for (int nn = 0; nn < 32; nn += 4) {
            float4 av[4], bv[4];
            #pragma unroll
            for (int i = 0; i < 4; i++) av[i] = *(float4*)&Ks[(ty<<2)+i][nn];
            #pragma unroll
            for (int j = 0; j < 4; j++) bv[j] = *(float4*)&Vs[(tx<<2)+j][nn];
            #pragma unroll
            for (int i = 0; i < 4; i++)
                #pragma unroll
                for (int j = 0; j < 4; j++)
                    acc[i][j] += av[i].x*bv[j].x + av[i].y*bv[j].y
                               + av[i].z*bv[j].z + av[i].w*bv[j].w;
        }
        __syncthreads();
    }
    float* cp = g_ctxp + ((size_t)(sp*BHN + bh))*4096;
    #pragma unroll
    for (int i = 0; i < 4; i++) {
        float4 o = make_float4(acc[i][0], acc[i][1], acc[i][2], acc[i][3]);
        *(float4*)&cp[((ty<<2)+i)*64 + (tx<<2)] = o;
    }
}

__global__ void __launch_bounds__(256) ctxred() {
    int bh = blockIdx.x, tid = threadIdx.x;
    for (int i = tid; i < 4096; i += 256) {
        float s = 0.f;
        #pragma unroll
        for (int sp = 0; sp < 8; sp++) s += g_ctxp[((size_t)(sp*BHN + bh))*4096 + i];
        g_ctx[(size_t)bh*4096 + i] = s;
    }
}

// ==================== out = qs @ ctx -> a3 hi/lo [b][p][he] (K-major for GEMM4) ====================
__global__ void __launch_bounds__(256) gemm3() {
    __shared__ float Cs[64][64];
    __shared__ float Qs[64][65];
    int p2t = blockIdx.x, bh = blockIdx.y;
    int b = bh >> 3, head = bh & 7;
    int tid = threadIdx.x;
    const float* ctx = g_ctx + (size_t)bh*4096;
    for (int i = tid; i < 4096; i += 256) Cs[i>>6][i&63] = ctx[i];
    const float* qb = g_qs + ((size_t)bh*HW + p2t*64)*DH;
    #pragma unroll
    for (int i = 0; i < 16; i++) { int idx = tid + (i<<8); Qs[idx>>6][idx&63] = qb[idx]; }
    __syncthreads();
    int tx = tid & 15, ty = tid >> 4;
    float acc[4][4] = {};
    #pragma unroll
    for (int d = 0; d < 64; d++) {
        float a0 = Qs[(ty<<2)+0][d], a1 = Qs[(ty<<2)+1][d];
        float a2 = Qs[(ty<<2)+2][d], a3 = Qs[(ty<<2)+3][d];
        float4 bv = *(float4*)&Cs[d][tx<<2];
        acc[0][0]+=a0*bv.x; acc[0][1]+=a0*bv.y; acc[0][2]+=a0*bv.z; acc[0][3]+=a0*bv.w;
        acc[1][0]+=a1*bv.x; acc[1][1]+=a1*bv.y; acc[1][2]+=a1*bv.z; acc[1][3]+=a1*bv.w;
        acc[2][0]+=a2*bv.x; acc[2][1]+=a2*bv.y; acc[2][2]+=a2*bv.z; acc[2][3]+=a2*bv.w;
        acc[3][0]+=a3*bv.x; acc[3][1]+=a3*bv.y; acc[3][2]+=a3*bv.z; acc[3][3]+=a3*bv.w;
    }
    __syncthreads();
    #pragma unroll
    for (int i = 0; i < 4; i++)
        #pragma unroll
        for (int j = 0; j < 4; j++)
            Qs[(ty<<2)+i][(tx<<2)+j] = acc[i][j];   // [p2l][e]
    __syncthreads();
    size_t rowbase = (size_t)b*HW + p2t*64;
    #pragma unroll
    for (int i = 0; i < 16; i++) {
        int idx = tid + (i<<8); int pl = idx >> 6, e = idx & 63;
        float v = Qs[pl][e];
        __nv_bfloat16 h = __float2bfloat16(v);
        __nv_bfloat16 l = __float2bfloat16(v - __bfloat162float(h));
        size_t o = (rowbase + pl)*HID + head*DH + e;
        g_a3hi[o] = h;
        g_a3lo[o] = l;
    }
}

// ==================== launch ====================
#define SMEM_G1 83456    /* 2*40960 + 1536 */
#define SMEM_G4 105984   /* 2*51200 + 3584 */

extern "C" void kernel_launch(void* const* d_in, const int* in_sizes, int n_in,
                              void* d_out, int out_size) {
    const float* feat = (const float*)d_in[0];
    const float* gin  = (const float*)d_in[1];
    const float* wqkv = (const float*)d_in[2];
    const float* wout = (const float*)d_in[3];
    const float* gout = (const float*)d_in[4];
    float* out = (float*)d_out;

    cudaFuncSetAttribute(gemm_p<128,128,256,true>,
                         cudaFuncAttributeMaxDynamicSharedMemorySize, SMEM_G1);
    cudaFuncSetAttribute(gemm_p<256,64,512,false>,
                         cudaFuncAttributeMaxDynamicSharedMemorySize, SMEM_G4);

    prep_w1b<<<OQKV, 256>>>(wqkv, gin);
    prep_w2b<<<CCH, 256>>>(wout);
    conv_feat<<<dim3(HW/64, BATCH), 256>>>(feat);
    gemm_p<128,128,256,true><<<dim3(HW/128, OQKV/128, BATCH), 256, SMEM_G1>>>(nullptr, nullptr);
    kmerge<<<BHN*DH/8, 256>>>();
    gemm2<<<dim3(8, BHN), 256>>>();
    ctxred<<<BHN, 256>>>();
    gemm3<<<dim3(HW/64, BHN), 256>>>();
    gemm_p<256,64,512,false><<<dim3(HW/64, 1, BATCH), 256, SMEM_G4>>>(out, gout);
}

// round 8
// speedup vs baseline: 1.9586x; 1.1908x over previous
#include <cuda_runtime.h>
#include <cuda_fp16.h>
#include <math.h>
#include <stdint.h>

#define BATCH 16
#define CCH   256
#define HW    4096
#define HEADS 8
#define DH    64
#define HID   512
#define OQKV  1536
#define BHN   (BATCH*HEADS)   /* 128 */
#define QSCALE 0.125f
#define LNEPS  1e-5f
#define INV_N  (1.0f/4096.0f)
#define SPAD  40   /* smem row pitch in fp16: 80B -> 8 ldmatrix rows hit distinct banks */
#define A3SCALE    262144.0f          /* 2^18: lifts a3 (~4e-6) into fp16 normal range */
#define A3UNSCALE  (1.0f/262144.0f)

// ==================== scratch (device globals; no allocations) ====================
__device__ __align__(256) float g_stat1[BATCH*HW*2];            // (mu, rstd) input LN
__device__ __align__(256) float g_ws[OQKV];                     // row sums of (w_qkv*g) eff
__device__ __align__(256) __half g_w1hi[OQKV*CCH];              // (w_qkv*g) hi [o][c] K-major
__device__ __align__(256) __half g_w1lo[OQKV*CCH];
__device__ __align__(256) __half g_w2hi[CCH*HID];               // w_out hi [o][he] K-major
__device__ __align__(256) __half g_w2lo[CCH*HID];
__device__ __align__(256) __half g_fT[(size_t)BATCH*HW*CCH];    // feature^T fp16 [b][p][c]
__device__ __align__(256) float g_qkv[(size_t)BATCH*OQKV*HW];   // k,v regions fp32
__device__ __align__(256) float g_qs[(size_t)BHN*HW*DH];        // softmaxed q [bh][p2][d]
__device__ __align__(256) float g_kpm[32*BHN*DH];               // per-tile partial max
__device__ __align__(256) float g_kps[32*BHN*DH];               // per-tile partial sumexp
__device__ __align__(256) float g_kmax[BHN*DH];
__device__ __align__(256) float g_ksum[BHN*DH];
__device__ __align__(256) float g_invn[BHN*HW];
__device__ __align__(256) float g_ctxp[8*BHN*DH*DH];
__device__ __align__(256) float g_ctx[BHN*DH*DH];
__device__ __align__(256) __half g_a3[(size_t)BATCH*HW*HID];    // [b][p][he] K-major fp16 (x 2^18)

// ==================== helpers (sm_80+ PTX, valid on sm_100) ====================
__device__ __forceinline__ uint32_t smem_u32(const void* p) {
    uint32_t a;
    asm("{ .reg .u64 t; cvta.to.shared.u64 t, %1; cvt.u32.u64 %0, t; }" : "=r"(a) : "l"(p));
    return a;
}
__device__ __forceinline__ void ldmx4(uint32_t* r, uint32_t a) {
    asm volatile("ldmatrix.sync.aligned.m8n8.x4.shared.b16 {%0,%1,%2,%3}, [%4];"
        : "=r"(r[0]), "=r"(r[1]), "=r"(r[2]), "=r"(r[3]) : "r"(a));
}
__device__ __forceinline__ void mma_f16(float* d, const uint32_t* a, uint32_t b0, uint32_t b1) {
    asm volatile("mma.sync.aligned.m16n8k16.row.col.f32.f16.f16.f32 "
        "{%0,%1,%2,%3}, {%4,%5,%6,%7}, {%8,%9}, {%0,%1,%2,%3};"
        : "+f"(d[0]), "+f"(d[1]), "+f"(d[2]), "+f"(d[3])
        : "r"(a[0]), "r"(a[1]), "r"(a[2]), "r"(a[3]), "r"(b0), "r"(b1));
}
__device__ __forceinline__ void cp16(uint32_t s, const void* g) {
    asm volatile("cp.async.cg.shared.global [%0], [%1], 16;" :: "r"(s), "l"(g) : "memory");
}
#define CP_COMMIT() asm volatile("cp.async.commit_group;" ::: "memory")
#define CP_WAIT1()  asm volatile("cp.async.wait_group 1;" ::: "memory")

// ==================== weight prep (fp16 hi/lo splits) ====================
__global__ void __launch_bounds__(256) prep_w1b(const float* __restrict__ wqkv,
                                                const float* __restrict__ gin) {
    int o = blockIdx.x, c = threadIdx.x;
    float w = wqkv[o*CCH + c] * gin[c];
    __half h = __float2half_rn(w);
    __half l = __float2half_rn(w - __half2float(h));
    g_w1hi[o*CCH + c] = h;
    g_w1lo[o*CCH + c] = l;
    float we = __half2float(h) + __half2float(l);
    __shared__ float red[256];
    red[c] = we; __syncthreads();
    for (int s = 128; s > 0; s >>= 1) { if (c < s) red[c] += red[c+s]; __syncthreads(); }
    if (c == 0) g_ws[o] = red[0];
}

__global__ void __launch_bounds__(256) prep_w2b(const float* __restrict__ wout) {
    int o = blockIdx.x;
    for (int t = threadIdx.x; t < HID; t += 256) {
        float w = wout[o*HID + t];
        __half h = __float2half_rn(w);
        __half l = __float2half_rn(w - __half2float(h));
        g_w2hi[o*HID + t] = h;
        g_w2lo[o*HID + t] = l;
    }
}

// ==================== feature transpose + fp16 + LN stats (fused) ====================
__global__ void __launch_bounds__(256) conv_feat(const float* __restrict__ feat) {
    __shared__ float S[128][65];
    __shared__ float s_s[256], s_ss[256];
    int p0 = blockIdx.x*64, b = blockIdx.y;
    int tid = threadIdx.x;
    float sum = 0.f, ssum = 0.f;
    for (int h = 0; h < 2; h++) {
        #pragma unroll
        for (int i = 0; i < 32; i++) {
            int idx = tid + (i<<8);
            int cl = idx >> 6, pl = idx & 63;
            float v = feat[((size_t)(b*CCH + h*128 + cl))*HW + p0 + pl];
            S[cl][pl] = v;
            sum += v; ssum = fmaf(v, v, ssum);
        }
        __syncthreads();
        #pragma unroll
        for (int i = 0; i < 32; i++) {
            int idx = tid + (i<<8);
            int pl = idx >> 7, cl = idx & 127;
            g_fT[((size_t)b*HW + p0 + pl)*CCH + h*128 + cl] = __float2half_rn(S[cl][pl]);
        }
        __syncthreads();
    }
    s_s[tid] = sum; s_ss[tid] = ssum;
    __syncthreads();
    if (tid < 64) {
        float s  = s_s[tid] + s_s[tid+64] + s_s[tid+128] + s_s[tid+192];
        float ss = s_ss[tid] + s_ss[tid+64] + s_ss[tid+128] + s_ss[tid+192];
        float mu = s * (1.f/CCH);
        float var = fmaf(-mu, mu, ss * (1.f/CCH));
        ((float2*)g_stat1)[(size_t)b*HW + p0 + tid] = make_float2(mu, rsqrtf(var + LNEPS));
    }
}

// ==================== pipelined warp-MMA GEMM (fp16x2 asym, cp.async, 2 CTA/SM) ====================
// A = weights split hi+lo fp16 (exact), B = activations single fp16.
// G1=true : TM=128,TN=128,K=256. Epilogue by qkv region (q-softmax / k-partials / v-norm).
// G1=false: TM=256,TN=64, K=512. Epilogue = unscale 2^-18, full output LayerNorm, writes d_out.
template<int TM, int TN, int KTOT, bool G1>
__global__ void __launch_bounds__(256, 2) gemm_p(float* __restrict__ Cext,
                                                 const float* __restrict__ gout) {
    extern __shared__ char smem[];
    constexpr int WN    = TN/32;
    constexpr int A_ARR = TM*SPAD*2;
    constexpr int B_ARR = TN*SPAD*2;
    constexpr int STAGE = 2*A_ARR + B_ARR;
    constexpr int BUFB  = TM*(G1 ? (TN+2) : (TN+4))*4;
    constexpr int FIX   = (2*STAGE > BUFB) ? 2*STAGE : BUFB;
    constexpr int KC    = KTOT/32;

    int tid = threadIdx.x, wid = tid >> 5, lane = tid & 31;
    int b = blockIdx.z, m0 = blockIdx.y*TM, n0 = blockIdx.x*TN;
    int wm = wid / WN, wn = wid % WN;
    uint32_t sb = smem_u32(smem);

    const __half* Ah = (G1 ? g_w1hi : g_w2hi) + (size_t)m0*KTOT;
    const __half* Al = (G1 ? g_w1lo : g_w2lo) + (size_t)m0*KTOT;
    const __half* Bp = (G1 ? g_fT : g_a3) + ((size_t)b*HW + n0)*KTOT;
    float* Cb = (G1 ? g_qkv : Cext) + ((size_t)(b*(G1 ? OQKV : CCH) + m0))*HW + n0;

    float2* sstat = (float2*)(smem + FIX);          // G1
    float*  sws   = (float*)(smem + FIX + 1024);    // G1
    float*  sg    = (float*)(smem + FIX);           // G4
    float*  ps    = (float*)(smem + FIX + 1024);    // G4
    float*  pss   = (float*)(smem + FIX + 2048);    // G4
    float2* mrs   = (float2*)(smem + FIX + 3072);   // G4

    if (G1) {
        if (tid < 128) sstat[tid] = ((const float2*)g_stat1)[(size_t)b*HW + n0 + tid];
        else           sws[tid-128] = g_ws[m0 + tid - 128];
    } else {
        sg[tid] = gout[tid];
    }

    auto load_stage = [&](int kc, int s) {
        #pragma unroll
        for (int i = 0; i < TM*8/256; i++) {          // A hi+lo
            int e = tid + (i << 8);
            int arr = e >= TM*4;
            int rq = arr ? e - TM*4 : e;
            int r = rq >> 2, q = rq & 3;
            const __half* gp = (arr ? Al : Ah) + (size_t)r*KTOT + kc*32 + q*8;
            cp16(sb + s*STAGE + arr*A_ARR + (r*SPAD + q*8)*2, gp);
        }
        #pragma unroll
        for (int i = 0; i < TN*4/256; i++) {          // B single
            int e = tid + (i << 8);
            int r = e >> 2, q = e & 3;
            const __half* gp = Bp + (size_t)r*KTOT + kc*32 + q*8;
            cp16(sb + s*STAGE + 2*A_ARR + (r*SPAD + q*8)*2, gp);
        }
    };

    float acc[4][4][4] = {};
    int lrow = (lane & 7) + (((lane >> 3) & 1) << 3);
    int lcol = (lane >> 4) << 3;

    load_stage(0, 0);
    CP_COMMIT();

    for (int kc = 0; kc < KC; kc++) {
        if (kc + 1 < KC) load_stage(kc+1, (kc+1) & 1);
        CP_COMMIT();
        CP_WAIT1();
        __syncthreads();
        uint32_t sbase = sb + (kc & 1)*STAGE;
        #pragma unroll
        for (int ks = 0; ks < 2; ks++) {
            int kof = ks*16 + lcol;
            uint32_t bf[2][4];
            #pragma unroll
            for (int bt = 0; bt < 2; bt++) {
                int row = wn*32 + bt*16 + lrow;
                ldmx4(bf[bt], sbase + 2*A_ARR + (row*SPAD + kof)*2);
            }
            #pragma unroll
            for (int mt = 0; mt < 4; mt++) {
                uint32_t afh[4], afl[4];
                int row = wm*64 + mt*16 + lrow;
                ldmx4(afh, sbase + (row*SPAD + kof)*2);
                ldmx4(afl, sbase + A_ARR + (row*SPAD + kof)*2);
                #pragma unroll
                for (int nt = 0; nt < 4; nt++) {
                    int bt = nt >> 1, od = nt & 1;
                    mma_f16(acc[mt][nt], afh, bf[bt][od], bf[bt][od+2]);
                    mma_f16(acc[mt][nt], afl, bf[bt][od], bf[bt][od+2]);
                }
            }
        }
        __syncthreads();
    }

    if (G1) {
        float* buf = (float*)smem;   // 128 x 128, pitch 130
        #pragma unroll
        for (int mt = 0; mt < 4; mt++) {
            int rml = wm*64 + mt*16 + (lane >> 2);
            #pragma unroll
            for (int nt = 0; nt < 4; nt++) {
                int cl = wn*32 + nt*8 + 2*(lane & 3);
                float* d = acc[mt][nt];
                float2 s0 = sstat[cl], s1 = sstat[cl+1];
                float w0 = sws[rml], w1 = sws[rml+8];
                buf[rml*130 + cl]       = s0.y*(d[0] - s0.x*w0);
                buf[rml*130 + cl + 1]   = s1.y*(d[1] - s1.x*w0);
                buf[(rml+8)*130 + cl]     = s0.y*(d[2] - s0.x*w1);
                buf[(rml+8)*130 + cl + 1] = s1.y*(d[3] - s1.x*w1);
            }
        }
        __syncthreads();
        int region = blockIdx.y >> 2;
        if (region == 0) {
            // q: softmax over d + spatial-transpose store to g_qs
            int col = tid & 127, g = tid >> 7;
            int p = n0 + col, h2 = p >> 6, wi = p & 63;
            int bh = b*8 + blockIdx.y*2 + g;
            float mx = -1e30f;
            #pragma unroll 8
            for (int d = 0; d < 64; d++) mx = fmaxf(mx, buf[(g*64+d)*130 + col]);
            float sum = 0.f;
            #pragma unroll 8
            for (int d = 0; d < 64; d++) {
                float e = __expf(buf[(g*64+d)*130 + col] - mx);
                buf[(g*64+d)*130 + col] = e;
                sum += e;
            }
            float r = QSCALE / sum;
            float4* dst = (float4*)&g_qs[((size_t)bh*HW + wi*64 + h2)*DH];
            #pragma unroll
            for (int d4 = 0; d4 < 16; d4++) {
                dst[d4] = make_float4(buf[(g*64+d4*4+0)*130+col]*r, buf[(g*64+d4*4+1)*130+col]*r,
                                      buf[(g*64+d4*4+2)*130+col]*r, buf[(g*64+d4*4+3)*130+col]*r);
            }
        } else {
            #pragma unroll 8
            for (int i = 0; i < 64; i++) {
                int idx = tid + (i << 8);
                int row = idx >> 7, col = idx & 127;
                Cb[(size_t)row*HW + col] = buf[row*130 + col];
            }
            if (region == 1) {
                // k: per-row online-softmax partial over this tile's 128 pixels
                int row = tid >> 1, half = tid & 1;
                float m = -1e30f;
                #pragma unroll 8
                for (int c = half*64; c < half*64 + 64; c++) m = fmaxf(m, buf[row*130 + c]);
                float s = 0.f;
                #pragma unroll 8
                for (int c = half*64; c < half*64 + 64; c++) s += __expf(buf[row*130 + c] - m);
                float om = __shfl_xor_sync(0xffffffffu, m, 1);
                float os = __shfl_xor_sync(0xffffffffu, s, 1);
                float M = fmaxf(m, om);
                float S = s*__expf(m - M) + os*__expf(om - M);
                if (half == 0) {
                    int ch = (blockIdx.y - 4)*128 + row;
                    int r = (b*8 + (ch >> 6))*64 + (ch & 63);
                    g_kpm[blockIdx.x*(BHN*DH) + r] = M;
                    g_kps[blockIdx.x*(BHN*DH) + r] = S;
                }
            } else {
                // v: per-pixel inverse norm over 64 rows (one head per group)
                int col = tid & 127, g = tid >> 7;
                float ss = 0.f;
                #pragma unroll 8
                for (int d = 0; d < 64; d++) {
                    float v = buf[(g*64+d)*130 + col];
                    ss = fmaf(v, v, ss);
                }
                int bh = b*8 + (blockIdx.y - 8)*2 + g;
                g_invn[(size_t)bh*HW + n0 + col] = 1.f / fmaxf(sqrtf(ss), 1e-12f);
            }
        }
    } else {
        // G4 epilogue: unscale a3 factor, then full output LN over 256 channels
        float* buf = (float*)smem;   // 256 x 64, pitch 68
        #pragma unroll
        for (int mt = 0; mt < 4; mt++) {
            int rml = wm*64 + mt*16 + (lane >> 2);
            #pragma unroll
            for (int nt = 0; nt < 4; nt++) {
                int cl = wn*32 + nt*8 + 2*(lane & 3);
                float* d = acc[mt][nt];
                buf[rml*68 + cl]     = d[0] * A3UNSCALE;
                buf[rml*68 + cl + 1] = d[1] * A3UNSCALE;
                buf[(rml+8)*68 + cl]     = d[2] * A3UNSCALE;
                buf[(rml+8)*68 + cl + 1] = d[3] * A3UNSCALE;
            }
        }
        __syncthreads();
        {
            int col = tid & 63, part = tid >> 6;
            float s = 0.f, ss = 0.f;
            #pragma unroll 8
            for (int r = part*64; r < part*64 + 64; r++) {
                float v = buf[r*68 + col];
                s += v; ss = fmaf(v, v, ss);
            }
            ps[part*64 + col] = s;
            pss[part*64 + col] = ss;
        }
        __syncthreads();
        if (tid < 64) {
            float s  = ps[tid] + ps[64+tid] + ps[128+tid] + ps[192+tid];
            float ss = pss[tid] + pss[64+tid] + pss[128+tid] + pss[192+tid];
            float mu = s * (1.f/CCH);
            float var = fmaf(-mu, mu, ss * (1.f/CCH));
            mrs[tid] = make_float2(mu, rsqrtf(var + LNEPS));
        }
        __syncthreads();
        #pragma unroll 8
        for (int i = 0; i < 64; i++) {
            int idx = tid + (i << 8);
            int row = idx >> 6, col = idx & 63;
            float2 st = mrs[col];
            Cb[(size_t)row*HW + col] = (buf[row*68 + col] - st.x) * st.y * sg[row];
        }
    }
}

// ==================== merge k-softmax partials over 32 tiles ====================
__global__ void __launch_bounds__(256) kmerge() {
    int r = blockIdx.x*8 + (threadIdx.x >> 5);
    int lane = threadIdx.x & 31;
    float m = g_kpm[lane*(BHN*DH) + r];
    float s = g_kps[lane*(BHN*DH) + r];
    float M = m;
    #pragma unroll
    for (int o = 16; o > 0; o >>= 1) M = fmaxf(M, __shfl_xor_sync(0xffffffffu, M, o));
    float sc = s * __expf(m - M);
    #pragma unroll
    for (int o = 16; o > 0; o >>= 1) sc += __shfl_xor_sync(0xffffffffu, sc, o);
    if (lane == 0) { g_kmax[r] = M; g_ksum[r] = sc; }
}

// ==================== context partials ====================
__global__ void __launch_bounds__(256) gemm2() {
    int sp = blockIdx.x, bh = blockIdx.y;
    int b = bh >> 3, head = bh & 7;
    const float* kbase = g_qkv + ((size_t)b*OQKV + HID   + head*DH)*HW;
    const float* vbase = g_qkv + ((size_t)b*OQKV + 2*HID + head*DH)*HW;
    __shared__ float Ks[64][36];
    __shared__ float Vs[64][36];
    __shared__ float smx[64], srs[64];
    __shared__ float sinv[512];
    int tid = threadIdx.x;
    if (tid < 64) { smx[tid] = g_kmax[bh*64 + tid]; srs[tid] = 1.f / g_ksum[bh*64 + tid]; }
    int n0 = sp*512;
    for (int i = tid; i < 512; i += 256) sinv[i] = g_invn[(size_t)bh*HW + n0 + i] * INV_N;
    __syncthreads();
    int tx = tid & 15, ty = tid >> 4;
    float acc[4][4] = {};
    for (int nt = 0; nt < 16; nt++) {
        int nb = n0 + nt*32;
        #pragma unroll
        for (int i = 0; i < 2; i++) {
            int idx = tid + (i<<8);
            int r = idx >> 3, cg = (idx & 7) << 2;
            float4 kv = *(const float4*)&kbase[(size_t)r*HW + nb + cg];
            float m = smx[r], rs = srs[r];
            float4 ke = make_float4(__expf(kv.x-m)*rs, __expf(kv.y-m)*rs,
                                    __expf(kv.z-m)*rs, __expf(kv.w-m)*rs);
            *(float4*)&Ks[r][cg] = ke;
            float4 vv = *(const float4*)&vbase[(size_t)r*HW + nb + cg];
            int ln = nt*32 + cg;
            float4 ve = make_float4(vv.x*sinv[ln+0], vv.y*sinv[ln+1],
                                    vv.z*sinv[ln+2], vv.w*sinv[ln+3]);
            *(float4*)&Vs[r][cg] = ve;
        }
        __syncthreads();
        #pragma unroll
        for (int nn = 0; nn < 32; nn += 4) {
            float4 av[4], bv[4];
            #pragma unroll
            for (int i = 0; i < 4; i++) av[i] = *(float4*)&Ks[(ty<<2)+i][nn];
            #pragma unroll
            for (int j = 0; j < 4; j++) bv[j] = *(float4*)&Vs[(tx<<2)+j][nn];
            #pragma unroll
            for (int i = 0; i < 4; i++)
                #pragma unroll
                for (int j = 0; j < 4; j++)
                    acc[i][j] += av[i].x*bv[j].x + av[i].y*bv[j].y
                               + av[i].z*bv[j].z + av[i].w*bv[j].w;
        }
        __syncthreads();
    }
    float* cp = g_ctxp + ((size_t)(sp*BHN + bh))*4096;
    #pragma unroll
    for (int i = 0; i < 4; i++) {
        float4 o = make_float4(acc[i][0], acc[i][1], acc[i][2], acc[i][3]);
        *(float4*)&cp[((ty<<2)+i)*64 + (tx<<2)] = o;
    }
}

__global__ void __launch_bounds__(256) ctxred() {
    int bh = blockIdx.x, tid = threadIdx.x;
    for (int i = tid; i < 4096; i += 256) {
        float s = 0.f;
        #pragma unroll
        for (int sp = 0; sp < 8; sp++) s += g_ctxp[((size_t)(sp*BHN + bh))*4096 + i];
        g_ctx[(size_t)bh*4096 + i] = s;
    }
}

// ==================== out = qs @ ctx -> a3 fp16 (x 2^18) [b][p][he] ====================
__global__ void __launch_bounds__(256) gemm3() {
    __shared__ float Cs[64][64];
    __shared__ float Qs[64][65];
    int p2t = blockIdx.x, bh = blockIdx.y;
    int b = bh >> 3, head = bh & 7;
    int tid = threadIdx.x;
    const float* ctx = g_ctx + (size_t)bh*4096;
    for (int i = tid; i < 4096; i += 256) Cs[i>>6][i&63] = ctx[i];
    const float* qb = g_qs + ((size_t)bh*HW + p2t*64)*DH;
    #pragma unroll
    for (int i = 0; i < 16; i++) { int idx = tid + (i<<8); Qs[idx>>6][idx&63] = qb[idx]; }
    __syncthreads();
    int tx = tid & 15, ty = tid >> 4;
    float acc[4][4] = {};
    #pragma unroll
    for (int d = 0; d < 64; d++) {
        float a0 = Qs[(ty<<2)+0][d], a1 = Qs[(ty<<2)+1][d];
        float a2 = Qs[(ty<<2)+2][d], a3 = Qs[(ty<<2)+3][d];
        float4 bv = *(float4*)&Cs[d][tx<<2];
        acc[0][0]+=a0*bv.x; acc[0][1]+=a0*bv.y; acc[0][2]+=a0*bv.z; acc[0][3]+=a0*bv.w;
        acc[1][0]+=a1*bv.x; acc[1][1]+=a1*bv.y; acc[1][2]+=a1*bv.z; acc[1][3]+=a1*bv.w;
        acc[2][0]+=a2*bv.x; acc[2][1]+=a2*bv.y; acc[2][2]+=a2*bv.z; acc[2][3]+=a2*bv.w;
        acc[3][0]+=a3*bv.x; acc[3][1]+=a3*bv.y; acc[3][2]+=a3*bv.z; acc[3][3]+=a3*bv.w;
    }
    __syncthreads();
    #pragma unroll
    for (int i = 0; i < 4; i++)
        #pragma unroll
        for (int j = 0; j < 4; j++)
            Qs[(ty<<2)+i][(tx<<2)+j] = acc[i][j];   // [p2l][e]
    __syncthreads();
    size_t rowbase = (size_t)b*HW + p2t*64;
    #pragma unroll
    for (int i = 0; i < 16; i++) {
        int idx = tid + (i<<8); int pl = idx >> 6, e = idx & 63;
        g_a3[(rowbase + pl)*HID + head*DH + e] = __float2half_rn(Qs[pl][e] * A3SCALE);
    }
}

// ==================== launch ====================
#define SMEM_G1 68096    /* max(2*30720, 128*130*4)=66560 + 1536 */
#define SMEM_G4 95744    /* max(2*46080, 256*68*4)=92160 + 3584 */

extern "C" void kernel_launch(void* const* d_in, const int* in_sizes, int n_in,
                              void* d_out, int out_size) {
    const float* feat = (const float*)d_in[0];
    const float* gin  = (const float*)d_in[1];
    const float* wqkv = (const float*)d_in[2];
    const float* wout = (const float*)d_in[3];
    const float* gout = (const float*)d_in[4];
    float* out = (float*)d_out;

    cudaFuncSetAttribute(gemm_p<128,128,256,true>,
                         cudaFuncAttributeMaxDynamicSharedMemorySize, SMEM_G1);
    cudaFuncSetAttribute(gemm_p<256,64,512,false>,
                         cudaFuncAttributeMaxDynamicSharedMemorySize, SMEM_G4);

    prep_w1b<<<OQKV, 256>>>(wqkv, gin);
    prep_w2b<<<CCH, 256>>>(wout);
    conv_feat<<<dim3(HW/64, BATCH), 256>>>(feat);
    gemm_p<128,128,256,true><<<dim3(HW/128, OQKV/128, BATCH), 256, SMEM_G1>>>(nullptr, nullptr);
    kmerge<<<BHN*DH/8, 256>>>();
    gemm2<<<dim3(8, BHN), 256>>>();
    ctxred<<<BHN, 256>>>();
    gemm3<<<dim3(HW/64, BHN), 256>>>();
    gemm_p<256,64,512,false><<<dim3(HW/64, 1, BATCH), 256, SMEM_G4>>>(out, gout);
}

// round 9
// speedup vs baseline: 2.0303x; 1.0366x over previous
#include <cuda_runtime.h>
#include <cuda_fp16.h>
#include <math.h>
#include <stdint.h>

#define BATCH 16
#define CCH   256
#define HW    4096
#define HEADS 8
#define DH    64
#define HID   512
#define OQKV  1536
#define BHN   (BATCH*HEADS)   /* 128 */
#define QSCALE 0.125f
#define LNEPS  1e-5f
#define INV_N  (1.0f/4096.0f)
#define SPAD  40   /* smem row pitch in fp16: 80B -> 8 ldmatrix rows hit distinct banks */
#define A3SCALE    262144.0f          /* 2^18: lifts a3 (~4e-6) into fp16 normal range */
#define A3UNSCALE  (1.0f/262144.0f)

// ==================== scratch (device globals; no allocations) ====================
__device__ __align__(256) float g_stat1[BATCH*HW*2];            // (mu, rstd) input LN
__device__ __align__(256) float g_ws[OQKV];                     // row sums of (w_qkv*g) eff
__device__ __align__(256) __half g_w1hi[OQKV*CCH];              // (w_qkv*g) hi [o][c] K-major
__device__ __align__(256) __half g_w1lo[OQKV*CCH];
__device__ __align__(256) __half g_w2hi[CCH*HID];               // w_out hi [o][he] K-major
__device__ __align__(256) __half g_w2lo[CCH*HID];
__device__ __align__(256) __half g_fT[(size_t)BATCH*HW*CCH];    // feature^T fp16 [b][p][c]
__device__ __align__(256) __half g_kv[(size_t)BATCH*1024*HW];   // k (ch 0-511), v (512-1023) fp16
__device__ __align__(256) __half g_qs[(size_t)BHN*HW*DH];       // softmaxed q fp16 [bh][p2][d]
__device__ __align__(256) float g_kpm[32*BHN*DH];               // per-tile partial max
__device__ __align__(256) float g_kps[32*BHN*DH];               // per-tile partial sumexp
__device__ __align__(256) float g_kmax[BHN*DH];
__device__ __align__(256) float g_ksum[BHN*DH];
__device__ __align__(256) float g_invn[BHN*HW];
__device__ __align__(256) float g_ctxp[8*BHN*DH*DH];
__device__ __align__(256) float g_ctx[BHN*DH*DH];
__device__ __align__(256) __half g_a3[(size_t)BATCH*HW*HID];    // [b][p][he] fp16 (x 2^18)

// ==================== helpers (sm_80+ PTX, valid on sm_100) ====================
__device__ __forceinline__ uint32_t smem_u32(const void* p) {
    uint32_t a;
    asm("{ .reg .u64 t; cvta.to.shared.u64 t, %1; cvt.u32.u64 %0, t; }" : "=r"(a) : "l"(p));
    return a;
}
__device__ __forceinline__ void ldmx4(uint32_t* r, uint32_t a) {
    asm volatile("ldmatrix.sync.aligned.m8n8.x4.shared.b16 {%0,%1,%2,%3}, [%4];"
        : "=r"(r[0]), "=r"(r[1]), "=r"(r[2]), "=r"(r[3]) : "r"(a));
}
__device__ __forceinline__ void mma_f16(float* d, const uint32_t* a, uint32_t b0, uint32_t b1) {
    asm volatile("mma.sync.aligned.m16n8k16.row.col.f32.f16.f16.f32 "
        "{%0,%1,%2,%3}, {%4,%5,%6,%7}, {%8,%9}, {%0,%1,%2,%3};"
        : "+f"(d[0]), "+f"(d[1]), "+f"(d[2]), "+f"(d[3])
        : "r"(a[0]), "r"(a[1]), "r"(a[2]), "r"(a[3]), "r"(b0), "r"(b1));
}
__device__ __forceinline__ void cp16(uint32_t s, const void* g) {
    asm volatile("cp.async.cg.shared.global [%0], [%1], 16;" :: "r"(s), "l"(g) : "memory");
}
#define CP_COMMIT() asm volatile("cp.async.commit_group;" ::: "memory")
#define CP_WAIT1()  asm volatile("cp.async.wait_group 1;" ::: "memory")
#define CP_WAIT0()  asm volatile("cp.async.wait_group 0;" ::: "memory")

// ==================== weight prep (fp16 hi/lo splits) ====================
__global__ void __launch_bounds__(256) prep_w1b(const float* __restrict__ wqkv,
                                                const float* __restrict__ gin) {
    int o = blockIdx.x, c = threadIdx.x;
    float w = wqkv[o*CCH + c] * gin[c];
    __half h = __float2half_rn(w);
    __half l = __float2half_rn(w - __half2float(h));
    g_w1hi[o*CCH + c] = h;
    g_w1lo[o*CCH + c] = l;
    float we = __half2float(h) + __half2float(l);
    __shared__ float red[256];
    red[c] = we; __syncthreads();
    for (int s = 128; s > 0; s >>= 1) { if (c < s) red[c] += red[c+s]; __syncthreads(); }
    if (c == 0) g_ws[o] = red[0];
}

__global__ void __launch_bounds__(256) prep_w2b(const float* __restrict__ wout) {
    int o = blockIdx.x;
    for (int t = threadIdx.x; t < HID; t += 256) {
        float w = wout[o*HID + t];
        __half h = __float2half_rn(w);
        __half l = __float2half_rn(w - __half2float(h));
        g_w2hi[o*HID + t] = h;
        g_w2lo[o*HID + t] = l;
    }
}

// ==================== feature transpose + fp16 + LN stats (fused) ====================
__global__ void __launch_bounds__(256) conv_feat(const float* __restrict__ feat) {
    __shared__ float S[128][65];
    __shared__ float s_s[256], s_ss[256];
    int p0 = blockIdx.x*64, b = blockIdx.y;
    int tid = threadIdx.x;
    float sum = 0.f, ssum = 0.f;
    for (int h = 0; h < 2; h++) {
        #pragma unroll
        for (int i = 0; i < 32; i++) {
            int idx = tid + (i<<8);
            int cl = idx >> 6, pl = idx & 63;
            float v = feat[((size_t)(b*CCH + h*128 + cl))*HW + p0 + pl];
            S[cl][pl] = v;
            sum += v; ssum = fmaf(v, v, ssum);
        }
        __syncthreads();
        #pragma unroll
        for (int i = 0; i < 32; i++) {
            int idx = tid + (i<<8);
            int pl = idx >> 7, cl = idx & 127;
            g_fT[((size_t)b*HW + p0 + pl)*CCH + h*128 + cl] = __float2half_rn(S[cl][pl]);
        }
        __syncthreads();
    }
    s_s[tid] = sum; s_ss[tid] = ssum;
    __syncthreads();
    if (tid < 64) {
        float s  = s_s[tid] + s_s[tid+64] + s_s[tid+128] + s_s[tid+192];
        float ss = s_ss[tid] + s_ss[tid+64] + s_ss[tid+128] + s_ss[tid+192];
        float mu = s * (1.f/CCH);
        float var = fmaf(-mu, mu, ss * (1.f/CCH));
        ((float2*)g_stat1)[(size_t)b*HW + p0 + tid] = make_float2(mu, rsqrtf(var + LNEPS));
    }
}

// ==================== pipelined warp-MMA GEMM (fp16x2 asym, cp.async, 2 CTA/SM) ====================
// G1=true : TM=128,TN=128,K=256, 3-stage pipeline, 1 barrier/chunk.
//   Epilogue by region: q->softmax+transpose to g_qs(fp16); k->g_kv fp16 + partials; v->g_kv fp16 + inv-norm.
// G1=false: TM=256,TN=64, K=512, 2-stage. Epilogue = unscale 2^-18 + full output LN -> d_out.
template<int TM, int TN, int KTOT, bool G1>
__global__ void __launch_bounds__(256, 2) gemm_p(float* __restrict__ Cext,
                                                 const float* __restrict__ gout) {
    extern __shared__ char smem[];
    constexpr int WN     = TN/32;
    constexpr int A_ARR  = TM*SPAD*2;
    constexpr int B_ARR  = TN*SPAD*2;
    constexpr int STAGE  = 2*A_ARR + B_ARR;
    constexpr int NSTG   = G1 ? 3 : 2;
    constexpr int BUFB   = TM*(G1 ? (TN+2) : (TN+4))*4;
    constexpr int FIX    = (NSTG*STAGE > BUFB) ? NSTG*STAGE : BUFB;
    constexpr int KC     = KTOT/32;

    int tid = threadIdx.x, wid = tid >> 5, lane = tid & 31;
    int b = blockIdx.z, m0 = blockIdx.y*TM, n0 = blockIdx.x*TN;
    int wm = wid / WN, wn = wid % WN;
    uint32_t sb = smem_u32(smem);

    const __half* Ah = (G1 ? g_w1hi : g_w2hi) + (size_t)m0*KTOT;
    const __half* Al = (G1 ? g_w1lo : g_w2lo) + (size_t)m0*KTOT;
    const __half* Bp = (G1 ? g_fT : g_a3) + ((size_t)b*HW + n0)*KTOT;

    float2* sstat = (float2*)(smem + FIX);          // G1
    float*  sws   = (float*)(smem + FIX + 1024);    // G1
    float*  sg    = (float*)(smem + FIX);           // G4
    float*  ps    = (float*)(smem + FIX + 1024);    // G4
    float*  pss   = (float*)(smem + FIX + 2048);    // G4
    float2* mrs   = (float2*)(smem + FIX + 3072);   // G4

    if (G1) {
        if (tid < 128) sstat[tid] = ((const float2*)g_stat1)[(size_t)b*HW + n0 + tid];
        else           sws[tid-128] = g_ws[m0 + tid - 128];
    } else {
        sg[tid] = gout[tid];
    }

    auto load_stage = [&](int kc, int s) {
        #pragma unroll
        for (int i = 0; i < TM*8/256; i++) {          // A hi+lo
            int e = tid + (i << 8);
            int arr = e >= TM*4;
            int rq = arr ? e - TM*4 : e;
            int r = rq >> 2, q = rq & 3;
            const __half* gp = (arr ? Al : Ah) + (size_t)r*KTOT + kc*32 + q*8;
            cp16(sb + s*STAGE + arr*A_ARR + (r*SPAD + q*8)*2, gp);
        }
        #pragma unroll
        for (int i = 0; i < TN*4/256; i++) {          // B single
            int e = tid + (i << 8);
            int r = e >> 2, q = e & 3;
            const __half* gp = Bp + (size_t)r*KTOT + kc*32 + q*8;
            cp16(sb + s*STAGE + 2*A_ARR + (r*SPAD + q*8)*2, gp);
        }
    };

    float acc[4][4][4] = {};
    int lrow = (lane & 7) + (((lane >> 3) & 1) << 3);
    int lcol = (lane >> 4) << 3;

    auto compute_stage = [&](int s) {
        uint32_t sbase = sb + s*STAGE;
        #pragma unroll
        for (int ks = 0; ks < 2; ks++) {
            int kof = ks*16 + lcol;
            uint32_t bf[2][4];
            #pragma unroll
            for (int bt = 0; bt < 2; bt++) {
                int row = wn*32 + bt*16 + lrow;
                ldmx4(bf[bt], sbase + 2*A_ARR + (row*SPAD + kof)*2);
            }
            #pragma unroll
            for (int mt = 0; mt < 4; mt++) {
                uint32_t afh[4], afl[4];
                int row = wm*64 + mt*16 + lrow;
                ldmx4(afh, sbase + (row*SPAD + kof)*2);
                ldmx4(afl, sbase + A_ARR + (row*SPAD + kof)*2);
                #pragma unroll
                for (int nt = 0; nt < 4; nt++) {
                    int bt = nt >> 1, od = nt & 1;
                    mma_f16(acc[mt][nt], afh, bf[bt][od], bf[bt][od+2]);
                    mma_f16(acc[mt][nt], afl, bf[bt][od], bf[bt][od+2]);
                }
            }
        }
    };

    if (G1) {
        // 3-stage, one barrier per chunk
        load_stage(0, 0); CP_COMMIT();
        load_stage(1, 1); CP_COMMIT();
        int sl = 2, sc = 0;
        for (int kc = 0; kc < KC; kc++) {
            if (kc + 1 < KC) { CP_WAIT1(); } else { CP_WAIT0(); }
            __syncthreads();
            if (kc + 2 < KC) {
                load_stage(kc+2, sl); CP_COMMIT();
                if (++sl == 3) sl = 0;
            }
            compute_stage(sc);
            if (++sc == 3) sc = 0;
        }
        __syncthreads();
    } else {
        // 2-stage (smem limit), two barriers per chunk
        load_stage(0, 0); CP_COMMIT();
        for (int kc = 0; kc < KC; kc++) {
            if (kc + 1 < KC) load_stage(kc+1, (kc+1) & 1);
            CP_COMMIT();
            CP_WAIT1();
            __syncthreads();
            compute_stage(kc & 1);
            __syncthreads();
        }
    }

    if (G1) {
        float* buf = (float*)smem;   // 128 x 128, pitch 130
        #pragma unroll
        for (int mt = 0; mt < 4; mt++) {
            int rml = wm*64 + mt*16 + (lane >> 2);
            #pragma unroll
            for (int nt = 0; nt < 4; nt++) {
                int cl = wn*32 + nt*8 + 2*(lane & 3);
                float* d = acc[mt][nt];
                float2 s0 = sstat[cl], s1 = sstat[cl+1];
                float w0 = sws[rml], w1 = sws[rml+8];
                buf[rml*130 + cl]       = s0.y*(d[0] - s0.x*w0);
                buf[rml*130 + cl + 1]   = s1.y*(d[1] - s1.x*w0);
                buf[(rml+8)*130 + cl]     = s0.y*(d[2] - s0.x*w1);
                buf[(rml+8)*130 + cl + 1] = s1.y*(d[3] - s1.x*w1);
            }
        }
        __syncthreads();
        int region = blockIdx.y >> 2;
        if (region == 0) {
            // q: softmax over d + spatial-transpose store to g_qs (fp16)
            int col = tid & 127, g = tid >> 7;
            int p = n0 + col, h2 = p >> 6, wi = p & 63;
            int bh = b*8 + blockIdx.y*2 + g;
            float mx = -1e30f;
            #pragma unroll 8
            for (int d = 0; d < 64; d++) mx = fmaxf(mx, buf[(g*64+d)*130 + col]);
            float sum = 0.f;
            #pragma unroll 8
            for (int d = 0; d < 64; d++) {
                float e = __expf(buf[(g*64+d)*130 + col] - mx);
                buf[(g*64+d)*130 + col] = e;
                sum += e;
            }
            float r = QSCALE / sum;
            uint4* dst = (uint4*)&g_qs[((size_t)bh*HW + wi*64 + h2)*DH];
            #pragma unroll
            for (int d8 = 0; d8 < 8; d8++) {
                __half2 h0 = __floats2half2_rn(buf[(g*64+d8*8+0)*130+col]*r, buf[(g*64+d8*8+1)*130+col]*r);
                __half2 h1 = __floats2half2_rn(buf[(g*64+d8*8+2)*130+col]*r, buf[(g*64+d8*8+3)*130+col]*r);
                __half2 h2v= __floats2half2_rn(buf[(g*64+d8*8+4)*130+col]*r, buf[(g*64+d8*8+5)*130+col]*r);
                __half2 h3 = __floats2half2_rn(buf[(g*64+d8*8+6)*130+col]*r, buf[(g*64+d8*8+7)*130+col]*r);
                uint4 u;
                u.x = *(uint32_t*)&h0; u.y = *(uint32_t*)&h1;
                u.z = *(uint32_t*)&h2v; u.w = *(uint32_t*)&h3;
                dst[d8] = u;
            }
        } else {
            // k / v: store tile to g_kv as fp16 (half2 vectorized)
            __half2* kvb = (__half2*)(g_kv + ((size_t)(b*1024 + (m0 - 512)))*HW + n0);
            #pragma unroll 8
            for (int i = 0; i < 32; i++) {
                int idx = tid + (i << 8);           // 8192 half2 elements
                int row = idx >> 6, c2 = idx & 63;
                kvb[(size_t)row*(HW/2) + c2] =
                    __floats2half2_rn(buf[row*130 + 2*c2], buf[row*130 + 2*c2 + 1]);
            }
            if (region == 1) {
                // k: per-row online-softmax partial over this tile's 128 pixels (fp32)
                int row = tid >> 1, half = tid & 1;
                float m = -1e30f;
                #pragma unroll 8
                for (int c = half*64; c < half*64 + 64; c++) m = fmaxf(m, buf[row*130 + c]);
                float s = 0.f;
                #pragma unroll 8
                for (int c = half*64; c < half*64 + 64; c++) s += __expf(buf[row*130 + c] - m);
                float om = __shfl_xor_sync(0xffffffffu, m, 1);
                float os = __shfl_xor_sync(0xffffffffu, s, 1);
                float M = fmaxf(m, om);
                float S = s*__expf(m - M) + os*__expf(om - M);
                if (half == 0) {
                    int ch = (blockIdx.y - 4)*128 + row;
                    int r = (b*8 + (ch >> 6))*64 + (ch & 63);
                    g_kpm[blockIdx.x*(BHN*DH) + r] = M;
                    g_kps[blockIdx.x*(BHN*DH) + r] = S;
                }
            } else {
                // v: per-pixel inverse norm over 64 rows (fp32)
                int col = tid & 127, g = tid >> 7;
                float ss = 0.f;
                #pragma unroll 8
                for (int d = 0; d < 64; d++) {
                    float v = buf[(g*64+d)*130 + col];
                    ss = fmaf(v, v, ss);
                }
                int bh = b*8 + (blockIdx.y - 8)*2 + g;
                g_invn[(size_t)bh*HW + n0 + col] = 1.f / fmaxf(sqrtf(ss), 1e-12f);
            }
        }
    } else {
        // G4 epilogue: unscale a3 factor, then full output LN over 256 channels
        float* buf = (float*)smem;   // 256 x 64, pitch 68
        float* Cb = Cext + ((size_t)(b*CCH + m0))*HW + n0;
        #pragma unroll
        for (int mt = 0; mt < 4; mt++) {
            int rml = wm*64 + mt*16 + (lane >> 2);
            #pragma unroll
            for (int nt = 0; nt < 4; nt++) {
                int cl = wn*32 + nt*8 + 2*(lane & 3);
                float* d = acc[mt][nt];
                buf[rml*68 + cl]     = d[0] * A3UNSCALE;
                buf[rml*68 + cl + 1] = d[1] * A3UNSCALE;
                buf[(rml+8)*68 + cl]     = d[2] * A3UNSCALE;
                buf[(rml+8)*68 + cl + 1] = d[3] * A3UNSCALE;
            }
        }
        __syncthreads();
        {
            int col = tid & 63, part = tid >> 6;
            float s = 0.f, ss = 0.f;
            #pragma unroll 8
            for (int r = part*64; r < part*64 + 64; r++) {
                float v = buf[r*68 + col];
                s += v; ss = fmaf(v, v, ss);
            }
            ps[part*64 + col] = s;
            pss[part*64 + col] = ss;
        }
        __syncthreads();
        if (tid < 64) {
            float s  = ps[tid] + ps[64+tid] + ps[128+tid] + ps[192+tid];
            float ss = pss[tid] + pss[64+tid] + pss[128+tid] + pss[192+tid];
            float mu = s * (1.f/CCH);
            float var = fmaf(-mu, mu, ss * (1.f/CCH));
            mrs[tid] = make_float2(mu, rsqrtf(var + LNEPS));
        }
        __syncthreads();
        #pragma unroll 8
        for (int i = 0; i < 64; i++) {
            int idx = tid + (i << 8);
            int row = idx >> 6, col = idx & 63;
            float2 st = mrs[col];
            Cb[(size_t)row*HW + col] = (buf[row*68 + col] - st.x) * st.y * sg[row];
        }
    }
}

// ==================== merge k-softmax partials over 32 tiles ====================
__global__ void __launch_bounds__(256) kmerge() {
    int r = blockIdx.x*8 + (threadIdx.x >> 5);
    int lane = threadIdx.x & 31;
    float m = g_kpm[lane*(BHN*DH) + r];
    float s = g_kps[lane*(BHN*DH) + r];
    float M = m;
    #pragma unroll
    for (int o = 16; o > 0; o >>= 1) M = fmaxf(M, __shfl_xor_sync(0xffffffffu, M, o));
    float sc = s * __expf(m - M);
    #pragma unroll
    for (int o = 16; o > 0; o >>= 1) sc += __shfl_xor_sync(0xffffffffu, sc, o);
    if (lane == 0) { g_kmax[r] = M; g_ksum[r] = sc; }
}

// ==================== context partials (k/v fp16 in, fp32 accum) ====================
__global__ void __launch_bounds__(256) gemm2() {
    int sp = blockIdx.x, bh = blockIdx.y;
    int b = bh >> 3, head = bh & 7;
    const __half* kbase = g_kv + ((size_t)(b*1024 + head*DH))*HW;
    const __half* vbase = g_kv + ((size_t)(b*1024 + 512 + head*DH))*HW;
    __shared__ float Ks[64][36];
    __shared__ float Vs[64][36];
    __shared__ float smx[64], srs[64];
    __shared__ float sinv[512];
    int tid = threadIdx.x;
    if (tid < 64) { smx[tid] = g_kmax[bh*64 + tid]; srs[tid] = 1.f / g_ksum[bh*64 + tid]; }
    int n0 = sp*512;
    for (int i = tid; i < 512; i += 256) sinv[i] = g_invn[(size_t)bh*HW + n0 + i] * INV_N;
    __syncthreads();
    int tx = tid & 15, ty = tid >> 4;
    float acc[4][4] = {};
    for (int nt = 0; nt < 16; nt++) {
        int nb = n0 + nt*32;
        #pragma unroll
        for (int i = 0; i < 2; i++) {
            int idx = tid + (i<<8);
            int r = idx >> 3, cg = (idx & 7) << 2;
            uint2 kraw = *(const uint2*)&kbase[(size_t)r*HW + nb + cg];
            float2 k01 = __half22float2(*(__half2*)&kraw.x);
            float2 k23 = __half22float2(*(__half2*)&kraw.y);
            float m = smx[r], rs = srs[r];
            Ks[r][cg+0] = __expf(k01.x-m)*rs;
            Ks[r][cg+1] = __expf(k01.y-m)*rs;
            Ks[r][cg+2] = __expf(k23.x-m)*rs;
            Ks[r][cg+3] = __expf(k23.y-m)*rs;
            uint2 vraw = *(const uint2*)&vbase[(size_t)r*HW + nb + cg];
            float2 v01 = __half22float2(*(__half2*)&vraw.x);
            float2 v23 = __half22float2(*(__half2*)&vraw.y);
            int ln = nt*32 + cg;
            Vs[r][cg+0] = v01.x*sinv[ln+0];
            Vs[r][cg+1] = v01.y*sinv[ln+1];
            Vs[r][cg+2] = v23.x*sinv[ln+2];
            Vs[r][cg+3] = v23.y*sinv[ln+3];
        }
        __syncthreads();
        #pragma unroll
        for (int nn = 0; nn < 32; nn += 4) {
            float4 av[4], bv[4];
            #pragma unroll
            for (int i = 0; i < 4; i++) av[i] = *(float4*)&Ks[(ty<<2)+i][nn];
            #pragma unroll
            for (int j = 0; j < 4; j++) bv[j] = *(float4*)&Vs[(tx<<2)+j][nn];
            #pragma unroll
            for (int i = 0; i < 4; i++)
                #pragma unroll
                for (int j = 0; j < 4; j++)
                    acc[i][j] += av[i].x*bv[j].x + av[i].y*bv[j].y
                               + av[i].z*bv[j].z + av[i].w*bv[j].w;
        }
        __syncthreads();
    }
    float* cp = g_ctxp + ((size_t)(sp*BHN + bh))*4096;
    #pragma unroll
    for (int i = 0; i < 4; i++) {
        float4 o = make_float4(acc[i][0], acc[i][1], acc[i][2], acc[i][3]);
        *(float4*)&cp[((ty<<2)+i)*64 + (tx<<2)] = o;
    }
}

__global__ void __launch_bounds__(256) ctxred() {
    int bh = blockIdx.x, tid = threadIdx.x;
    for (int i = tid; i < 4096; i += 256) {
        float s = 0.f;
        #pragma unroll
        for (int sp = 0; sp < 8; sp++) s += g_ctxp[((size_t)(sp*BHN + bh))*4096 + i];
        g_ctx[(size_t)bh*4096 + i] = s;
    }
}

// ==================== out = qs @ ctx -> a3 fp16 (x 2^18) [b][p][he] ====================
__global__ void __launch_bounds__(256) gemm3() {
    __shared__ float Cs[64][64];
    __shared__ float Qs[64][65];
    int p2t = blockIdx.x, bh = blockIdx.y;
    int b = bh >> 3, head = bh & 7;
    int tid = threadIdx.x;
    const float* ctx = g_ctx + (size_t)bh*4096;
    for (int i = tid; i < 4096; i += 256) Cs[i>>6][i&63] = ctx[i];
    const uint2* qb = (const uint2*)(g_qs + ((size_t)bh*HW + p2t*64)*DH);
    #pragma unroll
    for (int i = 0; i < 4; i++) {
        int idx = tid + (i<<8);             // 1024 groups of 4 halfs
        uint2 raw = qb[idx];
        float2 a = __half22float2(*(__half2*)&raw.x);
        float2 c = __half22float2(*(__half2*)&raw.y);
        int lin = idx << 2;
        int row = lin >> 6, col = lin & 63;
        Qs[row][col]   = a.x; Qs[row][col+1] = a.y;
        Qs[row][col+2] = c.x; Qs[row][col+3] = c.y;
    }
    __syncthreads();
    int tx = tid & 15, ty = tid >> 4;
    float acc[4][4] = {};
    #pragma unroll
    for (int d = 0; d < 64; d++) {
        float a0 = Qs[(ty<<2)+0][d], a1 = Qs[(ty<<2)+1][d];
        float a2 = Qs[(ty<<2)+2][d], a3 = Qs[(ty<<2)+3][d];
        float4 bv = *(float4*)&Cs[d][tx<<2];
        acc[0][0]+=a0*bv.x; acc[0][1]+=a0*bv.y; acc[0][2]+=a0*bv.z; acc[0][3]+=a0*bv.w;
        acc[1][0]+=a1*bv.x; acc[1][1]+=a1*bv.y; acc[1][2]+=a1*bv.z; acc[1][3]+=a1*bv.w;
        acc[2][0]+=a2*bv.x; acc[2][1]+=a2*bv.y; acc[2][2]+=a2*bv.z; acc[2][3]+=a2*bv.w;
        acc[3][0]+=a3*bv.x; acc[3][1]+=a3*bv.y; acc[3][2]+=a3*bv.z; acc[3][3]+=a3*bv.w;
    }
    __syncthreads();
    #pragma unroll
    for (int i = 0; i < 4; i++)
        #pragma unroll
        for (int j = 0; j < 4; j++)
            Qs[(ty<<2)+i][(tx<<2)+j] = acc[i][j];   // [p2l][e]
    __syncthreads();
    size_t rowbase = (size_t)b*HW + p2t*64;
    #pragma unroll
    for (int i = 0; i < 16; i++) {
        int idx = tid + (i<<8); int pl = idx >> 6, e = idx & 63;
        g_a3[(rowbase + pl)*HID + head*DH + e] = __float2half_rn(Qs[pl][e] * A3SCALE);
    }
}

// ==================== launch ====================
#define SMEM_G1 93696    /* 3*30720 = 92160 (> 128*130*4=66560) + 1536 */
#define SMEM_G4 95744    /* 2*46080 = 92160 (> 256*68*4=69632)  + 3584 */

extern "C" void kernel_launch(void* const* d_in, const int* in_sizes, int n_in,
                              void* d_out, int out_size) {
    const float* feat = (const float*)d_in[0];
    const float* gin  = (const float*)d_in[1];
    const float* wqkv = (const float*)d_in[2];
    const float* wout = (const float*)d_in[3];
    const float* gout = (const float*)d_in[4];
    float* out = (float*)d_out;

    cudaFuncSetAttribute(gemm_p<128,128,256,true>,
                         cudaFuncAttributeMaxDynamicSharedMemorySize, SMEM_G1);
    cudaFuncSetAttribute(gemm_p<256,64,512,false>,
                         cudaFuncAttributeMaxDynamicSharedMemorySize, SMEM_G4);

    prep_w1b<<<OQKV, 256>>>(wqkv, gin);
    prep_w2b<<<CCH, 256>>>(wout);
    conv_feat<<<dim3(HW/64, BATCH), 256>>>(feat);
    gemm_p<128,128,256,true><<<dim3(HW/128, OQKV/128, BATCH), 256, SMEM_G1>>>(nullptr, nullptr);
    kmerge<<<BHN*DH/8, 256>>>();
    gemm2<<<dim3(8, BHN), 256>>>();
    ctxred<<<BHN, 256>>>();
    gemm3<<<dim3(HW/64, BHN), 256>>>();
    gemm_p<256,64,512,false><<<dim3(HW/64, 1, BATCH), 256, SMEM_G4>>>(out, gout);
}

// round 10
// speedup vs baseline: 2.5444x; 1.2532x over previous
#include <cuda_runtime.h>
#include <cuda_fp16.h>
#include <math.h>
#include <stdint.h>

#define BATCH 16
#define CCH   256
#define HW    4096
#define HEADS 8
#define DH    64
#define HID   512
#define OQKV  1536
#define BHN   (BATCH*HEADS)   /* 128 */
#define QSCALE 0.125f
#define LNEPS  1e-5f
#define INV_N  (1.0f/4096.0f)
#define SPAD  40   /* smem row pitch in fp16: 80B -> 8 ldmatrix rows hit distinct banks */
#define A3SCALE    262144.0f          /* 2^18: lifts a3 (~4e-6) into fp16 normal range */
#define A3UNSCALE  (1.0f/262144.0f)

// ==================== scratch (device globals; no allocations) ====================
__device__ __align__(256) float g_stat1[BATCH*HW*2];            // (mu, rstd) input LN
__device__ __align__(256) float g_ws[OQKV];                     // row sums of fp16 w_eff
__device__ __align__(256) __half g_w1[OQKV*CCH];                // (w_qkv*g) fp16 [o][c] K-major
__device__ __align__(256) __half g_w2[CCH*HID];                 // w_out fp16 [o][he] K-major
__device__ __align__(256) __half g_fT[(size_t)BATCH*HW*CCH];    // feature^T fp16 [b][p][c]
__device__ __align__(256) __half g_kv[(size_t)BATCH*1024*HW];   // k (ch 0-511), v (512-1023) fp16
__device__ __align__(256) __half g_qs[(size_t)BHN*HW*DH];       // softmaxed q fp16 [bh][p2][d]
__device__ __align__(256) float g_kpm[32*BHN*DH];               // per-tile partial max
__device__ __align__(256) float g_kps[32*BHN*DH];               // per-tile partial sumexp
__device__ __align__(256) float g_kmax[BHN*DH];
__device__ __align__(256) float g_ksum[BHN*DH];
__device__ __align__(256) float g_invn[BHN*HW];
__device__ __align__(256) float g_ctxp[8*BHN*DH*DH];
__device__ __align__(256) float g_ctx[BHN*DH*DH];
__device__ __align__(256) __half g_a3[(size_t)BATCH*HW*HID];    // [b][p][he] fp16 (x 2^18)

// ==================== helpers (sm_80+ PTX, valid on sm_100) ====================
__device__ __forceinline__ uint32_t smem_u32(const void* p) {
    uint32_t a;
    asm("{ .reg .u64 t; cvta.to.shared.u64 t, %1; cvt.u32.u64 %0, t; }" : "=r"(a) : "l"(p));
    return a;
}
__device__ __forceinline__ void ldmx4(uint32_t* r, uint32_t a) {
    asm volatile("ldmatrix.sync.aligned.m8n8.x4.shared.b16 {%0,%1,%2,%3}, [%4];"
        : "=r"(r[0]), "=r"(r[1]), "=r"(r[2]), "=r"(r[3]) : "r"(a));
}
__device__ __forceinline__ void mma_f16(float* d, const uint32_t* a, uint32_t b0, uint32_t b1) {
    asm volatile("mma.sync.aligned.m16n8k16.row.col.f32.f16.f16.f32 "
        "{%0,%1,%2,%3}, {%4,%5,%6,%7}, {%8,%9}, {%0,%1,%2,%3};"
        : "+f"(d[0]), "+f"(d[1]), "+f"(d[2]), "+f"(d[3])
        : "r"(a[0]), "r"(a[1]), "r"(a[2]), "r"(a[3]), "r"(b0), "r"(b1));
}
__device__ __forceinline__ void cp16(uint32_t s, const void* g) {
    asm volatile("cp.async.cg.shared.global [%0], [%1], 16;" :: "r"(s), "l"(g) : "memory");
}
#define CP_COMMIT() asm volatile("cp.async.commit_group;" ::: "memory")
#define CP_WAIT1()  asm volatile("cp.async.wait_group 1;" ::: "memory")
#define CP_WAIT0()  asm volatile("cp.async.wait_group 0;" ::: "memory")

// ==================== weight prep (single fp16) ====================
__global__ void __launch_bounds__(256) prep_w1b(const float* __restrict__ wqkv,
                                                const float* __restrict__ gin) {
    int o = blockIdx.x, c = threadIdx.x;
    float w = wqkv[o*CCH + c] * gin[c];
    __half h = __float2half_rn(w);
    g_w1[o*CCH + c] = h;
    float we = __half2float(h);
    __shared__ float red[256];
    red[c] = we; __syncthreads();
    for (int s = 128; s > 0; s >>= 1) { if (c < s) red[c] += red[c+s]; __syncthreads(); }
    if (c == 0) g_ws[o] = red[0];
}

__global__ void __launch_bounds__(256) prep_w2b(const float* __restrict__ wout) {
    int o = blockIdx.x;
    for (int t = threadIdx.x; t < HID; t += 256)
        g_w2[o*HID + t] = __float2half_rn(wout[o*HID + t]);
}

// ==================== feature transpose + fp16 + LN stats (fused) ====================
__global__ void __launch_bounds__(256) conv_feat(const float* __restrict__ feat) {
    __shared__ float S[128][65];
    __shared__ float s_s[256], s_ss[256];
    int p0 = blockIdx.x*64, b = blockIdx.y;
    int tid = threadIdx.x;
    float sum = 0.f, ssum = 0.f;
    for (int h = 0; h < 2; h++) {
        #pragma unroll
        for (int i = 0; i < 32; i++) {
            int idx = tid + (i<<8);
            int cl = idx >> 6, pl = idx & 63;
            float v = feat[((size_t)(b*CCH + h*128 + cl))*HW + p0 + pl];
            S[cl][pl] = v;
            sum += v; ssum = fmaf(v, v, ssum);
        }
        __syncthreads();
        #pragma unroll
        for (int i = 0; i < 32; i++) {
            int idx = tid + (i<<8);
            int pl = idx >> 7, cl = idx & 127;
            g_fT[((size_t)b*HW + p0 + pl)*CCH + h*128 + cl] = __float2half_rn(S[cl][pl]);
        }
        __syncthreads();
    }
    s_s[tid] = sum; s_ss[tid] = ssum;
    __syncthreads();
    if (tid < 64) {
        float s  = s_s[tid] + s_s[tid+64] + s_s[tid+128] + s_s[tid+192];
        float ss = s_ss[tid] + s_ss[tid+64] + s_ss[tid+128] + s_ss[tid+192];
        float mu = s * (1.f/CCH);
        float var = fmaf(-mu, mu, ss * (1.f/CCH));
        ((float2*)g_stat1)[(size_t)b*HW + p0 + tid] = make_float2(mu, rsqrtf(var + LNEPS));
    }
}

// ==================== pipelined warp-MMA GEMM (single fp16, 3-stage, 1 barrier/chunk) ====================
// G1=true : TM=128,TN=128,K=256. Epilogue by qkv region (q-softmax / k-partials / v-norm).
// G1=false: TM=256,TN=64, K=512. Epilogue = unscale 2^-18 + full output LN -> d_out.
template<int TM, int TN, int KTOT, bool G1>
__global__ void __launch_bounds__(256, 2) gemm_p(float* __restrict__ Cext,
                                                 const float* __restrict__ gout) {
    extern __shared__ char smem[];
    constexpr int WN     = TN/32;
    constexpr int A_ARR  = TM*SPAD*2;
    constexpr int B_ARR  = TN*SPAD*2;
    constexpr int STAGE  = A_ARR + B_ARR;
    constexpr int BUFB   = TM*(G1 ? (TN+2) : (TN+4))*4;
    constexpr int FIX    = (3*STAGE > BUFB) ? 3*STAGE : BUFB;
    constexpr int KC     = KTOT/32;

    int tid = threadIdx.x, wid = tid >> 5, lane = tid & 31;
    int b = blockIdx.z, m0 = blockIdx.y*TM, n0 = blockIdx.x*TN;
    int wm = wid / WN, wn = wid % WN;
    uint32_t sb = smem_u32(smem);

    const __half* Ap = (G1 ? g_w1 : g_w2) + (size_t)m0*KTOT;
    const __half* Bp = (G1 ? g_fT : g_a3) + ((size_t)b*HW + n0)*KTOT;

    float2* sstat = (float2*)(smem + FIX);          // G1
    float*  sws   = (float*)(smem + FIX + 1024);    // G1
    float*  sg    = (float*)(smem + FIX);           // G4
    float*  ps    = (float*)(smem + FIX + 1024);    // G4
    float*  pss   = (float*)(smem + FIX + 2048);    // G4
    float2* mrs   = (float2*)(smem + FIX + 3072);   // G4

    if (G1) {
        if (tid < 128) sstat[tid] = ((const float2*)g_stat1)[(size_t)b*HW + n0 + tid];
        else           sws[tid-128] = g_ws[m0 + tid - 128];
    } else {
        sg[tid] = gout[tid];
    }

    auto load_stage = [&](int kc, int s) {
        #pragma unroll
        for (int i = 0; i < TM*4/256; i++) {          // A single
            int e = tid + (i << 8);
            int r = e >> 2, q = e & 3;
            cp16(sb + s*STAGE + (r*SPAD + q*8)*2, Ap + (size_t)r*KTOT + kc*32 + q*8);
        }
        #pragma unroll
        for (int i = 0; i < TN*4/256; i++) {          // B single
            int e = tid + (i << 8);
            int r = e >> 2, q = e & 3;
            cp16(sb + s*STAGE + A_ARR + (r*SPAD + q*8)*2, Bp + (size_t)r*KTOT + kc*32 + q*8);
        }
    };

    float acc[4][4][4] = {};
    int lrow = (lane & 7) + (((lane >> 3) & 1) << 3);
    int lcol = (lane >> 4) << 3;

    auto compute_stage = [&](int s) {
        uint32_t sbase = sb + s*STAGE;
        #pragma unroll
        for (int ks = 0; ks < 2; ks++) {
            int kof = ks*16 + lcol;
            uint32_t bf[2][4];
            #pragma unroll
            for (int bt = 0; bt < 2; bt++) {
                int row = wn*32 + bt*16 + lrow;
                ldmx4(bf[bt], sbase + A_ARR + (row*SPAD + kof)*2);
            }
            #pragma unroll
            for (int mt = 0; mt < 4; mt++) {
                uint32_t af[4];
                int row = wm*64 + mt*16 + lrow;
                ldmx4(af, sbase + (row*SPAD + kof)*2);
                #pragma unroll
                for (int nt = 0; nt < 4; nt++) {
                    int bt = nt >> 1, od = nt & 1;
                    mma_f16(acc[mt][nt], af, bf[bt][od], bf[bt][od+2]);
                }
            }
        }
    };

    // 3-stage pipeline, one barrier per chunk
    load_stage(0, 0); CP_COMMIT();
    load_stage(1, 1); CP_COMMIT();
    int sl = 2, sc = 0;
    for (int kc = 0; kc < KC; kc++) {
        if (kc + 1 < KC) { CP_WAIT1(); } else { CP_WAIT0(); }
        __syncthreads();
        if (kc + 2 < KC) {
            load_stage(kc+2, sl); CP_COMMIT();
            if (++sl == 3) sl = 0;
        }
        compute_stage(sc);
        if (++sc == 3) sc = 0;
    }
    __syncthreads();

    if (G1) {
        float* buf = (float*)smem;   // 128 x 128, pitch 130
        #pragma unroll
        for (int mt = 0; mt < 4; mt++) {
            int rml = wm*64 + mt*16 + (lane >> 2);
            #pragma unroll
            for (int nt = 0; nt < 4; nt++) {
                int cl = wn*32 + nt*8 + 2*(lane & 3);
                float* d = acc[mt][nt];
                float2 s0 = sstat[cl], s1 = sstat[cl+1];
                float w0 = sws[rml], w1 = sws[rml+8];
                buf[rml*130 + cl]       = s0.y*(d[0] - s0.x*w0);
                buf[rml*130 + cl + 1]   = s1.y*(d[1] - s1.x*w0);
                buf[(rml+8)*130 + cl]     = s0.y*(d[2] - s0.x*w1);
                buf[(rml+8)*130 + cl + 1] = s1.y*(d[3] - s1.x*w1);
            }
        }
        __syncthreads();
        int region = blockIdx.y >> 2;
        if (region == 0) {
            // q: softmax over d + spatial-transpose store to g_qs (fp16)
            int col = tid & 127, g = tid >> 7;
            int p = n0 + col, h2 = p >> 6, wi = p & 63;
            int bh = b*8 + blockIdx.y*2 + g;
            float mx = -1e30f;
            #pragma unroll 8
            for (int d = 0; d < 64; d++) mx = fmaxf(mx, buf[(g*64+d)*130 + col]);
            float sum = 0.f;
            #pragma unroll 8
            for (int d = 0; d < 64; d++) {
                float e = __expf(buf[(g*64+d)*130 + col] - mx);
                buf[(g*64+d)*130 + col] = e;
                sum += e;
            }
            float r = QSCALE / sum;
            uint4* dst = (uint4*)&g_qs[((size_t)bh*HW + wi*64 + h2)*DH];
            #pragma unroll
            for (int d8 = 0; d8 < 8; d8++) {
                __half2 h0 = __floats2half2_rn(buf[(g*64+d8*8+0)*130+col]*r, buf[(g*64+d8*8+1)*130+col]*r);
                __half2 h1 = __floats2half2_rn(buf[(g*64+d8*8+2)*130+col]*r, buf[(g*64+d8*8+3)*130+col]*r);
                __half2 h2v= __floats2half2_rn(buf[(g*64+d8*8+4)*130+col]*r, buf[(g*64+d8*8+5)*130+col]*r);
                __half2 h3 = __floats2half2_rn(buf[(g*64+d8*8+6)*130+col]*r, buf[(g*64+d8*8+7)*130+col]*r);
                uint4 u;
                u.x = *(uint32_t*)&h0; u.y = *(uint32_t*)&h1;
                u.z = *(uint32_t*)&h2v; u.w = *(uint32_t*)&h3;
                dst[d8] = u;
            }
        } else {
            // k / v: store tile to g_kv as fp16 (half2 vectorized)
            __half2* kvb = (__half2*)(g_kv + ((size_t)(b*1024 + (m0 - 512)))*HW + n0);
            #pragma unroll 8
            for (int i = 0; i < 32; i++) {
                int idx = tid + (i << 8);           // 8192 half2 elements
                int row = idx >> 6, c2 = idx & 63;
                kvb[(size_t)row*(HW/2) + c2] =
                    __floats2half2_rn(buf[row*130 + 2*c2], buf[row*130 + 2*c2 + 1]);
            }
            if (region == 1) {
                // k: per-row online-softmax partial over this tile's 128 pixels (fp32)
                int row = tid >> 1, half = tid & 1;
                float m = -1e30f;
                #pragma unroll 8
                for (int c = half*64; c < half*64 + 64; c++) m = fmaxf(m, buf[row*130 + c]);
                float s = 0.f;
                #pragma unroll 8
                for (int c = half*64; c < half*64 + 64; c++) s += __expf(buf[row*130 + c] - m);
                float om = __shfl_xor_sync(0xffffffffu, m, 1);
                float os = __shfl_xor_sync(0xffffffffu, s, 1);
                float M = fmaxf(m, om);
                float S = s*__expf(m - M) + os*__expf(om - M);
                if (half == 0) {
                    int ch = (blockIdx.y - 4)*128 + row;
                    int r = (b*8 + (ch >> 6))*64 + (ch & 63);
                    g_kpm[blockIdx.x*(BHN*DH) + r] = M;
                    g_kps[blockIdx.x*(BHN*DH) + r] = S;
                }
            } else {
                // v: per-pixel inverse norm over 64 rows (fp32)
                int col = tid & 127, g = tid >> 7;
                float ss = 0.f;
                #pragma unroll 8
                for (int d = 0; d < 64; d++) {
                    float v = buf[(g*64+d)*130 + col];
                    ss = fmaf(v, v, ss);
                }
                int bh = b*8 + (blockIdx.y - 8)*2 + g;
                g_invn[(size_t)bh*HW + n0 + col] = 1.f / fmaxf(sqrtf(ss), 1e-12f);
            }
        }
    } else {
        // G4 epilogue: unscale a3 factor, then full output LN over 256 channels
        float* buf = (float*)smem;   // 256 x 64, pitch 68
        float* Cb = Cext + ((size_t)(b*CCH + m0))*HW + n0;
        #pragma unroll
        for (int mt = 0; mt < 4; mt++) {
            int rml = wm*64 + mt*16 + (lane >> 2);
            #pragma unroll
            for (int nt = 0; nt < 4; nt++) {
                int cl = wn*32 + nt*8 + 2*(lane & 3);
                float* d = acc[mt][nt];
                buf[rml*68 + cl]     = d[0] * A3UNSCALE;
                buf[rml*68 + cl + 1] = d[1] * A3UNSCALE;
                buf[(rml+8)*68 + cl]     = d[2] * A3UNSCALE;
                buf[(rml+8)*68 + cl + 1] = d[3] * A3UNSCALE;
            }
        }
        __syncthreads();
        {
            int col = tid & 63, part = tid >> 6;
            float s = 0.f, ss = 0.f;
            #pragma unroll 8
            for (int r = part*64; r < part*64 + 64; r++) {
                float v = buf[r*68 + col];
                s += v; ss = fmaf(v, v, ss);
            }
            ps[part*64 + col] = s;
            pss[part*64 + col] = ss;
        }
        __syncthreads();
        if (tid < 64) {
            float s  = ps[tid] + ps[64+tid] + ps[128+tid] + ps[192+tid];
            float ss = pss[tid] + pss[64+tid] + pss[128+tid] + pss[192+tid];
            float mu = s * (1.f/CCH);
            float var = fmaf(-mu, mu, ss * (1.f/CCH));
            mrs[tid] = make_float2(mu, rsqrtf(var + LNEPS));
        }
        __syncthreads();
        #pragma unroll 8
        for (int i = 0; i < 64; i++) {
            int idx = tid + (i << 8);
            int row = idx >> 6, col = idx & 63;
            float2 st = mrs[col];
            Cb[(size_t)row*HW + col] = (buf[row*68 + col] - st.x) * st.y * sg[row];
        }
    }
}

// ==================== merge k-softmax partials over 32 tiles ====================
__global__ void __launch_bounds__(256) kmerge() {
    int r = blockIdx.x*8 + (threadIdx.x >> 5);
    int lane = threadIdx.x & 31;
    float m = g_kpm[lane*(BHN*DH) + r];
    float s = g_kps[lane*(BHN*DH) + r];
    float M = m;
    #pragma unroll
    for (int o = 16; o > 0; o >>= 1) M = fmaxf(M, __shfl_xor_sync(0xffffffffu, M, o));
    float sc = s * __expf(m - M);
    #pragma unroll
    for (int o = 16; o > 0; o >>= 1) sc += __shfl_xor_sync(0xffffffffu, sc, o);
    if (lane == 0) { g_kmax[r] = M; g_ksum[r] = sc; }
}

// ==================== context partials (k/v fp16 in, fp32 accum) ====================
__global__ void __launch_bounds__(256) gemm2() {
    int sp = blockIdx.x, bh = blockIdx.y;
    int b = bh >> 3, head = bh & 7;
    const __half* kbase = g_kv + ((size_t)(b*1024 + head*DH))*HW;
    const __half* vbase = g_kv + ((size_t)(b*1024 + 512 + head*DH))*HW;
    __shared__ float Ks[64][36];
    __shared__ float Vs[64][36];
    __shared__ float smx[64], srs[64];
    __shared__ float sinv[512];
    int tid = threadIdx.x;
    if (tid < 64) { smx[tid] = g_kmax[bh*64 + tid]; srs[tid] = 1.f / g_ksum[bh*64 + tid]; }
    int n0 = sp*512;
    for (int i = tid; i < 512; i += 256) sinv[i] = g_invn[(size_t)bh*HW + n0 + i] * INV_N;
    __syncthreads();
    int tx = tid & 15, ty = tid >> 4;
    float acc[4][4] = {};
    for (int nt = 0; nt < 16; nt++) {
        int nb = n0 + nt*32;
        #pragma unroll
        for (int i = 0; i < 2; i++) {
            int idx = tid + (i<<8);
            int r = idx >> 3, cg = (idx & 7) << 2;
            uint2 kraw = *(const uint2*)&kbase[(size_t)r*HW + nb + cg];
            float2 k01 = __half22float2(*(__half2*)&kraw.x);
            float2 k23 = __half22float2(*(__half2*)&kraw.y);
            float m = smx[r], rs = srs[r];
            Ks[r][cg+0] = __expf(k01.x-m)*rs;
            Ks[r][cg+1] = __expf(k01.y-m)*rs;
            Ks[r][cg+2] = __expf(k23.x-m)*rs;
            Ks[r][cg+3] = __expf(k23.y-m)*rs;
            uint2 vraw = *(const uint2*)&vbase[(size_t)r*HW + nb + cg];
            float2 v01 = __half22float2(*(__half2*)&vraw.x);
            float2 v23 = __half22float2(*(__half2*)&vraw.y);
            int ln = nt*32 + cg;
            Vs[r][cg+0] = v01.x*sinv[ln+0];
            Vs[r][cg+1] = v01.y*sinv[ln+1];
            Vs[r][cg+2] = v23.x*sinv[ln+2];
            Vs[r][cg+3] = v23.y*sinv[ln+3];
        }
        __syncthreads();
        #pragma unroll
        for (int nn = 0; nn < 32; nn += 4) {
            float4 av[4], bv[4];
            #pragma unroll
            for (int i = 0; i < 4; i++) av[i] = *(float4*)&Ks[(ty<<2)+i][nn];
            #pragma unroll
            for (int j = 0; j < 4; j++) bv[j] = *(float4*)&Vs[(tx<<2)+j][nn];
            #pragma unroll
            for (int i = 0; i < 4; i++)
                #pragma unroll
                for (int j = 0; j < 4; j++)
                    acc[i][j] += av[i].x*bv[j].x + av[i].y*bv[j].y
                               + av[i].z*bv[j].z + av[i].w*bv[j].w;
        }
        __syncthreads();
    }
    float* cp = g_ctxp + ((size_t)(sp*BHN + bh))*4096;
    #pragma unroll
    for (int i = 0; i < 4; i++) {
        float4 o = make_float4(acc[i][0], acc[i][1], acc[i][2], acc[i][3]);
        *(float4*)&cp[((ty<<2)+i)*64 + (tx<<2)] = o;
    }
}

__global__ void __launch_bounds__(256) ctxred() {
    int bh = blockIdx.x, tid = threadIdx.x;
    for (int i = tid; i < 4096; i += 256) {
        float s = 0.f;
        #pragma unroll
        for (int sp = 0; sp < 8; sp++) s += g_ctxp[((size_t)(sp*BHN + bh))*4096 + i];
        g_ctx[(size_t)bh*4096 + i] = s;
    }
}

// ==================== out = qs @ ctx -> a3 fp16 (x 2^18) [b][p][he] ====================
__global__ void __launch_bounds__(256) gemm3() {
    __shared__ float Cs[64][64];
    __shared__ float Qs[64][65];
    int p2t = blockIdx.x, bh = blockIdx.y;
    int b = bh >> 3, head = bh & 7;
    int tid = threadIdx.x;
    const float* ctx = g_ctx + (size_t)bh*4096;
    for (int i = tid; i < 4096; i += 256) Cs[i>>6][i&63] = ctx[i];
    const uint2* qb = (const uint2*)(g_qs + ((size_t)bh*HW + p2t*64)*DH);
    #pragma unroll
    for (int i = 0; i < 4; i++) {
        int idx = tid + (i<<8);             // 1024 groups of 4 halfs
        uint2 raw = qb[idx];
        float2 a = __half22float2(*(__half2*)&raw.x);
        float2 c = __half22float2(*(__half2*)&raw.y);
        int lin = idx << 2;
        int row = lin >> 6, col = lin & 63;
        Qs[row][col]   = a.x; Qs[row][col+1] = a.y;
        Qs[row][col+2] = c.x; Qs[row][col+3] = c.y;
    }
    __syncthreads();
    int tx = tid & 15, ty = tid >> 4;
    float acc[4][4] = {};
    #pragma unroll
    for (int d = 0; d < 64; d++) {
        float a0 = Qs[(ty<<2)+0][d], a1 = Qs[(ty<<2)+1][d];
        float a2 = Qs[(ty<<2)+2][d], a3 = Qs[(ty<<2)+3][d];
        float4 bv = *(float4*)&Cs[d][tx<<2];
        acc[0][0]+=a0*bv.x; acc[0][1]+=a0*bv.y; acc[0][2]+=a0*bv.z; acc[0][3]+=a0*bv.w;
        acc[1][0]+=a1*bv.x; acc[1][1]+=a1*bv.y; acc[1][2]+=a1*bv.z; acc[1][3]+=a1*bv.w;
        acc[2][0]+=a2*bv.x; acc[2][1]+=a2*bv.y; acc[2][2]+=a2*bv.z; acc[2][3]+=a2*bv.w;
        acc[3][0]+=a3*bv.x; acc[3][1]+=a3*bv.y; acc[3][2]+=a3*bv.z; acc[3][3]+=a3*bv.w;
    }
    __syncthreads();
    #pragma unroll
    for (int i = 0; i < 4; i++)
        #pragma unroll
        for (int j = 0; j < 4; j++)
            Qs[(ty<<2)+i][(tx<<2)+j] = acc[i][j];   // [p2l][e]
    __syncthreads();
    size_t rowbase = (size_t)b*HW + p2t*64;
    #pragma unroll
    for (int i = 0; i < 16; i++) {
        int idx = tid + (i<<8); int pl = idx >> 6, e = idx & 63;
        g_a3[(rowbase + pl)*HID + head*DH + e] = __float2half_rn(Qs[pl][e] * A3SCALE);
    }
}

// ==================== launch ====================
#define SMEM_G1 68096    /* max(3*20480=61440, 128*130*4=66560) + 1536 */
#define SMEM_G4 80384    /* max(3*25600=76800, 256*68*4=69632)  + 3584 */

extern "C" void kernel_launch(void* const* d_in, const int* in_sizes, int n_in,
                              void* d_out, int out_size) {
    const float* feat = (const float*)d_in[0];
    const float* gin  = (const float*)d_in[1];
    const float* wqkv = (const float*)d_in[2];
    const float* wout = (const float*)d_in[3];
    const float* gout = (const float*)d_in[4];
    float* out = (float*)d_out;

    cudaFuncSetAttribute(gemm_p<128,128,256,true>,
                         cudaFuncAttributeMaxDynamicSharedMemorySize, SMEM_G1);
    cudaFuncSetAttribute(gemm_p<256,64,512,false>,
                         cudaFuncAttributeMaxDynamicSharedMemorySize, SMEM_G4);

    prep_w1b<<<OQKV, 256>>>(wqkv, gin);
    prep_w2b<<<CCH, 256>>>(wout);
    conv_feat<<<dim3(HW/64, BATCH), 256>>>(feat);
    gemm_p<128,128,256,true><<<dim3(HW/128, OQKV/128, BATCH), 256, SMEM_G1>>>(nullptr, nullptr);
    kmerge<<<BHN*DH/8, 256>>>();
    gemm2<<<dim3(8, BHN), 256>>>();
    ctxred<<<BHN, 256>>>();
    gemm3<<<dim3(HW/64, BHN), 256>>>();
    gemm_p<256,64,512,false><<<dim3(HW/64, 1, BATCH), 256, SMEM_G4>>>(out, gout);
}

// round 11
// speedup vs baseline: 3.5534x; 1.3966x over previous
#include <cuda_runtime.h>
#include <cuda_fp16.h>
#include <math.h>
#include <stdint.h>

#define BATCH 16
#define CCH   256
#define HW    4096
#define HEADS 8
#define DH    64
#define HID   512
#define OQKV  1536
#define BHN   (BATCH*HEADS)   /* 128 */
#define QSCALE 0.125f
#define LNEPS  1e-5f
#define INV_N  (1.0f/4096.0f)
#define SPAD  40   /* smem row pitch in fp16: 80B -> 8 ldmatrix rows hit distinct banks */
#define A3SCALE    262144.0f          /* 2^18: lifts a3 (~4e-6) into fp16 normal range */
#define A3UNSCALE  (1.0f/262144.0f)

// ==================== scratch (device globals; no allocations) ====================
__device__ __align__(256) float g_stat1[BATCH*HW*2];            // (mu, rstd) input LN
__device__ __align__(256) float g_ws[OQKV];                     // row sums of fp16 w_eff
__device__ __align__(256) __half g_w1[OQKV*CCH];                // (w_qkv*g) fp16 [o][c] K-major
__device__ __align__(256) __half g_w2[CCH*HID];                 // w_out fp16 [o][he] K-major
__device__ __align__(256) __half g_fT[(size_t)BATCH*HW*CCH];    // feature^T fp16 [b][p][c]
__device__ __align__(256) __half g_kv[(size_t)BATCH*1024*HW];   // k'=exp(k-Mtile) ch 0-511, v'=v*invn 512-1023
__device__ __align__(256) __half g_qs[(size_t)BHN*HW*DH];       // softmaxed q fp16 [bh][p2][d]
__device__ __align__(256) float g_kpm[32*BHN*DH];               // per-tile partial max
__device__ __align__(256) float g_kps[32*BHN*DH];               // per-tile partial sumexp
__device__ __align__(256) float g_kmax[BHN*DH];
__device__ __align__(256) float g_ksum[BHN*DH];
__device__ __align__(256) float g_ctxp[8*BHN*DH*DH];
__device__ __align__(256) float g_ctx[BHN*DH*DH];
__device__ __align__(256) __half g_a3[(size_t)BATCH*HW*HID];    // [b][p][he] fp16 (x 2^18)

// ==================== helpers (sm_80+ PTX, valid on sm_100) ====================
__device__ __forceinline__ uint32_t smem_u32(const void* p) {
    uint32_t a;
    asm("{ .reg .u64 t; cvta.to.shared.u64 t, %1; cvt.u32.u64 %0, t; }" : "=r"(a) : "l"(p));
    return a;
}
__device__ __forceinline__ void ldmx4(uint32_t* r, uint32_t a) {
    asm volatile("ldmatrix.sync.aligned.m8n8.x4.shared.b16 {%0,%1,%2,%3}, [%4];"
        : "=r"(r[0]), "=r"(r[1]), "=r"(r[2]), "=r"(r[3]) : "r"(a));
}
__device__ __forceinline__ void mma_f16(float* d, const uint32_t* a, uint32_t b0, uint32_t b1) {
    asm volatile("mma.sync.aligned.m16n8k16.row.col.f32.f16.f16.f32 "
        "{%0,%1,%2,%3}, {%4,%5,%6,%7}, {%8,%9}, {%0,%1,%2,%3};"
        : "+f"(d[0]), "+f"(d[1]), "+f"(d[2]), "+f"(d[3])
        : "r"(a[0]), "r"(a[1]), "r"(a[2]), "r"(a[3]), "r"(b0), "r"(b1));
}
__device__ __forceinline__ void cp16(uint32_t s, const void* g) {
    asm volatile("cp.async.cg.shared.global [%0], [%1], 16;" :: "r"(s), "l"(g) : "memory");
}
#define CP_COMMIT() asm volatile("cp.async.commit_group;" ::: "memory")
#define CP_WAIT1()  asm volatile("cp.async.wait_group 1;" ::: "memory")
#define CP_WAIT0()  asm volatile("cp.async.wait_group 0;" ::: "memory")

// ==================== weight prep (single fp16) ====================
__global__ void __launch_bounds__(256) prep_w1b(const float* __restrict__ wqkv,
                                                const float* __restrict__ gin) {
    int o = blockIdx.x, c = threadIdx.x;
    float w = wqkv[o*CCH + c] * gin[c];
    __half h = __float2half_rn(w);
    g_w1[o*CCH + c] = h;
    float we = __half2float(h);
    __shared__ float red[256];
    red[c] = we; __syncthreads();
    for (int s = 128; s > 0; s >>= 1) { if (c < s) red[c] += red[c+s]; __syncthreads(); }
    if (c == 0) g_ws[o] = red[0];
}

__global__ void __launch_bounds__(256) prep_w2b(const float* __restrict__ wout) {
    int o = blockIdx.x;
    for (int t = threadIdx.x; t < HID; t += 256)
        g_w2[o*HID + t] = __float2half_rn(wout[o*HID + t]);
}

// ==================== feature transpose + fp16 + LN stats (fused) ====================
__global__ void __launch_bounds__(256) conv_feat(const float* __restrict__ feat) {
    __shared__ float S[128][65];
    __shared__ float s_s[256], s_ss[256];
    int p0 = blockIdx.x*64, b = blockIdx.y;
    int tid = threadIdx.x;
    float sum = 0.f, ssum = 0.f;
    for (int h = 0; h < 2; h++) {
        #pragma unroll
        for (int i = 0; i < 32; i++) {
            int idx = tid + (i<<8);
            int cl = idx >> 6, pl = idx & 63;
            float v = feat[((size_t)(b*CCH + h*128 + cl))*HW + p0 + pl];
            S[cl][pl] = v;
            sum += v; ssum = fmaf(v, v, ssum);
        }
        __syncthreads();
        #pragma unroll
        for (int i = 0; i < 32; i++) {
            int idx = tid + (i<<8);
            int pl = idx >> 7, cl = idx & 127;
            g_fT[((size_t)b*HW + p0 + pl)*CCH + h*128 + cl] = __float2half_rn(S[cl][pl]);
        }
        __syncthreads();
    }
    s_s[tid] = sum; s_ss[tid] = ssum;
    __syncthreads();
    if (tid < 64) {
        float s  = s_s[tid] + s_s[tid+64] + s_s[tid+128] + s_s[tid+192];
        float ss = s_ss[tid] + s_ss[tid+64] + s_ss[tid+128] + s_ss[tid+192];
        float mu = s * (1.f/CCH);
        float var = fmaf(-mu, mu, ss * (1.f/CCH));
        ((float2*)g_stat1)[(size_t)b*HW + p0 + tid] = make_float2(mu, rsqrtf(var + LNEPS));
    }
}

// ==================== pipelined warp-MMA GEMM (single fp16, 3-stage, 1 barrier/chunk) ====================
// G1=true : TM=128,TN=128,K=256. Epilogue by qkv region:
//   q: softmax+transpose -> g_qs fp16
//   k: per-row tile max -> store exp(k-Mtile) fp16 + partials (g_kpm/g_kps)
//   v: per-pixel inv-norm -> store v*invn fp16
// G1=false: TM=256,TN=64, K=512. Epilogue = unscale 2^-18 + full output LN -> d_out.
template<int TM, int TN, int KTOT, bool G1>
__global__ void __launch_bounds__(256, 2) gemm_p(float* __restrict__ Cext,
                                                 const float* __restrict__ gout) {
    extern __shared__ char smem[];
    constexpr int WN     = TN/32;
    constexpr int A_ARR  = TM*SPAD*2;
    constexpr int B_ARR  = TN*SPAD*2;
    constexpr int STAGE  = A_ARR + B_ARR;
    constexpr int BUFB   = TM*(G1 ? (TN+2) : (TN+4))*4;
    constexpr int FIX    = (3*STAGE > BUFB) ? 3*STAGE : BUFB;
    constexpr int KC     = KTOT/32;

    int tid = threadIdx.x, wid = tid >> 5, lane = tid & 31;
    int b = blockIdx.z, m0 = blockIdx.y*TM, n0 = blockIdx.x*TN;
    int wm = wid / WN, wn = wid % WN;
    uint32_t sb = smem_u32(smem);

    const __half* Ap = (G1 ? g_w1 : g_w2) + (size_t)m0*KTOT;
    const __half* Bp = (G1 ? g_fT : g_a3) + ((size_t)b*HW + n0)*KTOT;

    float2* sstat = (float2*)(smem + FIX);          // G1
    float*  sws   = (float*)(smem + FIX + 1024);    // G1
    float*  sg    = (float*)(smem + FIX);           // G4
    float*  ps    = (float*)(smem + FIX + 1024);    // G4
    float*  pss   = (float*)(smem + FIX + 2048);    // G4
    float2* mrs   = (float2*)(smem + FIX + 3072);   // G4

    if (G1) {
        if (tid < 128) sstat[tid] = ((const float2*)g_stat1)[(size_t)b*HW + n0 + tid];
        else           sws[tid-128] = g_ws[m0 + tid - 128];
    } else {
        sg[tid] = gout[tid];
    }

    auto load_stage = [&](int kc, int s) {
        #pragma unroll
        for (int i = 0; i < TM*4/256; i++) {          // A single
            int e = tid + (i << 8);
            int r = e >> 2, q = e & 3;
            cp16(sb + s*STAGE + (r*SPAD + q*8)*2, Ap + (size_t)r*KTOT + kc*32 + q*8);
        }
        #pragma unroll
        for (int i = 0; i < TN*4/256; i++) {          // B single
            int e = tid + (i << 8);
            int r = e >> 2, q = e & 3;
            cp16(sb + s*STAGE + A_ARR + (r*SPAD + q*8)*2, Bp + (size_t)r*KTOT + kc*32 + q*8);
        }
    };

    float acc[4][4][4] = {};
    int lrow = (lane & 7) + (((lane >> 3) & 1) << 3);
    int lcol = (lane >> 4) << 3;

    auto compute_stage = [&](int s) {
        uint32_t sbase = sb + s*STAGE;
        #pragma unroll
        for (int ks = 0; ks < 2; ks++) {
            int kof = ks*16 + lcol;
            uint32_t bf[2][4];
            #pragma unroll
            for (int bt = 0; bt < 2; bt++) {
                int row = wn*32 + bt*16 + lrow;
                ldmx4(bf[bt], sbase + A_ARR + (row*SPAD + kof)*2);
            }
            #pragma unroll
            for (int mt = 0; mt < 4; mt++) {
                uint32_t af[4];
                int row = wm*64 + mt*16 + lrow;
                ldmx4(af, sbase + (row*SPAD + kof)*2);
                #pragma unroll
                for (int nt = 0; nt < 4; nt++) {
                    int bt = nt >> 1, od = nt & 1;
                    mma_f16(acc[mt][nt], af, bf[bt][od], bf[bt][od+2]);
                }
            }
        }
    };

    // 3-stage pipeline, one barrier per chunk
    load_stage(0, 0); CP_COMMIT();
    load_stage(1, 1); CP_COMMIT();
    int sl = 2, sc = 0;
    for (int kc = 0; kc < KC; kc++) {
        if (kc + 1 < KC) { CP_WAIT1(); } else { CP_WAIT0(); }
        __syncthreads();
        if (kc + 2 < KC) {
            load_stage(kc+2, sl); CP_COMMIT();
            if (++sl == 3) sl = 0;
        }
        compute_stage(sc);
        if (++sc == 3) sc = 0;
    }
    __syncthreads();

    if (G1) {
        float* buf = (float*)smem;   // 128 x 128, pitch 130
        #pragma unroll
        for (int mt = 0; mt < 4; mt++) {
            int rml = wm*64 + mt*16 + (lane >> 2);
            #pragma unroll
            for (int nt = 0; nt < 4; nt++) {
                int cl = wn*32 + nt*8 + 2*(lane & 3);
                float* d = acc[mt][nt];
                float2 s0 = sstat[cl], s1 = sstat[cl+1];
                float w0 = sws[rml], w1 = sws[rml+8];
                buf[rml*130 + cl]       = s0.y*(d[0] - s0.x*w0);
                buf[rml*130 + cl + 1]   = s1.y*(d[1] - s1.x*w0);
                buf[(rml+8)*130 + cl]     = s0.y*(d[2] - s0.x*w1);
                buf[(rml+8)*130 + cl + 1] = s1.y*(d[3] - s1.x*w1);
            }
        }
        __syncthreads();
        int region = blockIdx.y >> 2;
        if (region == 0) {
            // q: softmax over d + spatial-transpose store to g_qs (fp16)
            int col = tid & 127, g = tid >> 7;
            int p = n0 + col, h2 = p >> 6, wi = p & 63;
            int bh = b*8 + blockIdx.y*2 + g;
            float mx = -1e30f;
            #pragma unroll 8
            for (int d = 0; d < 64; d++) mx = fmaxf(mx, buf[(g*64+d)*130 + col]);
            float sum = 0.f;
            #pragma unroll 8
            for (int d = 0; d < 64; d++) {
                float e = __expf(buf[(g*64+d)*130 + col] - mx);
                buf[(g*64+d)*130 + col] = e;
                sum += e;
            }
            float r = QSCALE / sum;
            uint4* dst = (uint4*)&g_qs[((size_t)bh*HW + wi*64 + h2)*DH];
            #pragma unroll
            for (int d8 = 0; d8 < 8; d8++) {
                __half2 h0 = __floats2half2_rn(buf[(g*64+d8*8+0)*130+col]*r, buf[(g*64+d8*8+1)*130+col]*r);
                __half2 h1 = __floats2half2_rn(buf[(g*64+d8*8+2)*130+col]*r, buf[(g*64+d8*8+3)*130+col]*r);
                __half2 h2v= __floats2half2_rn(buf[(g*64+d8*8+4)*130+col]*r, buf[(g*64+d8*8+5)*130+col]*r);
                __half2 h3 = __floats2half2_rn(buf[(g*64+d8*8+6)*130+col]*r, buf[(g*64+d8*8+7)*130+col]*r);
                uint4 u;
                u.x = *(uint32_t*)&h0; u.y = *(uint32_t*)&h1;
                u.z = *(uint32_t*)&h2v; u.w = *(uint32_t*)&h3;
                dst[d8] = u;
            }
        } else if (region == 1) {
            // k: per-row tile max, then store exp(k - Mtile) fp16 + online partials
            int row = tid >> 1, half = tid & 1;
            float m = -1e30f;
            #pragma unroll 8
            for (int c = half*64; c < half*64 + 64; c++) m = fmaxf(m, buf[row*130 + c]);
            float om = __shfl_xor_sync(0xffffffffu, m, 1);
            float M = fmaxf(m, om);
            __half2* kvb = (__half2*)(g_kv + ((size_t)(b*1024 + (m0 - 512)))*HW + n0);
            float s = 0.f;
            #pragma unroll 8
            for (int c2 = 0; c2 < 32; c2++) {
                int c = half*64 + 2*c2;
                float e0 = __expf(buf[row*130 + c]     - M);
                float e1 = __expf(buf[row*130 + c + 1] - M);
                s += e0 + e1;
                kvb[(size_t)row*(HW/2) + half*32 + c2] = __floats2half2_rn(e0, e1);
            }
            float os = __shfl_xor_sync(0xffffffffu, s, 1);
            float S = s + os;
            if (half == 0) {
                int ch = (blockIdx.y - 4)*128 + row;
                int r = (b*8 + (ch >> 6))*64 + (ch & 63);
                g_kpm[blockIdx.x*(BHN*DH) + r] = M;
                g_kps[blockIdx.x*(BHN*DH) + r] = S;
            }
        } else {
            // v: per-pixel inverse norm, then store v*invn fp16
            float* sinv2 = (float*)(smem + FIX);  // reuse sstat area (256 floats)
            int col = tid & 127, g = tid >> 7;
            float ss = 0.f;
            #pragma unroll 8
            for (int d = 0; d < 64; d++) {
                float v = buf[(g*64+d)*130 + col];
                ss = fmaf(v, v, ss);
            }
            sinv2[g*128 + col] = 1.f / fmaxf(sqrtf(ss), 1e-12f);
            __syncthreads();
            __half2* kvb = (__half2*)(g_kv + ((size_t)(b*1024 + (m0 - 512)))*HW + n0);
            #pragma unroll 8
            for (int i = 0; i < 32; i++) {
                int idx = tid + (i << 8);
                int row = idx >> 6, c2 = idx & 63;
                int gg = row >> 6;
                float v0 = buf[row*130 + 2*c2]     * sinv2[gg*128 + 2*c2];
                float v1 = buf[row*130 + 2*c2 + 1] * sinv2[gg*128 + 2*c2 + 1];
                kvb[(size_t)row*(HW/2) + c2] = __floats2half2_rn(v0, v1);
            }
        }
    } else {
        // G4 epilogue: unscale a3 factor, then full output LN over 256 channels
        float* buf = (float*)smem;   // 256 x 64, pitch 68
        float* Cb = Cext + ((size_t)(b*CCH + m0))*HW + n0;
        #pragma unroll
        for (int mt = 0; mt < 4; mt++) {
            int rml = wm*64 + mt*16 + (lane >> 2);
            #pragma unroll
            for (int nt = 0; nt < 4; nt++) {
                int cl = wn*32 + nt*8 + 2*(lane & 3);
                float* d = acc[mt][nt];
                buf[rml*68 + cl]     = d[0] * A3UNSCALE;
                buf[rml*68 + cl + 1] = d[1] * A3UNSCALE;
                buf[(rml+8)*68 + cl]     = d[2] * A3UNSCALE;
                buf[(rml+8)*68 + cl + 1] = d[3] * A3UNSCALE;
            }
        }
        __syncthreads();
        {
            int col = tid & 63, part = tid >> 6;
            float s = 0.f, ss = 0.f;
            #pragma unroll 8
            for (int r = part*64; r < part*64 + 64; r++) {
                float v = buf[r*68 + col];
                s += v; ss = fmaf(v, v, ss);
            }
            ps[part*64 + col] = s;
            pss[part*64 + col] = ss;
        }
        __syncthreads();
        if (tid < 64) {
            float s  = ps[tid] + ps[64+tid] + ps[128+tid] + ps[192+tid];
            float ss = pss[tid] + pss[64+tid] + pss[128+tid] + pss[192+tid];
            float mu = s * (1.f/CCH);
            float var = fmaf(-mu, mu, ss * (1.f/CCH));
            mrs[tid] = make_float2(mu, rsqrtf(var + LNEPS));
        }
        __syncthreads();
        #pragma unroll 8
        for (int i = 0; i < 64; i++) {
            int idx = tid + (i << 8);
            int row = idx >> 6, col = idx & 63;
            float2 st = mrs[col];
            Cb[(size_t)row*HW + col] = (buf[row*68 + col] - st.x) * st.y * sg[row];
        }
    }
}

// ==================== merge k-softmax partials over 32 tiles ====================
__global__ void __launch_bounds__(256) kmerge() {
    int r = blockIdx.x*8 + (threadIdx.x >> 5);
    int lane = threadIdx.x & 31;
    float m = g_kpm[lane*(BHN*DH) + r];
    float s = g_kps[lane*(BHN*DH) + r];
    float M = m;
    #pragma unroll
    for (int o = 16; o > 0; o >>= 1) M = fmaxf(M, __shfl_xor_sync(0xffffffffu, M, o));
    float sc = s * __expf(m - M);
    #pragma unroll
    for (int o = 16; o > 0; o >>= 1) sc += __shfl_xor_sync(0xffffffffu, sc, o);
    if (lane == 0) { g_kmax[r] = M; g_ksum[r] = sc; }
}

// ==================== context partials: tensor-core MMA over exp'd k / scaled v ====================
// ctx_p[sp][bh][d][e] = sum_{blk} sc[d,blk] * sum_{n in blk} k'[d,n] * v'[e,n]
#define G2PITCH 136
#define G2TILE  (64*G2PITCH*2)    /* 17408 B per operand tile */
#define G2STG   (2*G2TILE)        /* 34816 B per stage */
#define SMEM_G2 (2*G2STG)         /* 69632 B */

__global__ void __launch_bounds__(256, 2) gemm2() {
    extern __shared__ char smem[];
    uint32_t sb = smem_u32(smem);
    int sp = blockIdx.x, bh = blockIdx.y;
    int b = bh >> 3, head = bh & 7;
    int tid = threadIdx.x, wid = tid >> 5, lane = tid & 31;
    int wm = wid >> 1, wn = wid & 1;
    const __half* kbase = g_kv + ((size_t)(b*1024 + head*DH))*HW;
    const __half* vbase = g_kv + ((size_t)(b*1024 + 512 + head*DH))*HW;
    int n0 = sp*512;

    int r0 = wm*16 + (lane >> 2), r1 = r0 + 8;
    float km0 = g_kmax[bh*64 + r0], km1 = g_kmax[bh*64 + r1];
    float rs0 = 1.f / g_ksum[bh*64 + r0], rs1 = 1.f / g_ksum[bh*64 + r1];

    auto load_blk = [&](int blk, int s) {
        int nb = n0 + blk*128;
        #pragma unroll
        for (int i = 0; i < 8; i++) {
            int e = tid + (i << 8);
            int isv = e >= 1024;
            int rq = e & 1023;
            int r = rq >> 4, q = rq & 15;
            const __half* src = (isv ? vbase : kbase) + (size_t)r*HW + nb + q*8;
            cp16(sb + s*G2STG + isv*G2TILE + (r*G2PITCH + q*8)*2, src);
        }
    };

    float accT[4][4] = {};
    int lrow = (lane & 7) + (((lane >> 3) & 1) << 3);
    int lcol = (lane >> 4) << 3;

    load_blk(0, 0); CP_COMMIT();
    for (int blk = 0; blk < 4; blk++) {
        if (blk + 1 < 4) { load_blk(blk+1, (blk+1) & 1); }
        CP_COMMIT();
        if (blk + 1 < 4) { CP_WAIT1(); } else { CP_WAIT0(); }
        __syncthreads();
        uint32_t base = sb + (blk & 1)*G2STG;
        float accB[4][4] = {};
        #pragma unroll
        for (int ks = 0; ks < 8; ks++) {
            int kof = ks*16 + lcol;
            uint32_t af[4];
            {
                int row = wm*16 + lrow;
                ldmx4(af, base + (row*G2PITCH + kof)*2);
            }
            uint32_t bf[2][4];
            #pragma unroll
            for (int bt = 0; bt < 2; bt++) {
                int row = wn*32 + bt*16 + lrow;
                ldmx4(bf[bt], base + G2TILE + (row*G2PITCH + kof)*2);
            }
            #pragma unroll
            for (int nt = 0; nt < 4; nt++) {
                int bt = nt >> 1, od = nt & 1;
                mma_f16(accB[nt], af, bf[bt][od], bf[bt][od+2]);
            }
        }
        int tile = sp*4 + blk;
        float sc0 = __expf(g_kpm[(size_t)tile*(BHN*DH) + bh*64 + r0] - km0) * rs0;
        float sc1 = __expf(g_kpm[(size_t)tile*(BHN*DH) + bh*64 + r1] - km1) * rs1;
        #pragma unroll
        for (int nt = 0; nt < 4; nt++) {
            accT[nt][0] = fmaf(sc0, accB[nt][0], accT[nt][0]);
            accT[nt][1] = fmaf(sc0, accB[nt][1], accT[nt][1]);
            accT[nt][2] = fmaf(sc1, accB[nt][2], accT[nt][2]);
            accT[nt][3] = fmaf(sc1, accB[nt][3], accT[nt][3]);
        }
        __syncthreads();
    }
    float* cp = g_ctxp + ((size_t)(sp*BHN + bh))*4096;
    #pragma unroll
    for (int nt = 0; nt < 4; nt++) {
        int cl = wn*32 + nt*8 + 2*(lane & 3);
        *(float2*)&cp[r0*64 + cl] = make_float2(accT[nt][0], accT[nt][1]);
        *(float2*)&cp[r1*64 + cl] = make_float2(accT[nt][2], accT[nt][3]);
    }
}

__global__ void __launch_bounds__(256) ctxred() {
    int bh = blockIdx.x, tid = threadIdx.x;
    for (int i = tid; i < 4096; i += 256) {
        float s = 0.f;
        #pragma unroll
        for (int sp = 0; sp < 8; sp++) s += g_ctxp[((size_t)(sp*BHN + bh))*4096 + i];
        g_ctx[(size_t)bh*4096 + i] = s * INV_N;
    }
}

// ==================== out = qs @ ctx -> a3 fp16 (x 2^18) [b][p][he] ====================
__global__ void __launch_bounds__(256) gemm3() {
    __shared__ float Cs[64][64];
    __shared__ float Qs[64][65];
    int p2t = blockIdx.x, bh = blockIdx.y;
    int b = bh >> 3, head = bh & 7;
    int tid = threadIdx.x;
    const float* ctx = g_ctx + (size_t)bh*4096;
    for (int i = tid; i < 4096; i += 256) Cs[i>>6][i&63] = ctx[i];
    const uint2* qb = (const uint2*)(g_qs + ((size_t)bh*HW + p2t*64)*DH);
    #pragma unroll
    for (int i = 0; i < 4; i++) {
        int idx = tid + (i<<8);
        uint2 raw = qb[idx];
        float2 a = __half22float2(*(__half2*)&raw.x);
        float2 c = __half22float2(*(__half2*)&raw.y);
        int lin = idx << 2;
        int row = lin >> 6, col = lin & 63;
        Qs[row][col]   = a.x; Qs[row][col+1] = a.y;
        Qs[row][col+2] = c.x; Qs[row][col+3] = c.y;
    }
    __syncthreads();
    int tx = tid & 15, ty = tid >> 4;
    float acc[4][4] = {};
    #pragma unroll
    for (int d = 0; d < 64; d++) {
        float a0 = Qs[(ty<<2)+0][d], a1 = Qs[(ty<<2)+1][d];
        float a2 = Qs[(ty<<2)+2][d], a3 = Qs[(ty<<2)+3][d];
        float4 bv = *(float4*)&Cs[d][tx<<2];
        acc[0][0]+=a0*bv.x; acc[0][1]+=a0*bv.y; acc[0][2]+=a0*bv.z; acc[0][3]+=a0*bv.w;
        acc[1][0]+=a1*bv.x; acc[1][1]+=a1*bv.y; acc[1][2]+=a1*bv.z; acc[1][3]+=a1*bv.w;
        acc[2][0]+=a2*bv.x; acc[2][1]+=a2*bv.y; acc[2][2]+=a2*bv.z; acc[2][3]+=a2*bv.w;
        acc[3][0]+=a3*bv.x; acc[3][1]+=a3*bv.y; acc[3][2]+=a3*bv.z; acc[3][3]+=a3*bv.w;
    }
    __syncthreads();
    #pragma unroll
    for (int i = 0; i < 4; i++)
        #pragma unroll
        for (int j = 0; j < 4; j++)
            Qs[(ty<<2)+i][(tx<<2)+j] = acc[i][j];   // [p2l][e]
    __syncthreads();
    size_t rowbase = (size_t)b*HW + p2t*64;
    #pragma unroll
    for (int i = 0; i < 16; i++) {
        int idx = tid + (i<<8); int pl = idx >> 6, e = idx & 63;
        g_a3[(rowbase + pl)*HID + head*DH + e] = __float2half_rn(Qs[pl][e] * A3SCALE);
    }
}

// ==================== launch ====================
#define SMEM_G1 68096    /* max(3*20480=61440, 128*130*4=66560) + 1536 */
#define SMEM_G4 80384    /* max(3*25600=76800, 256*68*4=69632)  + 3584 */

extern "C" void kernel_launch(void* const* d_in, const int* in_sizes, int n_in,
                              void* d_out, int out_size) {
    const float* feat = (const float*)d_in[0];
    const float* gin  = (const float*)d_in[1];
    const float* wqkv = (const float*)d_in[2];
    const float* wout = (const float*)d_in[3];
    const float* gout = (const float*)d_in[4];
    float* out = (float*)d_out;

    cudaFuncSetAttribute(gemm_p<128,128,256,true>,
                         cudaFuncAttributeMaxDynamicSharedMemorySize, SMEM_G1);
    cudaFuncSetAttribute(gemm_p<256,64,512,false>,
                         cudaFuncAttributeMaxDynamicSharedMemorySize, SMEM_G4);
    cudaFuncSetAttribute(gemm2,
                         cudaFuncAttributeMaxDynamicSharedMemorySize, SMEM_G2);

    prep_w1b<<<OQKV, 256>>>(wqkv, gin);
    prep_w2b<<<CCH, 256>>>(wout);
    conv_feat<<<dim3(HW/64, BATCH), 256>>>(feat);
    gemm_p<128,128,256,true><<<dim3(HW/128, OQKV/128, BATCH), 256, SMEM_G1>>>(nullptr, nullptr);
    kmerge<<<BHN*DH/8, 256>>>();
    gemm2<<<dim3(8, BHN), 256, SMEM_G2>>>();
    ctxred<<<BHN, 256>>>();
    gemm3<<<dim3(HW/64, BHN), 256>>>();
    gemm_p<256,64,512,false><<<dim3(HW/64, 1, BATCH), 256, SMEM_G4>>>(out, gout);
}